// round 12
// baseline (speedup 1.0000x reference)
#include <cuda_runtime.h>
#include <math.h>

#define LSEQ 2048
#define DMODEL 2048
#define NH 16
#define NKVH 4
#define HDIM 128
#define NE 16
#define NTOPK 4
#define NG 4
#define NTKG 2
#define EI 1024
#define SHI 2048
#define NT 2048
#define EPSV 1e-5f
#define ATTN_SCALE 0.08838834764831845f
#define RSF 2.5f

// smem tile geometry: 128 rows x 32 k-floats, stride 36 (conflict-free)
#define TSTRIDE 36
#define TSTAGE  (128*TSTRIDE)
#define GEMM_SMEM3 (6*TSTAGE*4)        // 3 stages x (A+B) = 110592 B

typedef unsigned long long ull;

struct Freqs { float f[64]; };

// ---------------- scratch ----------------
__device__ float g_h   [LSEQ*DMODEL];
__device__ float g_q   [LSEQ*NH*HDIM];
__device__ float g_k   [LSEQ*NKVH*HDIM];
__device__ float g_v   [LSEQ*NKVH*HDIM];
__device__ float g_attn[LSEQ*NH*HDIM];
__device__ float g_h1  [LSEQ*DMODEL];
__device__ float g_t   [LSEQ*DMODEL];
__device__ float g_Cw  [NT*NE];
__device__ int   g_cnt [NE];
__device__ int   g_bucket[NE*NT];
__device__ float g_eg  [(size_t)NE*NT*EI];
__device__ float g_eu  [(size_t)NE*NT*EI];
__device__ float g_sg  [(size_t)NT*SHI];
__device__ float g_su  [(size_t)NT*SHI];
__device__ float g_y   [(size_t)NT*DMODEL];

// ---------------- helpers ----------------
__device__ __forceinline__ unsigned f2tf(float f){
    unsigned u; asm("cvt.rna.tf32.f32 %0,%1;" : "=r"(u) : "f"(f)); return u;
}
__device__ __forceinline__ void mma_tf32(float c[4],
    unsigned a0, unsigned a1, unsigned a2, unsigned a3, unsigned b0, unsigned b1)
{
    asm volatile("mma.sync.aligned.m16n8k8.row.col.f32.tf32.tf32.f32 "
        "{%0,%1,%2,%3},{%4,%5,%6,%7},{%8,%9},{%0,%1,%2,%3};"
        : "+f"(c[0]), "+f"(c[1]), "+f"(c[2]), "+f"(c[3])
        : "r"(a0), "r"(a1), "r"(a2), "r"(a3), "r"(b0), "r"(b1));
}
__device__ __forceinline__ unsigned sptr(const void* p){
    return (unsigned)__cvta_generic_to_shared(p);
}
__device__ __forceinline__ void ldsm4(unsigned &r0, unsigned &r1, unsigned &r2, unsigned &r3,
                                      unsigned addr)
{
    asm volatile("ldmatrix.sync.aligned.m8n8.x4.shared.b16 {%0,%1,%2,%3}, [%4];"
        : "=r"(r0), "=r"(r1), "=r"(r2), "=r"(r3) : "r"(addr));
}
#define CPA16(dst, src, n) asm volatile( \
    "cp.async.cg.shared.global [%0], [%1], 16, %2;\n" :: "r"(dst), "l"(src), "r"(n))
#define CPCOMMIT() asm volatile("cp.async.commit_group;\n" ::: "memory")
#define CPWAIT0()  asm volatile("cp.async.wait_group 0;\n" ::: "memory")
#define CPWAIT1()  asm volatile("cp.async.wait_group 1;\n" ::: "memory")

// f32x2 packed math
__device__ __forceinline__ ull pack2(float lo, float hi){
    ull r; asm("mov.b64 %0,{%1,%2};" : "=l"(r) : "f"(lo), "f"(hi)); return r;
}
__device__ __forceinline__ void unpack2(ull v, float &lo, float &hi){
    asm("mov.b64 {%0,%1},%2;" : "=f"(lo), "=f"(hi) : "l"(v));
}
__device__ __forceinline__ ull fma2(ull a, ull b, ull c){
    ull d; asm("fma.rn.f32x2 %0,%1,%2,%3;" : "=l"(d) : "l"(a), "l"(b), "l"(c)); return d;
}
__device__ __forceinline__ ull mul2(ull a, ull b){
    ull d; asm("mul.rn.f32x2 %0,%1,%2;" : "=l"(d) : "l"(a), "l"(b)); return d;
}

// ---------------- fragment lane offsets (bytes within a stage) ----------------
__device__ __forceinline__ void frag_offsets(int lane, int wm, int wn,
                                             unsigned* aOff, unsigned* bOff)
{
    int g = lane >> 3, lr = lane & 7;
    #pragma unroll
    for (int mt = 0; mt < 4; mt++)
        aOff[mt] = ((wm + mt*16 + (g & 1)*8 + lr) * TSTRIDE + (g >> 1)*4) * 4;
    #pragma unroll
    for (int p = 0; p < 2; p++)
        bOff[p] = ((wn + (2*p + (g >> 1))*8 + lr) * TSTRIDE + (g & 1)*4) * 4;
}

// ---------------- MMA stage compute via ldmatrix ----------------
__device__ __forceinline__ void mma_ldsm_1x(unsigned baseA, unsigned baseB,
    const unsigned* aOff, const unsigned* bOff, float (*acc)[4][4])
{
    #pragma unroll
    for (int ks = 0; ks < 32; ks += 8) {
        unsigned a[4][4], b[2][4];
        #pragma unroll
        for (int mt = 0; mt < 4; mt++)
            ldsm4(a[mt][0], a[mt][1], a[mt][2], a[mt][3], baseA + aOff[mt] + ks*4);
        #pragma unroll
        for (int p = 0; p < 2; p++)
            ldsm4(b[p][0], b[p][1], b[p][2], b[p][3], baseB + bOff[p] + ks*4);
        unsigned aT[4][4], bT[4][2];
        #pragma unroll
        for (int mt = 0; mt < 4; mt++)
            #pragma unroll
            for (int i = 0; i < 4; i++)
                aT[mt][i] = f2tf(__uint_as_float(a[mt][i]));
        #pragma unroll
        for (int p = 0; p < 2; p++) {
            bT[2*p][0]   = f2tf(__uint_as_float(b[p][0]));
            bT[2*p][1]   = f2tf(__uint_as_float(b[p][1]));
            bT[2*p+1][0] = f2tf(__uint_as_float(b[p][2]));
            bT[2*p+1][1] = f2tf(__uint_as_float(b[p][3]));
        }
        #pragma unroll
        for (int mt = 0; mt < 4; mt++)
            #pragma unroll
            for (int nt = 0; nt < 4; nt++)
                mma_tf32(acc[mt][nt], aT[mt][0], aT[mt][1], aT[mt][2], aT[mt][3],
                         bT[nt][0], bT[nt][1]);
    }
}

__device__ __forceinline__ void mma_ldsm_3x(unsigned baseA, unsigned baseB,
    const unsigned* aOff, const unsigned* bOff, float (*acc)[4][4])
{
    #pragma unroll
    for (int ks = 0; ks < 32; ks += 8) {
        unsigned a[4][4], b[2][4];
        #pragma unroll
        for (int mt = 0; mt < 4; mt++)
            ldsm4(a[mt][0], a[mt][1], a[mt][2], a[mt][3], baseA + aOff[mt] + ks*4);
        #pragma unroll
        for (int p = 0; p < 2; p++)
            ldsm4(b[p][0], b[p][1], b[p][2], b[p][3], baseB + bOff[p] + ks*4);
        unsigned aH[4][4], aL[4][4], bH[4][2], bL[4][2];
        #pragma unroll
        for (int mt = 0; mt < 4; mt++)
            #pragma unroll
            for (int i = 0; i < 4; i++) {
                float v = __uint_as_float(a[mt][i]);
                aH[mt][i] = f2tf(v);
                aL[mt][i] = f2tf(v - __uint_as_float(aH[mt][i]));
            }
        #pragma unroll
        for (int p = 0; p < 2; p++) {
            #pragma unroll
            for (int i = 0; i < 4; i++) {
                float v = __uint_as_float(b[p][i]);
                unsigned h = f2tf(v);
                unsigned l = f2tf(v - __uint_as_float(h));
                int nt = 2*p + (i >> 1), cc = i & 1;
                bH[nt][cc] = h; bL[nt][cc] = l;
            }
        }
        #pragma unroll
        for (int mt = 0; mt < 4; mt++)
            #pragma unroll
            for (int nt = 0; nt < 4; nt++) {
                mma_tf32(acc[mt][nt], aH[mt][0], aH[mt][1], aH[mt][2], aH[mt][3], bH[nt][0], bH[nt][1]);
                mma_tf32(acc[mt][nt], aL[mt][0], aL[mt][1], aL[mt][2], aL[mt][3], bH[nt][0], bH[nt][1]);
                mma_tf32(acc[mt][nt], aH[mt][0], aH[mt][1], aH[mt][2], aH[mt][3], bL[nt][0], bL[nt][1]);
            }
    }
}

// ============ fused QKV projection (3xTF32, 3-stage pipeline) ============
__global__ __launch_bounds__(256, 2) void qkv3_kernel(const float* __restrict__ A,
    const float* __restrict__ wq, const float* __restrict__ wk, const float* __restrict__ wv)
{
    extern __shared__ float sm[];
    float* As = sm;
    float* Bs = sm + 3*TSTAGE;
    const int K = DMODEL;
    int tid = threadIdx.x, lane = tid & 31, warp = tid >> 5;
    int m0 = blockIdx.y * 128, n0 = blockIdx.x * 128;
    int wm = (warp & 1) * 64, wn = (warp >> 1) * 32;

    const float* B; float* Cp; int ldc, ncol0;
    if (n0 < 2048)      { B = wq + (size_t)n0 * K;          Cp = g_q; ldc = NH*HDIM;   ncol0 = n0; }
    else if (n0 < 2560) { B = wk + (size_t)(n0 - 2048) * K; Cp = g_k; ldc = NKVH*HDIM; ncol0 = n0 - 2048; }
    else                { B = wv + (size_t)(n0 - 2560) * K; Cp = g_v; ldc = NKVH*HDIM; ncol0 = n0 - 2560; }

    unsigned aOff[4], bOff[2];
    frag_offsets(lane, wm, wn, aOff, bOff);
    unsigned sA[3] = { sptr(As), sptr(As + TSTAGE), sptr(As + 2*TSTAGE) };
    unsigned sB[3] = { sptr(Bs), sptr(Bs + TSTAGE), sptr(Bs + 2*TSTAGE) };

    const float* aSrc[4]; const float* bSrc[4]; unsigned soff[4];
    #pragma unroll
    for (int i = 0; i < 4; i++) {
        int idx = tid + i * 256, row = idx >> 3, ch = idx & 7;
        soff[i] = (row * TSTRIDE + ch * 4) * 4;
        aSrc[i] = A + (size_t)(m0 + row) * K + ch * 4;
        bSrc[i] = B + (size_t)row * K + ch * 4;
    }
    #pragma unroll
    for (int s = 0; s < 2; s++) {
        #pragma unroll
        for (int i = 0; i < 4; i++) {
            CPA16(sA[s] + soff[i], aSrc[i] + s*32, 16);
            CPA16(sB[s] + soff[i], bSrc[i] + s*32, 16);
        }
        CPCOMMIT();
    }

    float acc[4][4][4] = {};
    const int nst = K / 32;
    for (int it = 0; it < nst; it++) {
        if (it + 1 < nst) { CPWAIT1(); } else { CPWAIT0(); }
        __syncthreads();
        int cur = it % 3;
        int pf = it + 2;
        if (pf < nst) {
            int buf = pf % 3;
            #pragma unroll
            for (int i = 0; i < 4; i++) {
                CPA16(sA[buf] + soff[i], aSrc[i] + pf*32, 16);
                CPA16(sB[buf] + soff[i], bSrc[i] + pf*32, 16);
            }
            CPCOMMIT();
        }
        mma_ldsm_3x(sA[cur], sB[cur], aOff, bOff, acc);
    }
    int r = lane >> 2, c2 = (lane & 3) * 2;
    #pragma unroll
    for (int mt = 0; mt < 4; mt++) {
        int mrow = m0 + wm + mt * 16 + r;
        #pragma unroll
        for (int nt = 0; nt < 4; nt++) {
            int col = ncol0 + wn + nt * 8 + c2;
            size_t i00 = (size_t)mrow * ldc + col;
            size_t i10 = (size_t)(mrow + 8) * ldc + col;
            Cp[i00] = acc[mt][nt][0]; Cp[i00+1] = acc[mt][nt][1];
            Cp[i10] = acc[mt][nt][2]; Cp[i10+1] = acc[mt][nt][3];
        }
    }
}

// ============ o-proj + residual (3xTF32, 3-stage) ============
__global__ __launch_bounds__(256, 2) void gemm3o_kernel(const float* __restrict__ A,
    const float* __restrict__ B, float* __restrict__ C, const float* __restrict__ R)
{
    extern __shared__ float sm[];
    float* As = sm;
    float* Bs = sm + 3*TSTAGE;
    const int K = NH*HDIM, N = DMODEL;
    int tid = threadIdx.x, lane = tid & 31, warp = tid >> 5;
    int m0 = blockIdx.y * 128, n0 = blockIdx.x * 128;
    int wm = (warp & 1) * 64, wn = (warp >> 1) * 32;

    unsigned aOff[4], bOff[2];
    frag_offsets(lane, wm, wn, aOff, bOff);
    unsigned sA[3] = { sptr(As), sptr(As + TSTAGE), sptr(As + 2*TSTAGE) };
    unsigned sB[3] = { sptr(Bs), sptr(Bs + TSTAGE), sptr(Bs + 2*TSTAGE) };

    const float* aSrc[4]; const float* bSrc[4]; unsigned soff[4];
    #pragma unroll
    for (int i = 0; i < 4; i++) {
        int idx = tid + i * 256, row = idx >> 3, ch = idx & 7;
        soff[i] = (row * TSTRIDE + ch * 4) * 4;
        aSrc[i] = A + (size_t)(m0 + row) * K + ch * 4;
        bSrc[i] = B + (size_t)(n0 + row) * K + ch * 4;
    }
    #pragma unroll
    for (int s = 0; s < 2; s++) {
        #pragma unroll
        for (int i = 0; i < 4; i++) {
            CPA16(sA[s] + soff[i], aSrc[i] + s*32, 16);
            CPA16(sB[s] + soff[i], bSrc[i] + s*32, 16);
        }
        CPCOMMIT();
    }

    float acc[4][4][4] = {};
    const int nst = K / 32;
    for (int it = 0; it < nst; it++) {
        if (it + 1 < nst) { CPWAIT1(); } else { CPWAIT0(); }
        __syncthreads();
        int cur = it % 3;
        int pf = it + 2;
        if (pf < nst) {
            int buf = pf % 3;
            #pragma unroll
            for (int i = 0; i < 4; i++) {
                CPA16(sA[buf] + soff[i], aSrc[i] + pf*32, 16);
                CPA16(sB[buf] + soff[i], bSrc[i] + pf*32, 16);
            }
            CPCOMMIT();
        }
        mma_ldsm_3x(sA[cur], sB[cur], aOff, bOff, acc);
    }
    int r = lane >> 2, c2 = (lane & 3) * 2;
    #pragma unroll
    for (int mt = 0; mt < 4; mt++) {
        int mrow = m0 + wm + mt * 16 + r;
        #pragma unroll
        for (int nt = 0; nt < 4; nt++) {
            int col = n0 + wn + nt * 8 + c2;
            size_t i00 = (size_t)mrow * N + col;
            size_t i10 = (size_t)(mrow + 8) * N + col;
            C[i00] = acc[mt][nt][0] + R[i00]; C[i00+1] = acc[mt][nt][1] + R[i00+1];
            C[i10] = acc[mt][nt][2] + R[i10]; C[i10+1] = acc[mt][nt][3] + R[i10+1];
        }
    }
}

// ============ dual dense 1xTF32 GEMM (z selects gate/up), 3-stage ============
__global__ __launch_bounds__(256, 2) void dense1_dual_kernel(const float* __restrict__ A,
    const float* __restrict__ B0, const float* __restrict__ B1,
    float* __restrict__ C0, float* __restrict__ C1, int N, int K)
{
    const float* Bsel = blockIdx.z ? B1 : B0;
    float* Csel = blockIdx.z ? C1 : C0;
    extern __shared__ float sm[];
    float* As = sm;
    float* Bs = sm + 3*TSTAGE;
    int tid = threadIdx.x, lane = tid & 31, warp = tid >> 5;
    int m0 = blockIdx.y * 128, n0 = blockIdx.x * 128;
    int wm = (warp & 1) * 64, wn = (warp >> 1) * 32;

    unsigned aOff[4], bOff[2];
    frag_offsets(lane, wm, wn, aOff, bOff);
    unsigned sA[3] = { sptr(As), sptr(As + TSTAGE), sptr(As + 2*TSTAGE) };
    unsigned sB[3] = { sptr(Bs), sptr(Bs + TSTAGE), sptr(Bs + 2*TSTAGE) };

    const float* aSrc[4]; const float* bSrc[4]; unsigned soff[4];
    #pragma unroll
    for (int i = 0; i < 4; i++) {
        int idx = tid + i * 256, row = idx >> 3, ch = idx & 7;
        soff[i] = (row * TSTRIDE + ch * 4) * 4;
        aSrc[i] = A + (size_t)(m0 + row) * K + ch * 4;
        bSrc[i] = Bsel + (size_t)(n0 + row) * K + ch * 4;
    }
    #pragma unroll
    for (int s = 0; s < 2; s++) {
        #pragma unroll
        for (int i = 0; i < 4; i++) {
            CPA16(sA[s] + soff[i], aSrc[i] + s*32, 16);
            CPA16(sB[s] + soff[i], bSrc[i] + s*32, 16);
        }
        CPCOMMIT();
    }

    float acc[4][4][4] = {};
    const int nst = K / 32;
    for (int it = 0; it < nst; it++) {
        if (it + 1 < nst) { CPWAIT1(); } else { CPWAIT0(); }
        __syncthreads();
        int cur = it % 3;
        int pf = it + 2;
        if (pf < nst) {
            int buf = pf % 3;
            #pragma unroll
            for (int i = 0; i < 4; i++) {
                CPA16(sA[buf] + soff[i], aSrc[i] + pf*32, 16);
                CPA16(sB[buf] + soff[i], bSrc[i] + pf*32, 16);
            }
            CPCOMMIT();
        }
        mma_ldsm_1x(sA[cur], sB[cur], aOff, bOff, acc);
    }
    int r = lane >> 2, c2 = (lane & 3) * 2;
    #pragma unroll
    for (int mt = 0; mt < 4; mt++) {
        int mrow = m0 + wm + mt * 16 + r;
        #pragma unroll
        for (int nt = 0; nt < 4; nt++) {
            int col = n0 + wn + nt * 8 + c2;
            size_t i00 = (size_t)mrow * N + col;
            size_t i10 = (size_t)(mrow + 8) * N + col;
            Csel[i00] = acc[mt][nt][0]; Csel[i00+1] = acc[mt][nt][1];
            Csel[i10] = acc[mt][nt][2]; Csel[i10+1] = acc[mt][nt][3];
        }
    }
}

// ============ dense 1xTF32 GEMM, 3-stage ============
__global__ __launch_bounds__(256, 2) void dense1_kernel(const float* __restrict__ A,
    const float* __restrict__ B, float* __restrict__ C, int N, int K)
{
    extern __shared__ float sm[];
    float* As = sm;
    float* Bs = sm + 3*TSTAGE;
    int tid = threadIdx.x, lane = tid & 31, warp = tid >> 5;
    int m0 = blockIdx.y * 128, n0 = blockIdx.x * 128;
    int wm = (warp & 1) * 64, wn = (warp >> 1) * 32;

    unsigned aOff[4], bOff[2];
    frag_offsets(lane, wm, wn, aOff, bOff);
    unsigned sA[3] = { sptr(As), sptr(As + TSTAGE), sptr(As + 2*TSTAGE) };
    unsigned sB[3] = { sptr(Bs), sptr(Bs + TSTAGE), sptr(Bs + 2*TSTAGE) };

    const float* aSrc[4]; const float* bSrc[4]; unsigned soff[4];
    #pragma unroll
    for (int i = 0; i < 4; i++) {
        int idx = tid + i * 256, row = idx >> 3, ch = idx & 7;
        soff[i] = (row * TSTRIDE + ch * 4) * 4;
        aSrc[i] = A + (size_t)(m0 + row) * K + ch * 4;
        bSrc[i] = B + (size_t)(n0 + row) * K + ch * 4;
    }
    #pragma unroll
    for (int s = 0; s < 2; s++) {
        #pragma unroll
        for (int i = 0; i < 4; i++) {
            CPA16(sA[s] + soff[i], aSrc[i] + s*32, 16);
            CPA16(sB[s] + soff[i], bSrc[i] + s*32, 16);
        }
        CPCOMMIT();
    }

    float acc[4][4][4] = {};
    const int nst = K / 32;
    for (int it = 0; it < nst; it++) {
        if (it + 1 < nst) { CPWAIT1(); } else { CPWAIT0(); }
        __syncthreads();
        int cur = it % 3;
        int pf = it + 2;
        if (pf < nst) {
            int buf = pf % 3;
            #pragma unroll
            for (int i = 0; i < 4; i++) {
                CPA16(sA[buf] + soff[i], aSrc[i] + pf*32, 16);
                CPA16(sB[buf] + soff[i], bSrc[i] + pf*32, 16);
            }
            CPCOMMIT();
        }
        mma_ldsm_1x(sA[cur], sB[cur], aOff, bOff, acc);
    }
    int r = lane >> 2, c2 = (lane & 3) * 2;
    #pragma unroll
    for (int mt = 0; mt < 4; mt++) {
        int mrow = m0 + wm + mt * 16 + r;
        #pragma unroll
        for (int nt = 0; nt < 4; nt++) {
            int col = n0 + wn + nt * 8 + c2;
            size_t i00 = (size_t)mrow * N + col;
            size_t i10 = (size_t)(mrow + 8) * N + col;
            C[i00] = acc[mt][nt][0]; C[i00+1] = acc[mt][nt][1];
            C[i10] = acc[mt][nt][2]; C[i10+1] = acc[mt][nt][3];
        }
    }
}

// ============ gathered expert gate+up GEMM (1xTF32), z = e*2 + which, 3-stage ============
__global__ __launch_bounds__(256, 2) void egu1_kernel(const float* __restrict__ wg,
    const float* __restrict__ wu)
{
    int e = blockIdx.z >> 1;
    int which = blockIdx.z & 1;
    int cnt = g_cnt[e];
    int m0 = blockIdx.y * 128;
    if (m0 >= cnt) return;
    int n0 = blockIdx.x * 128;
    const float* W = which ? wu : wg;
    float* Cout = which ? g_eu : g_eg;
    extern __shared__ float sm[];
    float* As = sm;
    float* Bs = sm + 3*TSTAGE;
    __shared__ int toks[128];
    const int K = DMODEL;
    int tid = threadIdx.x, lane = tid & 31, warp = tid >> 5;
    if (tid < 128) {
        int m = m0 + tid;
        toks[tid] = (m < cnt) ? g_bucket[e * NT + m] : -1;
    }
    __syncthreads();
    const float* B = W + (size_t)e * EI * DMODEL + (size_t)n0 * K;
    int wm = (warp & 1) * 64, wn = (warp >> 1) * 32;

    unsigned aOff[4], bOff[2];
    frag_offsets(lane, wm, wn, aOff, bOff);
    unsigned sA[3] = { sptr(As), sptr(As + TSTAGE), sptr(As + 2*TSTAGE) };
    unsigned sB[3] = { sptr(Bs), sptr(Bs + TSTAGE), sptr(Bs + 2*TSTAGE) };

    const float* aSrc[4]; const float* bSrc[4]; unsigned soff[4]; int aBytes[4];
    #pragma unroll
    for (int i = 0; i < 4; i++) {
        int idx = tid + i * 256, row = idx >> 3, ch = idx & 7;
        soff[i] = (row * TSTRIDE + ch * 4) * 4;
        int tok = toks[row];
        aBytes[i] = (tok >= 0) ? 16 : 0;
        aSrc[i] = g_t + (size_t)(tok >= 0 ? tok : 0) * K + ch * 4;
        bSrc[i] = B + (size_t)row * K + ch * 4;
    }
    #pragma unroll
    for (int s = 0; s < 2; s++) {
        #pragma unroll
        for (int i = 0; i < 4; i++) {
            CPA16(sA[s] + soff[i], aSrc[i] + s*32, aBytes[i]);
            CPA16(sB[s] + soff[i], bSrc[i] + s*32, 16);
        }
        CPCOMMIT();
    }

    float acc[4][4][4] = {};
    const int nst = K / 32;
    for (int it = 0; it < nst; it++) {
        if (it + 1 < nst) { CPWAIT1(); } else { CPWAIT0(); }
        __syncthreads();
        int cur = it % 3;
        int pf = it + 2;
        if (pf < nst) {
            int buf = pf % 3;
            #pragma unroll
            for (int i = 0; i < 4; i++) {
                CPA16(sA[buf] + soff[i], aSrc[i] + pf*32, aBytes[i]);
                CPA16(sB[buf] + soff[i], bSrc[i] + pf*32, 16);
            }
            CPCOMMIT();
        }
        mma_ldsm_1x(sA[cur], sB[cur], aOff, bOff, acc);
    }
    int r = lane >> 2, c2 = (lane & 3) * 2;
    #pragma unroll
    for (int mt = 0; mt < 4; mt++) {
        int mloc = wm + mt * 16 + r;
        int m = m0 + mloc;
        #pragma unroll
        for (int nt = 0; nt < 4; nt++) {
            int col = n0 + wn + nt * 8 + c2;
            if (m < cnt) {
                size_t i00 = ((size_t)e * NT + m) * EI + col;
                Cout[i00] = acc[mt][nt][0]; Cout[i00+1] = acc[mt][nt][1];
            }
            if (m + 8 < cnt) {
                size_t i10 = ((size_t)e * NT + m + 8) * EI + col;
                Cout[i10] = acc[mt][nt][2]; Cout[i10+1] = acc[mt][nt][3];
            }
        }
    }
}

// ============ expert down GEMM (1xTF32) + scatter atomicAdd, 3-stage ============
__global__ __launch_bounds__(256, 2) void edown1_kernel(const float* __restrict__ wd)
{
    int e = blockIdx.z;
    int cnt = g_cnt[e];
    int m0 = blockIdx.y * 128;
    if (m0 >= cnt) return;
    int n0 = blockIdx.x * 128;
    extern __shared__ float sm[];
    float* As = sm;
    float* Bs = sm + 3*TSTAGE;
    __shared__ int toks[128];
    const int K = EI;
    int tid = threadIdx.x, lane = tid & 31, warp = tid >> 5;
    if (tid < 128) {
        int m = m0 + tid;
        toks[tid] = (m < cnt) ? g_bucket[e * NT + m] : -1;
    }
    __syncthreads();
    const float* Ae = g_eg + ((size_t)e * NT + m0) * EI;
    const float* B = wd + (size_t)e * DMODEL * EI + (size_t)n0 * K;
    int wm = (warp & 1) * 64, wn = (warp >> 1) * 32;

    unsigned aOff[4], bOff[2];
    frag_offsets(lane, wm, wn, aOff, bOff);
    unsigned sA[3] = { sptr(As), sptr(As + TSTAGE), sptr(As + 2*TSTAGE) };
    unsigned sB[3] = { sptr(Bs), sptr(Bs + TSTAGE), sptr(Bs + 2*TSTAGE) };

    const float* aSrc[4]; const float* bSrc[4]; unsigned soff[4]; int aBytes[4];
    #pragma unroll
    for (int i = 0; i < 4; i++) {
        int idx = tid + i * 256, row = idx >> 3, ch = idx & 7;
        soff[i] = (row * TSTRIDE + ch * 4) * 4;
        bool ok = (m0 + row) < cnt;
        aBytes[i] = ok ? 16 : 0;
        aSrc[i] = Ae + (size_t)(ok ? row : 0) * K + ch * 4;
        bSrc[i] = B + (size_t)row * K + ch * 4;
    }
    #pragma unroll
    for (int s = 0; s < 2; s++) {
        #pragma unroll
        for (int i = 0; i < 4; i++) {
            CPA16(sA[s] + soff[i], aSrc[i] + s*32, aBytes[i]);
            CPA16(sB[s] + soff[i], bSrc[i] + s*32, 16);
        }
        CPCOMMIT();
    }

    float acc[4][4][4] = {};
    const int nst = K / 32;
    for (int it = 0; it < nst; it++) {
        if (it + 1 < nst) { CPWAIT1(); } else { CPWAIT0(); }
        __syncthreads();
        int cur = it % 3;
        int pf = it + 2;
        if (pf < nst) {
            int buf = pf % 3;
            #pragma unroll
            for (int i = 0; i < 4; i++) {
                CPA16(sA[buf] + soff[i], aSrc[i] + pf*32, aBytes[i]);
                CPA16(sB[buf] + soff[i], bSrc[i] + pf*32, 16);
            }
            CPCOMMIT();
        }
        mma_ldsm_1x(sA[cur], sB[cur], aOff, bOff, acc);
    }
    int r = lane >> 2, c2 = (lane & 3) * 2;
    #pragma unroll
    for (int mt = 0; mt < 4; mt++) {
        int mloc = wm + mt * 16 + r;
        #pragma unroll
        for (int nt = 0; nt < 4; nt++) {
            int col = n0 + wn + nt * 8 + c2;
            if (m0 + mloc < cnt) {
                int tok = toks[mloc];
                atomicAdd(&g_y[(size_t)tok * DMODEL + col],     acc[mt][nt][0]);
                atomicAdd(&g_y[(size_t)tok * DMODEL + col + 1], acc[mt][nt][1]);
            }
            if (m0 + mloc + 8 < cnt) {
                int tok = toks[mloc + 8];
                atomicAdd(&g_y[(size_t)tok * DMODEL + col],     acc[mt][nt][2]);
                atomicAdd(&g_y[(size_t)tok * DMODEL + col + 1], acc[mt][nt][3]);
            }
        }
    }
}

// ---------------- RMSNorm ----------------
__global__ __launch_bounds__(256) void rmsnorm_kernel(const float* __restrict__ x,
                                                      const float* __restrict__ w,
                                                      float* __restrict__ out)
{
    int row = blockIdx.x;
    const float* xr = x + (size_t)row * DMODEL;
    float ss = 0.f;
    for (int d = threadIdx.x; d < DMODEL; d += 256) { float v = xr[d]; ss += v * v; }
    __shared__ float red[8];
    #pragma unroll
    for (int off = 16; off; off >>= 1) ss += __shfl_xor_sync(0xffffffffu, ss, off);
    if ((threadIdx.x & 31) == 0) red[threadIdx.x >> 5] = ss;
    __syncthreads();
    __shared__ float sinv;
    if (threadIdx.x == 0) {
        float tot = 0.f;
        #pragma unroll
        for (int i = 0; i < 8; i++) tot += red[i];
        sinv = 1.f / sqrtf(tot / (float)DMODEL + EPSV);
    }
    __syncthreads();
    float si = sinv;
    for (int d = threadIdx.x; d < DMODEL; d += 256)
        out[(size_t)row * DMODEL + d] = xr[d] * si * w[d];
}

// ---------------- fused per-(token,head) RMSNorm + RoPE (inline fp32 trig) ----------------
// Angle reduction: 2*pi = H1 + H2 + R2 with H1=6.28125 (12-bit mantissa),
// H2=4059*2^-21 (12-bit). k = rint(ang/2pi) <= 326 (9 bits) => k*H1, k*H2 exact.
// Reduction error <= ~5e-7 rad; sincosf on |red|<=pi is fast-math-safe.
__global__ __launch_bounds__(128) void qknorm_rope_kernel(const float* __restrict__ qw,
                                                          const float* __restrict__ kw,
                                                          Freqs fr)
{
    int row = blockIdx.x;
    float* buf; const float* w; int nh;
    if (row < LSEQ * NH) { buf = g_q; w = qw; nh = NH; }
    else { row -= LSEQ * NH; buf = g_k; w = kw; nh = NKVH; }
    int pos = row / nh;
    float* p = buf + (size_t)row * HDIM;
    int tid = threadIdx.x;
    float v = p[tid];
    float ss = v * v;
    #pragma unroll
    for (int off = 16; off; off >>= 1) ss += __shfl_xor_sync(0xffffffffu, ss, off);
    __shared__ float red_s[4];
    if ((tid & 31) == 0) red_s[tid >> 5] = ss;
    __syncthreads();
    __shared__ float sinv;
    if (tid == 0) sinv = 1.f / sqrtf((red_s[0] + red_s[1] + red_s[2] + red_s[3]) / (float)HDIM + EPSV);
    __shared__ float shn[HDIM];
    __syncthreads();
    shn[tid] = v * sinv * w[tid];
    __syncthreads();
    if (tid < 64) {
        float x1 = shn[tid], x2 = shn[tid + 64];
        float ang = (float)pos * fr.f[tid];             // matches reference fp32 product
        float k = rintf(ang * 0.15915494309189535f);    // 1/(2*pi)
        float red = ang - k * 6.28125f;
        red = red - k * 0.0019354820251464844f;         // 4059*2^-21
        red = red - k * (-1.7484556e-7f);               // residual
        float s, c;
        sincosf(red, &s, &c);
        p[tid]      = x1 * c - x2 * s;
        p[tid + 64] = x2 * c + x1 * s;
    }
}

// ---------------- flash attention (fp32 via f32x2, causal, GQA) ----------------
__global__ __launch_bounds__(128) void attn_kernel()
{
    __shared__ __align__(16) float Qs[32][HDIM];
    __shared__ __align__(16) float Ks[32][HDIM];
    __shared__ __align__(16) float Vs[32][HDIM];
    int h = blockIdx.y;
    int q0 = blockIdx.x * 32;
    int kvh = h >> 2;
    int tid = threadIdx.x;
    int r = tid >> 2, qd = tid & 3;

    for (int i = tid; i < 32 * 32; i += 128) {
        int row = i >> 5, d4 = i & 31;
        ((float4*)&Qs[row][0])[d4] =
            *(const float4*)(g_q + (size_t)(q0 + row) * (NH * HDIM) + h * HDIM + d4 * 4);
    }
    __syncthreads();
    ull qq[16];
    #pragma unroll
    for (int i = 0; i < 16; i++) qq[i] = *(const ull*)&Qs[r][qd * 32 + i * 2];

    ull o2[16];
    #pragma unroll
    for (int i = 0; i < 16; i++) o2[i] = 0ULL;
    float mrow = -INFINITY, lrow = 0.f;

    for (int k0 = 0; k0 <= q0; k0 += 32) {
        __syncthreads();
        for (int i = tid; i < 32 * 32; i += 128) {
            int row = i >> 5, d4 = i & 31;
            size_t base = (size_t)(k0 + row) * (NKVH * HDIM) + kvh * HDIM + d4 * 4;
            ((float4*)&Ks[row][0])[d4] = *(const float4*)(g_k + base);
            ((float4*)&Vs[row][0])[d4] = *(const float4*)(g_v + base);
        }
        __syncthreads();

        float s[32];
        float tmax = -INFINITY;
        #pragma unroll
        for (int j = 0; j < 32; j++) {
            const ull* K2 = (const ull*)&Ks[j][qd * 32];
            ull acc2 = 0ULL;
            #pragma unroll
            for (int i = 0; i < 16; i++) acc2 = fma2(qq[i], K2[i], acc2);
            float elo, ehi; unpack2(acc2, elo, ehi);
            float pacc = elo + ehi;
            pacc += __shfl_xor_sync(0xffffffffu, pacc, 1);
            pacc += __shfl_xor_sync(0xffffffffu, pacc, 2);
            pacc *= ATTN_SCALE;
            if (k0 + j > q0 + r) pacc = -INFINITY;
            s[j] = pacc;
            tmax = fmaxf(tmax, pacc);
        }
        float mnew = fmaxf(mrow, tmax);
        float alpha = __expf(mrow - mnew);
        lrow *= alpha;
        ull al2 = pack2(alpha, alpha);
        #pragma unroll
        for (int i = 0; i < 16; i++) o2[i] = mul2(o2[i], al2);
        #pragma unroll
        for (int j = 0; j < 32; j++) {
            float pv = __expf(s[j] - mnew);
            lrow += pv;
            ull pv2 = pack2(pv, pv);
            const ull* V2 = (const ull*)&Vs[j][qd * 32];
            #pragma unroll
            for (int i = 0; i < 16; i++) o2[i] = fma2(pv2, V2[i], o2[i]);
        }
        mrow = mnew;
    }
    float inv = 1.f / lrow;
    size_t base = (size_t)(q0 + r) * (NH * HDIM) + h * HDIM + qd * 32;
    #pragma unroll
    for (int i = 0; i < 16; i++) {
        float lo, hi; unpack2(o2[i], lo, hi);
        g_attn[base + i * 2]     = lo * inv;
        g_attn[base + i * 2 + 1] = hi * inv;
    }
}

// ---------------- zero expert counters ----------------
__global__ void zero_cnt_kernel()
{
    if (threadIdx.x < NE) g_cnt[threadIdx.x] = 0;
}

// ---------------- gating / routing (fp32, exact) ----------------
__global__ __launch_bounds__(256) void gate_kernel(const float* __restrict__ gate_w,
                                                   const float* __restrict__ gate_bias)
{
    int t = blockIdx.x;
    const float* tr = g_t + (size_t)t * DMODEL;
    float acc[NE];
    #pragma unroll
    for (int e = 0; e < NE; e++) acc[e] = 0.f;
    for (int d = threadIdx.x; d < DMODEL; d += 256) {
        float xv = tr[d];
        #pragma unroll
        for (int e = 0; e < NE; e++) acc[e] += xv * gate_w[e * DMODEL + d];
    }
    __shared__ float red[NE * 8];
    int lane = threadIdx.x & 31, wid = threadIdx.x >> 5;
    #pragma unroll
    for (int e = 0; e < NE; e++) {
        float v = acc[e];
        #pragma unroll
        for (int off = 16; off; off >>= 1) v += __shfl_xor_sync(0xffffffffu, v, off);
        if (lane == 0) red[e * 8 + wid] = v;
    }
    __syncthreads();
    __shared__ float sc_s[NE];
    if (threadIdx.x < NE) {
        float sum = 0.f;
        #pragma unroll
        for (int wq = 0; wq < 8; wq++) sum += red[threadIdx.x * 8 + wq];
        sc_s[threadIdx.x] = 1.f / (1.f + expf(-sum));
    }
    __syncthreads();
    if (threadIdx.x == 0) {
        float sc[NE], s2[NE];
        #pragma unroll
        for (int e = 0; e < NE; e++) { sc[e] = sc_s[e]; s2[e] = sc[e] + gate_bias[e]; }
        float gs[NG];
        #pragma unroll
        for (int gq = 0; gq < NG; gq++) {
            float m1 = -INFINITY, m2 = -INFINITY;
            #pragma unroll
            for (int j = 0; j < NE / NG; j++) {
                float vv = s2[gq * (NE / NG) + j];
                if (vv > m1) { m2 = m1; m1 = vv; }
                else if (vv > m2) { m2 = vv; }
            }
            gs[gq] = m1 + m2;
        }
        bool gsel[NG] = {false, false, false, false};
        {
            float gtmp[NG];
            #pragma unroll
            for (int gq = 0; gq < NG; gq++) gtmp[gq] = gs[gq];
            for (int it = 0; it < NTKG; it++) {
                int bi = 0; float bv = -INFINITY;
                #pragma unroll
                for (int gq = 0; gq < NG; gq++)
                    if (gtmp[gq] > bv) { bv = gtmp[gq]; bi = gq; }
                gsel[bi] = true; gtmp[bi] = -INFINITY;
            }
        }
        float masked[NE];
        #pragma unroll
        for (int e = 0; e < NE; e++) masked[e] = gsel[e >> 2] ? s2[e] : 0.f;
        int inds[NTOPK];
        for (int it = 0; it < NTOPK; it++) {
            int bi = 0; float bv = -INFINITY;
            #pragma unroll
            for (int e = 0; e < NE; e++)
                if (masked[e] > bv) { bv = masked[e]; bi = e; }
            inds[it] = bi; masked[bi] = -INFINITY;
        }
        float wv[NTOPK], wsum = 0.f;
        #pragma unroll
        for (int i = 0; i < NTOPK; i++) { wv[i] = sc[inds[i]]; wsum += wv[i]; }
        float invw = RSF / (wsum + 1e-20f);
        float crow[NE];
        #pragma unroll
        for (int e = 0; e < NE; e++) crow[e] = 0.f;
        #pragma unroll
        for (int i = 0; i < NTOPK; i++) crow[inds[i]] += wv[i] * invw;
        #pragma unroll
        for (int e = 0; e < NE; e++) g_Cw[t * NE + e] = crow[e];
        #pragma unroll
        for (int i = 0; i < NTOPK; i++) {
            int e = inds[i];
            int posn = atomicAdd(&g_cnt[e], 1);
            g_bucket[e * NT + posn] = t;
        }
    }
}

// ---------------- elementwise combines ----------------
__global__ __launch_bounds__(256) void combine_expert_kernel()
{
    long stride = (long)gridDim.x * 256;
    for (int e = 0; e < NE; e++) {
        int cnt = g_cnt[e];
        long work = (long)cnt * EI;
        for (long idx = (long)blockIdx.x * 256 + threadIdx.x; idx < work; idx += stride) {
            int m = (int)(idx / EI);
            int tok = g_bucket[e * NT + m];
            float w = g_Cw[tok * NE + e];
            size_t o = ((size_t)e * NT + m) * EI + (idx % EI);
            float gv = g_eg[o], uv = g_eu[o];
            g_eg[o] = (gv / (1.f + expf(-gv))) * uv * w;
        }
    }
}

__global__ __launch_bounds__(256) void combine_shared_kernel()
{
    size_t idx = (size_t)blockIdx.x * 256 + threadIdx.x;
    if (idx >= (size_t)NT * SHI) return;
    float gv = g_sg[idx], uv = g_su[idx];
    g_sg[idx] = (gv / (1.f + expf(-gv))) * uv;
}

// ---------------- final: out = h1 + y ----------------
__global__ void final_add_kernel(float* __restrict__ out)
{
    int i = blockIdx.x * blockDim.x + threadIdx.x;
    if (i < NT * DMODEL) out[i] = g_h1[i] + g_y[i];
}

// ---------------- launch ----------------
extern "C" void kernel_launch(void* const* d_in, const int* in_sizes, int n_in,
                              void* d_out, int out_size)
{
    const float* x        = (const float*)d_in[0];
    const float* w_q      = (const float*)d_in[1];
    const float* w_k      = (const float*)d_in[2];
    const float* w_v      = (const float*)d_in[3];
    const float* w_o      = (const float*)d_in[4];
    const float* q_norm_w = (const float*)d_in[5];
    const float* k_norm_w = (const float*)d_in[6];
    const float* ln1_w    = (const float*)d_in[7];
    const float* ln2_w    = (const float*)d_in[8];
    const float* gate_w   = (const float*)d_in[9];
    const float* gate_b   = (const float*)d_in[10];
    const float* wg       = (const float*)d_in[11];
    const float* wu       = (const float*)d_in[12];
    const float* wd       = (const float*)d_in[13];
    const float* sh_g     = (const float*)d_in[14];
    const float* sh_u     = (const float*)d_in[15];
    const float* sh_d     = (const float*)d_in[16];
    float* out = (float*)d_out;

    static int attr_done = 0;
    if (!attr_done) {
        cudaFuncSetAttribute(qkv3_kernel,       cudaFuncAttributeMaxDynamicSharedMemorySize, GEMM_SMEM3);
        cudaFuncSetAttribute(gemm3o_kernel,     cudaFuncAttributeMaxDynamicSharedMemorySize, GEMM_SMEM3);
        cudaFuncSetAttribute(dense1_kernel,     cudaFuncAttributeMaxDynamicSharedMemorySize, GEMM_SMEM3);
        cudaFuncSetAttribute(dense1_dual_kernel,cudaFuncAttributeMaxDynamicSharedMemorySize, GEMM_SMEM3);
        cudaFuncSetAttribute(egu1_kernel,       cudaFuncAttributeMaxDynamicSharedMemorySize, GEMM_SMEM3);
        cudaFuncSetAttribute(edown1_kernel,     cudaFuncAttributeMaxDynamicSharedMemorySize, GEMM_SMEM3);
        attr_done = 1;
    }

    // host-side RoPE frequency table (double pow, fp32-rounded == reference)
    Freqs fr;
    for (int j = 0; j < 64; j++)
        fr.f[j] = (float)(1.0 / pow(1000000.0, (double)j / 64.0));

    float *ph, *ph1, *pt, *psg, *psu, *py, *pattn;
    cudaGetSymbolAddress((void**)&ph,    g_h);
    cudaGetSymbolAddress((void**)&ph1,   g_h1);
    cudaGetSymbolAddress((void**)&pt,    g_t);
    cudaGetSymbolAddress((void**)&psg,   g_sg);
    cudaGetSymbolAddress((void**)&psu,   g_su);
    cudaGetSymbolAddress((void**)&py,    g_y);
    cudaGetSymbolAddress((void**)&pattn, g_attn);

    // 1. pre-attn norm
    rmsnorm_kernel<<<LSEQ, 256>>>(x, ln1_w, ph);
    // 2. fused QKV projection (3xTF32, 3-stage)
    qkv3_kernel<<<dim3(24, 16), 256, GEMM_SMEM3>>>(ph, w_q, w_k, w_v);
    // 3. fused q/k rmsnorm + rope (inline fp32 trig)
    qknorm_rope_kernel<<<LSEQ * (NH + NKVH), 128>>>(q_norm_w, k_norm_w, fr);
    // 4. attention  <- profiled slot
    attn_kernel<<<dim3(LSEQ / 32, NH), 128>>>();
    // 5. output proj + residual (3xTF32, 3-stage)
    gemm3o_kernel<<<dim3(16, 16), 256, GEMM_SMEM3>>>(pattn, w_o, ph1, x);
    // 6. post-attn norm
    rmsnorm_kernel<<<LSEQ, 256>>>(ph1, ln2_w, pt);
    // 7. routing (fp32, exact)
    zero_cnt_kernel<<<1, 32>>>();
    gate_kernel<<<NT, 256>>>(gate_w, gate_b);
    // 8. shared expert: gate+up, combine, down (STORES y)
    dense1_dual_kernel<<<dim3(SHI / 128, NT / 128, 2), 256, GEMM_SMEM3>>>(
        pt, sh_g, sh_u, psg, psu, SHI, DMODEL);
    combine_shared_kernel<<<(int)(((size_t)NT * SHI + 255) / 256), 256>>>();
    dense1_kernel<<<dim3(DMODEL / 128, NT / 128), 256, GEMM_SMEM3>>>(psg, sh_d, py, DMODEL, SHI);
    // 9. routed experts: gate+up, combine, down (atomicAdd y)
    egu1_kernel<<<dim3(EI / 128, NT / 128, NE * 2), 256, GEMM_SMEM3>>>(wg, wu);
    combine_expert_kernel<<<1184, 256>>>();
    edown1_kernel<<<dim3(DMODEL / 128, NT / 128, NE), 256, GEMM_SMEM3>>>(wd);
    // 10. final residual add
    final_add_kernel<<<(NT * DMODEL + 255) / 256, 256>>>(out);
    (void)in_sizes; (void)n_in; (void)out_size;
}

// round 13
// speedup vs baseline: 1.5764x; 1.5764x over previous
#include <cuda_runtime.h>
#include <math.h>

#define LSEQ 2048
#define DMODEL 2048
#define NH 16
#define NKVH 4
#define HDIM 128
#define NE 16
#define NTOPK 4
#define NG 4
#define NTKG 2
#define EI 1024
#define SHI 2048
#define NT 2048
#define EPSV 1e-5f
#define ATTN_SCALE 0.08838834764831845f
#define RSF 2.5f

// 3x smem tile geometry: 128 rows x 32 k-floats, stride 36 (conflict-free)
#define TSTRIDE 36
#define TSTAGE  (128*TSTRIDE)
#define GEMM_SMEM3 (6*TSTAGE*4)        // 3 stages x (A+B), A=B=128 rows: 110592 B

// 1x smem tile geometry: A 128 rows, B 64 rows
#define A1STAGE (128*TSTRIDE)
#define B1STAGE (64*TSTRIDE)
#define GEMM_SMEM1 (3*(A1STAGE+B1STAGE)*4)   // 82944 B

typedef unsigned long long ull;

struct Freqs { float f[64]; };

// ---------------- scratch ----------------
__device__ float g_h   [LSEQ*DMODEL];
__device__ float g_q   [LSEQ*NH*HDIM];
__device__ float g_k   [LSEQ*NKVH*HDIM];
__device__ float g_v   [LSEQ*NKVH*HDIM];
__device__ float g_attn[LSEQ*NH*HDIM];
__device__ float g_h1  [LSEQ*DMODEL];
__device__ float g_t   [LSEQ*DMODEL];
__device__ float g_Cw  [NT*NE];
__device__ int   g_cnt [NE];
__device__ int   g_bucket[NE*NT];
__device__ float g_eg  [(size_t)NE*NT*EI];
__device__ float g_eu  [(size_t)NE*NT*EI];
__device__ float g_sg  [(size_t)NT*SHI];
__device__ float g_su  [(size_t)NT*SHI];
__device__ float g_y   [(size_t)NT*DMODEL];
__device__ float g_cos [LSEQ*64];
__device__ float g_sin [LSEQ*64];

// ---------------- helpers ----------------
__device__ __forceinline__ unsigned f2tf(float f){
    unsigned u; asm("cvt.rna.tf32.f32 %0,%1;" : "=r"(u) : "f"(f)); return u;
}
__device__ __forceinline__ void mma_tf32(float c[4],
    unsigned a0, unsigned a1, unsigned a2, unsigned a3, unsigned b0, unsigned b1)
{
    asm volatile("mma.sync.aligned.m16n8k8.row.col.f32.tf32.tf32.f32 "
        "{%0,%1,%2,%3},{%4,%5,%6,%7},{%8,%9},{%0,%1,%2,%3};"
        : "+f"(c[0]), "+f"(c[1]), "+f"(c[2]), "+f"(c[3])
        : "r"(a0), "r"(a1), "r"(a2), "r"(a3), "r"(b0), "r"(b1));
}
__device__ __forceinline__ unsigned sptr(const void* p){
    return (unsigned)__cvta_generic_to_shared(p);
}
__device__ __forceinline__ void ldsm4(unsigned &r0, unsigned &r1, unsigned &r2, unsigned &r3,
                                      unsigned addr)
{
    asm volatile("ldmatrix.sync.aligned.m8n8.x4.shared.b16 {%0,%1,%2,%3}, [%4];"
        : "=r"(r0), "=r"(r1), "=r"(r2), "=r"(r3) : "r"(addr));
}
#define CPA16(dst, src, n) asm volatile( \
    "cp.async.cg.shared.global [%0], [%1], 16, %2;\n" :: "r"(dst), "l"(src), "r"(n))
#define CPCOMMIT() asm volatile("cp.async.commit_group;\n" ::: "memory")
#define CPWAIT0()  asm volatile("cp.async.wait_group 0;\n" ::: "memory")
#define CPWAIT1()  asm volatile("cp.async.wait_group 1;\n" ::: "memory")

// f32x2 packed math
__device__ __forceinline__ ull pack2(float lo, float hi){
    ull r; asm("mov.b64 %0,{%1,%2};" : "=l"(r) : "f"(lo), "f"(hi)); return r;
}
__device__ __forceinline__ void unpack2(ull v, float &lo, float &hi){
    asm("mov.b64 {%0,%1},%2;" : "=f"(lo), "=f"(hi) : "l"(v));
}
__device__ __forceinline__ ull fma2(ull a, ull b, ull c){
    ull d; asm("fma.rn.f32x2 %0,%1,%2,%3;" : "=l"(d) : "l"(a), "l"(b), "l"(c)); return d;
}
__device__ __forceinline__ ull mul2(ull a, ull b){
    ull d; asm("mul.rn.f32x2 %0,%1,%2;" : "=l"(d) : "l"(a), "l"(b)); return d;
}

// ---------------- 3x fragment lane offsets (128x128 tile) ----------------
__device__ __forceinline__ void frag_offsets(int lane, int wm, int wn,
                                             unsigned* aOff, unsigned* bOff)
{
    int g = lane >> 3, lr = lane & 7;
    #pragma unroll
    for (int mt = 0; mt < 4; mt++)
        aOff[mt] = ((wm + mt*16 + (g & 1)*8 + lr) * TSTRIDE + (g >> 1)*4) * 4;
    #pragma unroll
    for (int p = 0; p < 2; p++)
        bOff[p] = ((wn + (2*p + (g >> 1))*8 + lr) * TSTRIDE + (g & 1)*4) * 4;
}

// ---------------- 1x fragment lane offsets (128x64 tile, warp 32x32) ----------------
__device__ __forceinline__ void frag_offsets64(int lane, int wm, int wn,
                                               unsigned* aOff, unsigned* bOff)
{
    int g = lane >> 3, lr = lane & 7;
    #pragma unroll
    for (int mt = 0; mt < 2; mt++)
        aOff[mt] = ((wm + mt*16 + (g & 1)*8 + lr) * TSTRIDE + (g >> 1)*4) * 4;
    #pragma unroll
    for (int p = 0; p < 2; p++)
        bOff[p] = ((wn + (2*p + (g >> 1))*8 + lr) * TSTRIDE + (g & 1)*4) * 4;
}

// ---------------- 3x MMA stage (128x128) ----------------
__device__ __forceinline__ void mma_ldsm_3x(unsigned baseA, unsigned baseB,
    const unsigned* aOff, const unsigned* bOff, float (*acc)[4][4])
{
    #pragma unroll
    for (int ks = 0; ks < 32; ks += 8) {
        unsigned a[4][4], b[2][4];
        #pragma unroll
        for (int mt = 0; mt < 4; mt++)
            ldsm4(a[mt][0], a[mt][1], a[mt][2], a[mt][3], baseA + aOff[mt] + ks*4);
        #pragma unroll
        for (int p = 0; p < 2; p++)
            ldsm4(b[p][0], b[p][1], b[p][2], b[p][3], baseB + bOff[p] + ks*4);
        unsigned aH[4][4], aL[4][4], bH[4][2], bL[4][2];
        #pragma unroll
        for (int mt = 0; mt < 4; mt++)
            #pragma unroll
            for (int i = 0; i < 4; i++) {
                float v = __uint_as_float(a[mt][i]);
                aH[mt][i] = f2tf(v);
                aL[mt][i] = f2tf(v - __uint_as_float(aH[mt][i]));
            }
        #pragma unroll
        for (int p = 0; p < 2; p++) {
            #pragma unroll
            for (int i = 0; i < 4; i++) {
                float v = __uint_as_float(b[p][i]);
                unsigned h = f2tf(v);
                unsigned l = f2tf(v - __uint_as_float(h));
                int nt = 2*p + (i >> 1), cc = i & 1;
                bH[nt][cc] = h; bL[nt][cc] = l;
            }
        }
        #pragma unroll
        for (int mt = 0; mt < 4; mt++)
            #pragma unroll
            for (int nt = 0; nt < 4; nt++) {
                mma_tf32(acc[mt][nt], aH[mt][0], aH[mt][1], aH[mt][2], aH[mt][3], bH[nt][0], bH[nt][1]);
                mma_tf32(acc[mt][nt], aL[mt][0], aL[mt][1], aL[mt][2], aL[mt][3], bH[nt][0], bH[nt][1]);
                mma_tf32(acc[mt][nt], aH[mt][0], aH[mt][1], aH[mt][2], aH[mt][3], bL[nt][0], bL[nt][1]);
            }
    }
}

// ---------------- 1x MMA stage (128x64, warp 32x32) ----------------
__device__ __forceinline__ void mma_ldsm_1x64(unsigned baseA, unsigned baseB,
    const unsigned* aOff, const unsigned* bOff, float (*acc)[4][4])
{
    #pragma unroll
    for (int ks = 0; ks < 32; ks += 8) {
        unsigned a[2][4], b[2][4];
        #pragma unroll
        for (int mt = 0; mt < 2; mt++)
            ldsm4(a[mt][0], a[mt][1], a[mt][2], a[mt][3], baseA + aOff[mt] + ks*4);
        #pragma unroll
        for (int p = 0; p < 2; p++)
            ldsm4(b[p][0], b[p][1], b[p][2], b[p][3], baseB + bOff[p] + ks*4);
        unsigned aT[2][4], bT[4][2];
        #pragma unroll
        for (int mt = 0; mt < 2; mt++)
            #pragma unroll
            for (int i = 0; i < 4; i++)
                aT[mt][i] = f2tf(__uint_as_float(a[mt][i]));
        #pragma unroll
        for (int p = 0; p < 2; p++) {
            bT[2*p][0]   = f2tf(__uint_as_float(b[p][0]));
            bT[2*p][1]   = f2tf(__uint_as_float(b[p][1]));
            bT[2*p+1][0] = f2tf(__uint_as_float(b[p][2]));
            bT[2*p+1][1] = f2tf(__uint_as_float(b[p][3]));
        }
        #pragma unroll
        for (int mt = 0; mt < 2; mt++)
            #pragma unroll
            for (int nt = 0; nt < 4; nt++)
                mma_tf32(acc[mt][nt], aT[mt][0], aT[mt][1], aT[mt][2], aT[mt][3],
                         bT[nt][0], bT[nt][1]);
    }
}

// ============ fused QKV projection (3xTF32, 3-stage pipeline) ============
__global__ __launch_bounds__(256, 2) void qkv3_kernel(const float* __restrict__ A,
    const float* __restrict__ wq, const float* __restrict__ wk, const float* __restrict__ wv)
{
    extern __shared__ float sm[];
    float* As = sm;
    float* Bs = sm + 3*TSTAGE;
    const int K = DMODEL;
    int tid = threadIdx.x, lane = tid & 31, warp = tid >> 5;
    int m0 = blockIdx.y * 128, n0 = blockIdx.x * 128;
    int wm = (warp & 1) * 64, wn = (warp >> 1) * 32;

    const float* B; float* Cp; int ldc, ncol0;
    if (n0 < 2048)      { B = wq + (size_t)n0 * K;          Cp = g_q; ldc = NH*HDIM;   ncol0 = n0; }
    else if (n0 < 2560) { B = wk + (size_t)(n0 - 2048) * K; Cp = g_k; ldc = NKVH*HDIM; ncol0 = n0 - 2048; }
    else                { B = wv + (size_t)(n0 - 2560) * K; Cp = g_v; ldc = NKVH*HDIM; ncol0 = n0 - 2560; }

    unsigned aOff[4], bOff[2];
    frag_offsets(lane, wm, wn, aOff, bOff);
    unsigned sA[3] = { sptr(As), sptr(As + TSTAGE), sptr(As + 2*TSTAGE) };
    unsigned sB[3] = { sptr(Bs), sptr(Bs + TSTAGE), sptr(Bs + 2*TSTAGE) };

    const float* aSrc[4]; const float* bSrc[4]; unsigned soff[4];
    #pragma unroll
    for (int i = 0; i < 4; i++) {
        int idx = tid + i * 256, row = idx >> 3, ch = idx & 7;
        soff[i] = (row * TSTRIDE + ch * 4) * 4;
        aSrc[i] = A + (size_t)(m0 + row) * K + ch * 4;
        bSrc[i] = B + (size_t)row * K + ch * 4;
    }
    #pragma unroll
    for (int s = 0; s < 2; s++) {
        #pragma unroll
        for (int i = 0; i < 4; i++) {
            CPA16(sA[s] + soff[i], aSrc[i] + s*32, 16);
            CPA16(sB[s] + soff[i], bSrc[i] + s*32, 16);
        }
        CPCOMMIT();
    }

    float acc[4][4][4] = {};
    const int nst = K / 32;
    for (int it = 0; it < nst; it++) {
        if (it + 1 < nst) { CPWAIT1(); } else { CPWAIT0(); }
        __syncthreads();
        int cur = it % 3;
        int pf = it + 2;
        if (pf < nst) {
            int buf = pf % 3;
            #pragma unroll
            for (int i = 0; i < 4; i++) {
                CPA16(sA[buf] + soff[i], aSrc[i] + pf*32, 16);
                CPA16(sB[buf] + soff[i], bSrc[i] + pf*32, 16);
            }
            CPCOMMIT();
        }
        mma_ldsm_3x(sA[cur], sB[cur], aOff, bOff, acc);
    }
    int r = lane >> 2, c2 = (lane & 3) * 2;
    #pragma unroll
    for (int mt = 0; mt < 4; mt++) {
        int mrow = m0 + wm + mt * 16 + r;
        #pragma unroll
        for (int nt = 0; nt < 4; nt++) {
            int col = ncol0 + wn + nt * 8 + c2;
            size_t i00 = (size_t)mrow * ldc + col;
            size_t i10 = (size_t)(mrow + 8) * ldc + col;
            Cp[i00] = acc[mt][nt][0]; Cp[i00+1] = acc[mt][nt][1];
            Cp[i10] = acc[mt][nt][2]; Cp[i10+1] = acc[mt][nt][3];
        }
    }
}

// ============ o-proj + residual (3xTF32, 3-stage) ============
__global__ __launch_bounds__(256, 2) void gemm3o_kernel(const float* __restrict__ A,
    const float* __restrict__ B, float* __restrict__ C, const float* __restrict__ R)
{
    extern __shared__ float sm[];
    float* As = sm;
    float* Bs = sm + 3*TSTAGE;
    const int K = NH*HDIM, N = DMODEL;
    int tid = threadIdx.x, lane = tid & 31, warp = tid >> 5;
    int m0 = blockIdx.y * 128, n0 = blockIdx.x * 128;
    int wm = (warp & 1) * 64, wn = (warp >> 1) * 32;

    unsigned aOff[4], bOff[2];
    frag_offsets(lane, wm, wn, aOff, bOff);
    unsigned sA[3] = { sptr(As), sptr(As + TSTAGE), sptr(As + 2*TSTAGE) };
    unsigned sB[3] = { sptr(Bs), sptr(Bs + TSTAGE), sptr(Bs + 2*TSTAGE) };

    const float* aSrc[4]; const float* bSrc[4]; unsigned soff[4];
    #pragma unroll
    for (int i = 0; i < 4; i++) {
        int idx = tid + i * 256, row = idx >> 3, ch = idx & 7;
        soff[i] = (row * TSTRIDE + ch * 4) * 4;
        aSrc[i] = A + (size_t)(m0 + row) * K + ch * 4;
        bSrc[i] = B + (size_t)(n0 + row) * K + ch * 4;
    }
    #pragma unroll
    for (int s = 0; s < 2; s++) {
        #pragma unroll
        for (int i = 0; i < 4; i++) {
            CPA16(sA[s] + soff[i], aSrc[i] + s*32, 16);
            CPA16(sB[s] + soff[i], bSrc[i] + s*32, 16);
        }
        CPCOMMIT();
    }

    float acc[4][4][4] = {};
    const int nst = K / 32;
    for (int it = 0; it < nst; it++) {
        if (it + 1 < nst) { CPWAIT1(); } else { CPWAIT0(); }
        __syncthreads();
        int cur = it % 3;
        int pf = it + 2;
        if (pf < nst) {
            int buf = pf % 3;
            #pragma unroll
            for (int i = 0; i < 4; i++) {
                CPA16(sA[buf] + soff[i], aSrc[i] + pf*32, 16);
                CPA16(sB[buf] + soff[i], bSrc[i] + pf*32, 16);
            }
            CPCOMMIT();
        }
        mma_ldsm_3x(sA[cur], sB[cur], aOff, bOff, acc);
    }
    int r = lane >> 2, c2 = (lane & 3) * 2;
    #pragma unroll
    for (int mt = 0; mt < 4; mt++) {
        int mrow = m0 + wm + mt * 16 + r;
        #pragma unroll
        for (int nt = 0; nt < 4; nt++) {
            int col = n0 + wn + nt * 8 + c2;
            size_t i00 = (size_t)mrow * N + col;
            size_t i10 = (size_t)(mrow + 8) * N + col;
            C[i00] = acc[mt][nt][0] + R[i00]; C[i00+1] = acc[mt][nt][1] + R[i00+1];
            C[i10] = acc[mt][nt][2] + R[i10]; C[i10+1] = acc[mt][nt][3] + R[i10+1];
        }
    }
}

// ============ dual dense 1xTF32 GEMM (128x64 tile, z selects gate/up) ============
__global__ __launch_bounds__(256, 2) void dense1_dual_kernel(const float* __restrict__ A,
    const float* __restrict__ B0, const float* __restrict__ B1,
    float* __restrict__ C0, float* __restrict__ C1, int N, int K)
{
    const float* Bsel = blockIdx.z ? B1 : B0;
    float* Csel = blockIdx.z ? C1 : C0;
    extern __shared__ float sm[];
    float* As = sm;
    float* Bs = sm + 3*A1STAGE;
    int tid = threadIdx.x, lane = tid & 31, warp = tid >> 5;
    int m0 = blockIdx.y * 128, n0 = blockIdx.x * 64;
    int wm = (warp >> 1) * 32, wn = (warp & 1) * 32;

    unsigned aOff[2], bOff[2];
    frag_offsets64(lane, wm, wn, aOff, bOff);
    unsigned sA[3] = { sptr(As), sptr(As + A1STAGE), sptr(As + 2*A1STAGE) };
    unsigned sB[3] = { sptr(Bs), sptr(Bs + B1STAGE), sptr(Bs + 2*B1STAGE) };

    const float* aSrc[4]; unsigned aSoff[4];
    const float* bSrc[2]; unsigned bSoff[2];
    #pragma unroll
    for (int i = 0; i < 4; i++) {
        int idx = tid + i * 256, row = idx >> 3, ch = idx & 7;
        aSoff[i] = (row * TSTRIDE + ch * 4) * 4;
        aSrc[i] = A + (size_t)(m0 + row) * K + ch * 4;
    }
    #pragma unroll
    for (int i = 0; i < 2; i++) {
        int idx = tid + i * 256, row = idx >> 3, ch = idx & 7;
        bSoff[i] = (row * TSTRIDE + ch * 4) * 4;
        bSrc[i] = Bsel + (size_t)(n0 + row) * K + ch * 4;
    }
    #pragma unroll
    for (int s = 0; s < 2; s++) {
        #pragma unroll
        for (int i = 0; i < 4; i++) CPA16(sA[s] + aSoff[i], aSrc[i] + s*32, 16);
        #pragma unroll
        for (int i = 0; i < 2; i++) CPA16(sB[s] + bSoff[i], bSrc[i] + s*32, 16);
        CPCOMMIT();
    }

    float acc[2][4][4] = {};
    const int nst = K / 32;
    for (int it = 0; it < nst; it++) {
        if (it + 1 < nst) { CPWAIT1(); } else { CPWAIT0(); }
        __syncthreads();
        int cur = it % 3;
        int pf = it + 2;
        if (pf < nst) {
            int buf = pf % 3;
            #pragma unroll
            for (int i = 0; i < 4; i++) CPA16(sA[buf] + aSoff[i], aSrc[i] + pf*32, 16);
            #pragma unroll
            for (int i = 0; i < 2; i++) CPA16(sB[buf] + bSoff[i], bSrc[i] + pf*32, 16);
            CPCOMMIT();
        }
        mma_ldsm_1x64(sA[cur], sB[cur], aOff, bOff, acc);
    }
    int r = lane >> 2, c2 = (lane & 3) * 2;
    #pragma unroll
    for (int mt = 0; mt < 2; mt++) {
        int mrow = m0 + wm + mt * 16 + r;
        #pragma unroll
        for (int nt = 0; nt < 4; nt++) {
            int col = n0 + wn + nt * 8 + c2;
            size_t i00 = (size_t)mrow * N + col;
            size_t i10 = (size_t)(mrow + 8) * N + col;
            Csel[i00] = acc[mt][nt][0]; Csel[i00+1] = acc[mt][nt][1];
            Csel[i10] = acc[mt][nt][2]; Csel[i10+1] = acc[mt][nt][3];
        }
    }
}

// ============ dense 1xTF32 GEMM (128x64 tile) ============
__global__ __launch_bounds__(256, 2) void dense1_kernel(const float* __restrict__ A,
    const float* __restrict__ B, float* __restrict__ C, int N, int K)
{
    extern __shared__ float sm[];
    float* As = sm;
    float* Bs = sm + 3*A1STAGE;
    int tid = threadIdx.x, lane = tid & 31, warp = tid >> 5;
    int m0 = blockIdx.y * 128, n0 = blockIdx.x * 64;
    int wm = (warp >> 1) * 32, wn = (warp & 1) * 32;

    unsigned aOff[2], bOff[2];
    frag_offsets64(lane, wm, wn, aOff, bOff);
    unsigned sA[3] = { sptr(As), sptr(As + A1STAGE), sptr(As + 2*A1STAGE) };
    unsigned sB[3] = { sptr(Bs), sptr(Bs + B1STAGE), sptr(Bs + 2*B1STAGE) };

    const float* aSrc[4]; unsigned aSoff[4];
    const float* bSrc[2]; unsigned bSoff[2];
    #pragma unroll
    for (int i = 0; i < 4; i++) {
        int idx = tid + i * 256, row = idx >> 3, ch = idx & 7;
        aSoff[i] = (row * TSTRIDE + ch * 4) * 4;
        aSrc[i] = A + (size_t)(m0 + row) * K + ch * 4;
    }
    #pragma unroll
    for (int i = 0; i < 2; i++) {
        int idx = tid + i * 256, row = idx >> 3, ch = idx & 7;
        bSoff[i] = (row * TSTRIDE + ch * 4) * 4;
        bSrc[i] = B + (size_t)(n0 + row) * K + ch * 4;
    }
    #pragma unroll
    for (int s = 0; s < 2; s++) {
        #pragma unroll
        for (int i = 0; i < 4; i++) CPA16(sA[s] + aSoff[i], aSrc[i] + s*32, 16);
        #pragma unroll
        for (int i = 0; i < 2; i++) CPA16(sB[s] + bSoff[i], bSrc[i] + s*32, 16);
        CPCOMMIT();
    }

    float acc[2][4][4] = {};
    const int nst = K / 32;
    for (int it = 0; it < nst; it++) {
        if (it + 1 < nst) { CPWAIT1(); } else { CPWAIT0(); }
        __syncthreads();
        int cur = it % 3;
        int pf = it + 2;
        if (pf < nst) {
            int buf = pf % 3;
            #pragma unroll
            for (int i = 0; i < 4; i++) CPA16(sA[buf] + aSoff[i], aSrc[i] + pf*32, 16);
            #pragma unroll
            for (int i = 0; i < 2; i++) CPA16(sB[buf] + bSoff[i], bSrc[i] + pf*32, 16);
            CPCOMMIT();
        }
        mma_ldsm_1x64(sA[cur], sB[cur], aOff, bOff, acc);
    }
    int r = lane >> 2, c2 = (lane & 3) * 2;
    #pragma unroll
    for (int mt = 0; mt < 2; mt++) {
        int mrow = m0 + wm + mt * 16 + r;
        #pragma unroll
        for (int nt = 0; nt < 4; nt++) {
            int col = n0 + wn + nt * 8 + c2;
            size_t i00 = (size_t)mrow * N + col;
            size_t i10 = (size_t)(mrow + 8) * N + col;
            C[i00] = acc[mt][nt][0]; C[i00+1] = acc[mt][nt][1];
            C[i10] = acc[mt][nt][2]; C[i10+1] = acc[mt][nt][3];
        }
    }
}

// ============ gathered expert gate+up GEMM (1x, 128x64 tile), z = e*2+which ============
__global__ __launch_bounds__(256, 2) void egu1_kernel(const float* __restrict__ wg,
    const float* __restrict__ wu)
{
    int e = blockIdx.z >> 1;
    int which = blockIdx.z & 1;
    int cnt = g_cnt[e];
    int m0 = blockIdx.y * 128;
    if (m0 >= cnt) return;
    int n0 = blockIdx.x * 64;
    const float* W = which ? wu : wg;
    float* Cout = which ? g_eu : g_eg;
    extern __shared__ float sm[];
    float* As = sm;
    float* Bs = sm + 3*A1STAGE;
    __shared__ int toks[128];
    const int K = DMODEL;
    int tid = threadIdx.x, lane = tid & 31, warp = tid >> 5;
    if (tid < 128) {
        int m = m0 + tid;
        toks[tid] = (m < cnt) ? g_bucket[e * NT + m] : -1;
    }
    __syncthreads();
    const float* B = W + (size_t)e * EI * DMODEL + (size_t)n0 * K;
    int wm = (warp >> 1) * 32, wn = (warp & 1) * 32;

    unsigned aOff[2], bOff[2];
    frag_offsets64(lane, wm, wn, aOff, bOff);
    unsigned sA[3] = { sptr(As), sptr(As + A1STAGE), sptr(As + 2*A1STAGE) };
    unsigned sB[3] = { sptr(Bs), sptr(Bs + B1STAGE), sptr(Bs + 2*B1STAGE) };

    const float* aSrc[4]; unsigned aSoff[4]; int aBytes[4];
    const float* bSrc[2]; unsigned bSoff[2];
    #pragma unroll
    for (int i = 0; i < 4; i++) {
        int idx = tid + i * 256, row = idx >> 3, ch = idx & 7;
        aSoff[i] = (row * TSTRIDE + ch * 4) * 4;
        int tok = toks[row];
        aBytes[i] = (tok >= 0) ? 16 : 0;
        aSrc[i] = g_t + (size_t)(tok >= 0 ? tok : 0) * K + ch * 4;
    }
    #pragma unroll
    for (int i = 0; i < 2; i++) {
        int idx = tid + i * 256, row = idx >> 3, ch = idx & 7;
        bSoff[i] = (row * TSTRIDE + ch * 4) * 4;
        bSrc[i] = B + (size_t)row * K + ch * 4;
    }
    #pragma unroll
    for (int s = 0; s < 2; s++) {
        #pragma unroll
        for (int i = 0; i < 4; i++) CPA16(sA[s] + aSoff[i], aSrc[i] + s*32, aBytes[i]);
        #pragma unroll
        for (int i = 0; i < 2; i++) CPA16(sB[s] + bSoff[i], bSrc[i] + s*32, 16);
        CPCOMMIT();
    }

    float acc[2][4][4] = {};
    const int nst = K / 32;
    for (int it = 0; it < nst; it++) {
        if (it + 1 < nst) { CPWAIT1(); } else { CPWAIT0(); }
        __syncthreads();
        int cur = it % 3;
        int pf = it + 2;
        if (pf < nst) {
            int buf = pf % 3;
            #pragma unroll
            for (int i = 0; i < 4; i++) CPA16(sA[buf] + aSoff[i], aSrc[i] + pf*32, aBytes[i]);
            #pragma unroll
            for (int i = 0; i < 2; i++) CPA16(sB[buf] + bSoff[i], bSrc[i] + pf*32, 16);
            CPCOMMIT();
        }
        mma_ldsm_1x64(sA[cur], sB[cur], aOff, bOff, acc);
    }
    int r = lane >> 2, c2 = (lane & 3) * 2;
    #pragma unroll
    for (int mt = 0; mt < 2; mt++) {
        int mloc = wm + mt * 16 + r;
        int m = m0 + mloc;
        #pragma unroll
        for (int nt = 0; nt < 4; nt++) {
            int col = n0 + wn + nt * 8 + c2;
            if (m < cnt) {
                size_t i00 = ((size_t)e * NT + m) * EI + col;
                Cout[i00] = acc[mt][nt][0]; Cout[i00+1] = acc[mt][nt][1];
            }
            if (m + 8 < cnt) {
                size_t i10 = ((size_t)e * NT + m + 8) * EI + col;
                Cout[i10] = acc[mt][nt][2]; Cout[i10+1] = acc[mt][nt][3];
            }
        }
    }
}

// ============ expert down GEMM (1x, 128x64 tile) + scatter atomicAdd ============
__global__ __launch_bounds__(256, 2) void edown1_kernel(const float* __restrict__ wd)
{
    int e = blockIdx.z;
    int cnt = g_cnt[e];
    int m0 = blockIdx.y * 128;
    if (m0 >= cnt) return;
    int n0 = blockIdx.x * 64;
    extern __shared__ float sm[];
    float* As = sm;
    float* Bs = sm + 3*A1STAGE;
    __shared__ int toks[128];
    const int K = EI;
    int tid = threadIdx.x, lane = tid & 31, warp = tid >> 5;
    if (tid < 128) {
        int m = m0 + tid;
        toks[tid] = (m < cnt) ? g_bucket[e * NT + m] : -1;
    }
    __syncthreads();
    const float* Ae = g_eg + ((size_t)e * NT + m0) * EI;
    const float* B = wd + (size_t)e * DMODEL * EI + (size_t)n0 * K;
    int wm = (warp >> 1) * 32, wn = (warp & 1) * 32;

    unsigned aOff[2], bOff[2];
    frag_offsets64(lane, wm, wn, aOff, bOff);
    unsigned sA[3] = { sptr(As), sptr(As + A1STAGE), sptr(As + 2*A1STAGE) };
    unsigned sB[3] = { sptr(Bs), sptr(Bs + B1STAGE), sptr(Bs + 2*B1STAGE) };

    const float* aSrc[4]; unsigned aSoff[4]; int aBytes[4];
    const float* bSrc[2]; unsigned bSoff[2];
    #pragma unroll
    for (int i = 0; i < 4; i++) {
        int idx = tid + i * 256, row = idx >> 3, ch = idx & 7;
        aSoff[i] = (row * TSTRIDE + ch * 4) * 4;
        bool ok = (m0 + row) < cnt;
        aBytes[i] = ok ? 16 : 0;
        aSrc[i] = Ae + (size_t)(ok ? row : 0) * K + ch * 4;
    }
    #pragma unroll
    for (int i = 0; i < 2; i++) {
        int idx = tid + i * 256, row = idx >> 3, ch = idx & 7;
        bSoff[i] = (row * TSTRIDE + ch * 4) * 4;
        bSrc[i] = B + (size_t)row * K + ch * 4;
    }
    #pragma unroll
    for (int s = 0; s < 2; s++) {
        #pragma unroll
        for (int i = 0; i < 4; i++) CPA16(sA[s] + aSoff[i], aSrc[i] + s*32, aBytes[i]);
        #pragma unroll
        for (int i = 0; i < 2; i++) CPA16(sB[s] + bSoff[i], bSrc[i] + s*32, 16);
        CPCOMMIT();
    }

    float acc[2][4][4] = {};
    const int nst = K / 32;
    for (int it = 0; it < nst; it++) {
        if (it + 1 < nst) { CPWAIT1(); } else { CPWAIT0(); }
        __syncthreads();
        int cur = it % 3;
        int pf = it + 2;
        if (pf < nst) {
            int buf = pf % 3;
            #pragma unroll
            for (int i = 0; i < 4; i++) CPA16(sA[buf] + aSoff[i], aSrc[i] + pf*32, aBytes[i]);
            #pragma unroll
            for (int i = 0; i < 2; i++) CPA16(sB[buf] + bSoff[i], bSrc[i] + pf*32, 16);
            CPCOMMIT();
        }
        mma_ldsm_1x64(sA[cur], sB[cur], aOff, bOff, acc);
    }
    int r = lane >> 2, c2 = (lane & 3) * 2;
    #pragma unroll
    for (int mt = 0; mt < 2; mt++) {
        int mloc = wm + mt * 16 + r;
        #pragma unroll
        for (int nt = 0; nt < 4; nt++) {
            int col = n0 + wn + nt * 8 + c2;
            if (m0 + mloc < cnt) {
                int tok = toks[mloc];
                atomicAdd(&g_y[(size_t)tok * DMODEL + col],     acc[mt][nt][0]);
                atomicAdd(&g_y[(size_t)tok * DMODEL + col + 1], acc[mt][nt][1]);
            }
            if (m0 + mloc + 8 < cnt) {
                int tok = toks[mloc + 8];
                atomicAdd(&g_y[(size_t)tok * DMODEL + col],     acc[mt][nt][2]);
                atomicAdd(&g_y[(size_t)tok * DMODEL + col + 1], acc[mt][nt][3]);
            }
        }
    }
}

// ---------------- RoPE table fill (fp32 only; host freqs; Cody-Waite reduction) ----------------
// 2*pi = 6.28125 + 4059*2^-21 + residual; k <= 326 so k*H1, k*H2 exact.
// Also zeroes expert counters (runs before gate each replay).
__global__ void rope_fill_kernel(Freqs fr)
{
    int pos = blockIdx.x, j = threadIdx.x;
    float ang = (float)pos * fr.f[j];
    float k = rintf(ang * 0.15915494309189535f);
    float red = ang - k * 6.28125f;
    red = red - k * 0.0019354820251464844f;
    red = red - k * (-1.7484556e-7f);
    float s, c;
    sincosf(red, &s, &c);
    g_cos[pos * 64 + j] = c;
    g_sin[pos * 64 + j] = s;
    if (pos == 0 && j < NE) g_cnt[j] = 0;
}

// ---------------- RMSNorm ----------------
__global__ __launch_bounds__(256) void rmsnorm_kernel(const float* __restrict__ x,
                                                      const float* __restrict__ w,
                                                      float* __restrict__ out)
{
    int row = blockIdx.x;
    const float* xr = x + (size_t)row * DMODEL;
    float ss = 0.f;
    for (int d = threadIdx.x; d < DMODEL; d += 256) { float v = xr[d]; ss += v * v; }
    __shared__ float red[8];
    #pragma unroll
    for (int off = 16; off; off >>= 1) ss += __shfl_xor_sync(0xffffffffu, ss, off);
    if ((threadIdx.x & 31) == 0) red[threadIdx.x >> 5] = ss;
    __syncthreads();
    __shared__ float sinv;
    if (threadIdx.x == 0) {
        float tot = 0.f;
        #pragma unroll
        for (int i = 0; i < 8; i++) tot += red[i];
        sinv = 1.f / sqrtf(tot / (float)DMODEL + EPSV);
    }
    __syncthreads();
    float si = sinv;
    for (int d = threadIdx.x; d < DMODEL; d += 256)
        out[(size_t)row * DMODEL + d] = xr[d] * si * w[d];
}

// ---------------- fused per-(token,head) RMSNorm + RoPE (table-based) ----------------
__global__ __launch_bounds__(128) void qknorm_rope_kernel(const float* __restrict__ qw,
                                                          const float* __restrict__ kw)
{
    int row = blockIdx.x;
    float* buf; const float* w; int nh;
    if (row < LSEQ * NH) { buf = g_q; w = qw; nh = NH; }
    else { row -= LSEQ * NH; buf = g_k; w = kw; nh = NKVH; }
    int pos = row / nh;
    float* p = buf + (size_t)row * HDIM;
    int tid = threadIdx.x;
    float v = p[tid];
    float ss = v * v;
    #pragma unroll
    for (int off = 16; off; off >>= 1) ss += __shfl_xor_sync(0xffffffffu, ss, off);
    __shared__ float red[4];
    if ((tid & 31) == 0) red[tid >> 5] = ss;
    __syncthreads();
    __shared__ float sinv;
    if (tid == 0) sinv = 1.f / sqrtf((red[0] + red[1] + red[2] + red[3]) / (float)HDIM + EPSV);
    __shared__ float shn[HDIM];
    __syncthreads();
    shn[tid] = v * sinv * w[tid];
    __syncthreads();
    if (tid < 64) {
        float x1 = shn[tid], x2 = shn[tid + 64];
        float c = g_cos[pos * 64 + tid], s = g_sin[pos * 64 + tid];
        p[tid]      = x1 * c - x2 * s;
        p[tid + 64] = x2 * c + x1 * s;
    }
}

// ---------------- flash attention (fp32 via f32x2, causal, GQA) ----------------
__global__ __launch_bounds__(128) void attn_kernel()
{
    __shared__ __align__(16) float Qs[32][HDIM];
    __shared__ __align__(16) float Ks[32][HDIM];
    __shared__ __align__(16) float Vs[32][HDIM];
    int h = blockIdx.y;
    int q0 = blockIdx.x * 32;
    int kvh = h >> 2;
    int tid = threadIdx.x;
    int r = tid >> 2, qd = tid & 3;

    for (int i = tid; i < 32 * 32; i += 128) {
        int row = i >> 5, d4 = i & 31;
        ((float4*)&Qs[row][0])[d4] =
            *(const float4*)(g_q + (size_t)(q0 + row) * (NH * HDIM) + h * HDIM + d4 * 4);
    }
    __syncthreads();
    ull qq[16];
    #pragma unroll
    for (int i = 0; i < 16; i++) qq[i] = *(const ull*)&Qs[r][qd * 32 + i * 2];

    ull o2[16];
    #pragma unroll
    for (int i = 0; i < 16; i++) o2[i] = 0ULL;
    float mrow = -INFINITY, lrow = 0.f;

    for (int k0 = 0; k0 <= q0; k0 += 32) {
        __syncthreads();
        for (int i = tid; i < 32 * 32; i += 128) {
            int row = i >> 5, d4 = i & 31;
            size_t base = (size_t)(k0 + row) * (NKVH * HDIM) + kvh * HDIM + d4 * 4;
            ((float4*)&Ks[row][0])[d4] = *(const float4*)(g_k + base);
            ((float4*)&Vs[row][0])[d4] = *(const float4*)(g_v + base);
        }
        __syncthreads();

        float s[32];
        float tmax = -INFINITY;
        #pragma unroll
        for (int j = 0; j < 32; j++) {
            const ull* K2 = (const ull*)&Ks[j][qd * 32];
            ull acc2 = 0ULL;
            #pragma unroll
            for (int i = 0; i < 16; i++) acc2 = fma2(qq[i], K2[i], acc2);
            float elo, ehi; unpack2(acc2, elo, ehi);
            float pacc = elo + ehi;
            pacc += __shfl_xor_sync(0xffffffffu, pacc, 1);
            pacc += __shfl_xor_sync(0xffffffffu, pacc, 2);
            pacc *= ATTN_SCALE;
            if (k0 + j > q0 + r) pacc = -INFINITY;
            s[j] = pacc;
            tmax = fmaxf(tmax, pacc);
        }
        float mnew = fmaxf(mrow, tmax);
        float alpha = __expf(mrow - mnew);
        lrow *= alpha;
        ull al2 = pack2(alpha, alpha);
        #pragma unroll
        for (int i = 0; i < 16; i++) o2[i] = mul2(o2[i], al2);
        #pragma unroll
        for (int j = 0; j < 32; j++) {
            float pv = __expf(s[j] - mnew);
            lrow += pv;
            ull pv2 = pack2(pv, pv);
            const ull* V2 = (const ull*)&Vs[j][qd * 32];
            #pragma unroll
            for (int i = 0; i < 16; i++) o2[i] = fma2(pv2, V2[i], o2[i]);
        }
        mrow = mnew;
    }
    float inv = 1.f / lrow;
    size_t base = (size_t)(q0 + r) * (NH * HDIM) + h * HDIM + qd * 32;
    #pragma unroll
    for (int i = 0; i < 16; i++) {
        float lo, hi; unpack2(o2[i], lo, hi);
        g_attn[base + i * 2]     = lo * inv;
        g_attn[base + i * 2 + 1] = hi * inv;
    }
}

// ---------------- gating / routing (fp32, exact) ----------------
__global__ __launch_bounds__(256) void gate_kernel(const float* __restrict__ gate_w,
                                                   const float* __restrict__ gate_bias)
{
    int t = blockIdx.x;
    const float* tr = g_t + (size_t)t * DMODEL;
    float acc[NE];
    #pragma unroll
    for (int e = 0; e < NE; e++) acc[e] = 0.f;
    for (int d = threadIdx.x; d < DMODEL; d += 256) {
        float xv = tr[d];
        #pragma unroll
        for (int e = 0; e < NE; e++) acc[e] += xv * gate_w[e * DMODEL + d];
    }
    __shared__ float red[NE * 8];
    int lane = threadIdx.x & 31, wid = threadIdx.x >> 5;
    #pragma unroll
    for (int e = 0; e < NE; e++) {
        float v = acc[e];
        #pragma unroll
        for (int off = 16; off; off >>= 1) v += __shfl_xor_sync(0xffffffffu, v, off);
        if (lane == 0) red[e * 8 + wid] = v;
    }
    __syncthreads();
    __shared__ float sc_s[NE];
    if (threadIdx.x < NE) {
        float sum = 0.f;
        #pragma unroll
        for (int wq = 0; wq < 8; wq++) sum += red[threadIdx.x * 8 + wq];
        sc_s[threadIdx.x] = 1.f / (1.f + expf(-sum));
    }
    __syncthreads();
    if (threadIdx.x == 0) {
        float sc[NE], s2[NE];
        #pragma unroll
        for (int e = 0; e < NE; e++) { sc[e] = sc_s[e]; s2[e] = sc[e] + gate_bias[e]; }
        float gs[NG];
        #pragma unroll
        for (int gq = 0; gq < NG; gq++) {
            float m1 = -INFINITY, m2 = -INFINITY;
            #pragma unroll
            for (int j = 0; j < NE / NG; j++) {
                float vv = s2[gq * (NE / NG) + j];
                if (vv > m1) { m2 = m1; m1 = vv; }
                else if (vv > m2) { m2 = vv; }
            }
            gs[gq] = m1 + m2;
        }
        bool gsel[NG] = {false, false, false, false};
        {
            float gtmp[NG];
            #pragma unroll
            for (int gq = 0; gq < NG; gq++) gtmp[gq] = gs[gq];
            for (int it = 0; it < NTKG; it++) {
                int bi = 0; float bv = -INFINITY;
                #pragma unroll
                for (int gq = 0; gq < NG; gq++)
                    if (gtmp[gq] > bv) { bv = gtmp[gq]; bi = gq; }
                gsel[bi] = true; gtmp[bi] = -INFINITY;
            }
        }
        float masked[NE];
        #pragma unroll
        for (int e = 0; e < NE; e++) masked[e] = gsel[e >> 2] ? s2[e] : 0.f;
        int inds[NTOPK];
        for (int it = 0; it < NTOPK; it++) {
            int bi = 0; float bv = -INFINITY;
            #pragma unroll
            for (int e = 0; e < NE; e++)
                if (masked[e] > bv) { bv = masked[e]; bi = e; }
            inds[it] = bi; masked[bi] = -INFINITY;
        }
        float wv[NTOPK], wsum = 0.f;
        #pragma unroll
        for (int i = 0; i < NTOPK; i++) { wv[i] = sc[inds[i]]; wsum += wv[i]; }
        float invw = RSF / (wsum + 1e-20f);
        float crow[NE];
        #pragma unroll
        for (int e = 0; e < NE; e++) crow[e] = 0.f;
        #pragma unroll
        for (int i = 0; i < NTOPK; i++) crow[inds[i]] += wv[i] * invw;
        #pragma unroll
        for (int e = 0; e < NE; e++) g_Cw[t * NE + e] = crow[e];
        #pragma unroll
        for (int i = 0; i < NTOPK; i++) {
            int e = inds[i];
            int posn = atomicAdd(&g_cnt[e], 1);
            g_bucket[e * NT + posn] = t;
        }
    }
}

// ---------------- elementwise combines ----------------
__global__ __launch_bounds__(256) void combine_expert_kernel()
{
    long stride = (long)gridDim.x * 256;
    for (int e = 0; e < NE; e++) {
        int cnt = g_cnt[e];
        long work = (long)cnt * EI;
        for (long idx = (long)blockIdx.x * 256 + threadIdx.x; idx < work; idx += stride) {
            int m = (int)(idx / EI);
            int tok = g_bucket[e * NT + m];
            float w = g_Cw[tok * NE + e];
            size_t o = ((size_t)e * NT + m) * EI + (idx % EI);
            float gv = g_eg[o], uv = g_eu[o];
            g_eg[o] = (gv / (1.f + expf(-gv))) * uv * w;
        }
    }
}

__global__ __launch_bounds__(256) void combine_shared_kernel()
{
    size_t idx = (size_t)blockIdx.x * 256 + threadIdx.x;
    if (idx >= (size_t)NT * SHI) return;
    float gv = g_sg[idx], uv = g_su[idx];
    g_sg[idx] = (gv / (1.f + expf(-gv))) * uv;
}

// ---------------- final: out = h1 + y ----------------
__global__ void final_add_kernel(float* __restrict__ out)
{
    int i = blockIdx.x * blockDim.x + threadIdx.x;
    if (i < NT * DMODEL) out[i] = g_h1[i] + g_y[i];
}

// ---------------- launch ----------------
extern "C" void kernel_launch(void* const* d_in, const int* in_sizes, int n_in,
                              void* d_out, int out_size)
{
    const float* x        = (const float*)d_in[0];
    const float* w_q      = (const float*)d_in[1];
    const float* w_k      = (const float*)d_in[2];
    const float* w_v      = (const float*)d_in[3];
    const float* w_o      = (const float*)d_in[4];
    const float* q_norm_w = (const float*)d_in[5];
    const float* k_norm_w = (const float*)d_in[6];
    const float* ln1_w    = (const float*)d_in[7];
    const float* ln2_w    = (const float*)d_in[8];
    const float* gate_w   = (const float*)d_in[9];
    const float* gate_b   = (const float*)d_in[10];
    const float* wg       = (const float*)d_in[11];
    const float* wu       = (const float*)d_in[12];
    const float* wd       = (const float*)d_in[13];
    const float* sh_g     = (const float*)d_in[14];
    const float* sh_u     = (const float*)d_in[15];
    const float* sh_d     = (const float*)d_in[16];
    float* out = (float*)d_out;

    static int attr_done = 0;
    if (!attr_done) {
        cudaFuncSetAttribute(qkv3_kernel,       cudaFuncAttributeMaxDynamicSharedMemorySize, GEMM_SMEM3);
        cudaFuncSetAttribute(gemm3o_kernel,     cudaFuncAttributeMaxDynamicSharedMemorySize, GEMM_SMEM3);
        cudaFuncSetAttribute(dense1_kernel,     cudaFuncAttributeMaxDynamicSharedMemorySize, GEMM_SMEM1);
        cudaFuncSetAttribute(dense1_dual_kernel,cudaFuncAttributeMaxDynamicSharedMemorySize, GEMM_SMEM1);
        cudaFuncSetAttribute(egu1_kernel,       cudaFuncAttributeMaxDynamicSharedMemorySize, GEMM_SMEM1);
        cudaFuncSetAttribute(edown1_kernel,     cudaFuncAttributeMaxDynamicSharedMemorySize, GEMM_SMEM1);
        attr_done = 1;
    }

    // host-side RoPE frequency table (double pow, fp32-rounded == reference)
    Freqs fr;
    for (int j = 0; j < 64; j++)
        fr.f[j] = (float)(1.0 / pow(1000000.0, (double)j / 64.0));

    float *ph, *ph1, *pt, *psg, *psu, *py, *pattn;
    cudaGetSymbolAddress((void**)&ph,    g_h);
    cudaGetSymbolAddress((void**)&ph1,   g_h1);
    cudaGetSymbolAddress((void**)&pt,    g_t);
    cudaGetSymbolAddress((void**)&psg,   g_sg);
    cudaGetSymbolAddress((void**)&psu,   g_su);
    cudaGetSymbolAddress((void**)&py,    g_y);
    cudaGetSymbolAddress((void**)&pattn, g_attn);

    // 1. RoPE table fill (fp32 trig) + expert counter zeroing
    rope_fill_kernel<<<LSEQ, 64>>>(fr);
    // 2. pre-attn norm
    rmsnorm_kernel<<<LSEQ, 256>>>(x, ln1_w, ph);
    // 3. fused QKV projection (3xTF32, 3-stage)
    qkv3_kernel<<<dim3(24, 16), 256, GEMM_SMEM3>>>(ph, w_q, w_k, w_v);
    // 4. fused q/k rmsnorm + rope (table)  <- profiled slot
    qknorm_rope_kernel<<<LSEQ * (NH + NKVH), 128>>>(q_norm_w, k_norm_w);
    // 5. attention
    attn_kernel<<<dim3(LSEQ / 32, NH), 128>>>();
    // 6. output proj + residual (3xTF32, 3-stage)
    gemm3o_kernel<<<dim3(16, 16), 256, GEMM_SMEM3>>>(pattn, w_o, ph1, x);
    // 7. post-attn norm
    rmsnorm_kernel<<<LSEQ, 256>>>(ph1, ln2_w, pt);
    // 8. routing (fp32, exact)
    gate_kernel<<<NT, 256>>>(gate_w, gate_b);
    // 9. shared expert: gate+up (128x64 1x), combine, down (STORES y)
    dense1_dual_kernel<<<dim3(SHI / 64, NT / 128, 2), 256, GEMM_SMEM1>>>(
        pt, sh_g, sh_u, psg, psu, SHI, DMODEL);
    combine_shared_kernel<<<(int)(((size_t)NT * SHI + 255) / 256), 256>>>();
    dense1_kernel<<<dim3(DMODEL / 64, NT / 128), 256, GEMM_SMEM1>>>(psg, sh_d, py, DMODEL, SHI);
    // 10. routed experts: gate+up, combine, down (atomicAdd y)
    egu1_kernel<<<dim3(EI / 64, NT / 128, NE * 2), 256, GEMM_SMEM1>>>(wg, wu);
    combine_expert_kernel<<<1184, 256>>>();
    edown1_kernel<<<dim3(DMODEL / 64, NT / 128, NE), 256, GEMM_SMEM1>>>(wd);
    // 11. final residual add
    final_add_kernel<<<(NT * DMODEL + 255) / 256, 256>>>(out);
    (void)in_sizes; (void)n_in; (void)out_size;
}

// round 14
// speedup vs baseline: 1.6095x; 1.0210x over previous
#include <cuda_runtime.h>
#include <math.h>

#define LSEQ 2048
#define DMODEL 2048
#define NH 16
#define NKVH 4
#define HDIM 128
#define NE 16
#define NTOPK 4
#define NG 4
#define NTKG 2
#define EI 1024
#define SHI 2048
#define NT 2048
#define EPSV 1e-5f
#define ATTN_SCALE 0.08838834764831845f
#define RSF 2.5f

// smem tile geometry: rows x 32 k-floats, stride 36 (conflict-free)
#define TSTRIDE 36
#define TSTAGE  (128*TSTRIDE)
#define GEMM_SMEM3 (6*TSTAGE*4)        // 3 stages x 256 rows = 110592 B (3x, 1x-128, fused)

typedef unsigned long long ull;

struct Freqs { float f[64]; };

// ---------------- scratch ----------------
__device__ float g_h   [LSEQ*DMODEL];
__device__ float g_q   [LSEQ*NH*HDIM];
__device__ float g_k   [LSEQ*NKVH*HDIM];
__device__ float g_v   [LSEQ*NKVH*HDIM];
__device__ float g_attn[LSEQ*NH*HDIM];
__device__ float g_h1  [LSEQ*DMODEL];
__device__ float g_t   [LSEQ*DMODEL];
__device__ float g_Cw  [NT*NE];
__device__ int   g_cnt [NE];
__device__ int   g_bucket[NE*NT];
__device__ float g_eg  [(size_t)NE*NT*EI];   // fused hm output (routed)
__device__ float g_sg  [(size_t)NT*SHI];     // fused hm output (shared)
__device__ float g_y   [(size_t)NT*DMODEL];

// ---------------- helpers ----------------
__device__ __forceinline__ unsigned f2tf(float f){
    unsigned u; asm("cvt.rna.tf32.f32 %0,%1;" : "=r"(u) : "f"(f)); return u;
}
__device__ __forceinline__ void mma_tf32(float c[4],
    unsigned a0, unsigned a1, unsigned a2, unsigned a3, unsigned b0, unsigned b1)
{
    asm volatile("mma.sync.aligned.m16n8k8.row.col.f32.tf32.tf32.f32 "
        "{%0,%1,%2,%3},{%4,%5,%6,%7},{%8,%9},{%0,%1,%2,%3};"
        : "+f"(c[0]), "+f"(c[1]), "+f"(c[2]), "+f"(c[3])
        : "r"(a0), "r"(a1), "r"(a2), "r"(a3), "r"(b0), "r"(b1));
}
__device__ __forceinline__ unsigned sptr(const void* p){
    return (unsigned)__cvta_generic_to_shared(p);
}
__device__ __forceinline__ void ldsm4(unsigned &r0, unsigned &r1, unsigned &r2, unsigned &r3,
                                      unsigned addr)
{
    asm volatile("ldmatrix.sync.aligned.m8n8.x4.shared.b16 {%0,%1,%2,%3}, [%4];"
        : "=r"(r0), "=r"(r1), "=r"(r2), "=r"(r3) : "r"(addr));
}
#define CPA16(dst, src, n) asm volatile( \
    "cp.async.cg.shared.global [%0], [%1], 16, %2;\n" :: "r"(dst), "l"(src), "r"(n))
#define CPCOMMIT() asm volatile("cp.async.commit_group;\n" ::: "memory")
#define CPWAIT0()  asm volatile("cp.async.wait_group 0;\n" ::: "memory")
#define CPWAIT1()  asm volatile("cp.async.wait_group 1;\n" ::: "memory")

// f32x2 packed math
__device__ __forceinline__ ull pack2(float lo, float hi){
    ull r; asm("mov.b64 %0,{%1,%2};" : "=l"(r) : "f"(lo), "f"(hi)); return r;
}
__device__ __forceinline__ void unpack2(ull v, float &lo, float &hi){
    asm("mov.b64 {%0,%1},%2;" : "=f"(lo), "=f"(hi) : "l"(v));
}
__device__ __forceinline__ ull fma2(ull a, ull b, ull c){
    ull d; asm("fma.rn.f32x2 %0,%1,%2,%3;" : "=l"(d) : "l"(a), "l"(b), "l"(c)); return d;
}
__device__ __forceinline__ ull mul2(ull a, ull b){
    ull d; asm("mul.rn.f32x2 %0,%1,%2;" : "=l"(d) : "l"(a), "l"(b)); return d;
}

// ---------------- fragment lane offsets ----------------
// 128x128 tile (warp 64x32): aOff[4] m-tiles, bOff[2] n-pairs
__device__ __forceinline__ void frag_offsets(int lane, int wm, int wn,
                                             unsigned* aOff, unsigned* bOff)
{
    int g = lane >> 3, lr = lane & 7;
    #pragma unroll
    for (int mt = 0; mt < 4; mt++)
        aOff[mt] = ((wm + mt*16 + (g & 1)*8 + lr) * TSTRIDE + (g >> 1)*4) * 4;
    #pragma unroll
    for (int p = 0; p < 2; p++)
        bOff[p] = ((wn + (2*p + (g >> 1))*8 + lr) * TSTRIDE + (g & 1)*4) * 4;
}
// warp 32x32 tile: aOff[2] m-tiles, bOff[2] n-pairs
__device__ __forceinline__ void frag_offsets32(int lane, int wm, int wn,
                                               unsigned* aOff, unsigned* bOff)
{
    int g = lane >> 3, lr = lane & 7;
    #pragma unroll
    for (int mt = 0; mt < 2; mt++)
        aOff[mt] = ((wm + mt*16 + (g & 1)*8 + lr) * TSTRIDE + (g >> 1)*4) * 4;
    #pragma unroll
    for (int p = 0; p < 2; p++)
        bOff[p] = ((wn + (2*p + (g >> 1))*8 + lr) * TSTRIDE + (g & 1)*4) * 4;
}

// ---------------- MMA stage: 3x compensated (128x128) ----------------
__device__ __forceinline__ void mma_ldsm_3x(unsigned baseA, unsigned baseB,
    const unsigned* aOff, const unsigned* bOff, float (*acc)[4][4])
{
    #pragma unroll
    for (int ks = 0; ks < 32; ks += 8) {
        unsigned a[4][4], b[2][4];
        #pragma unroll
        for (int mt = 0; mt < 4; mt++)
            ldsm4(a[mt][0], a[mt][1], a[mt][2], a[mt][3], baseA + aOff[mt] + ks*4);
        #pragma unroll
        for (int p = 0; p < 2; p++)
            ldsm4(b[p][0], b[p][1], b[p][2], b[p][3], baseB + bOff[p] + ks*4);
        unsigned aH[4][4], aL[4][4], bH[4][2], bL[4][2];
        #pragma unroll
        for (int mt = 0; mt < 4; mt++)
            #pragma unroll
            for (int i = 0; i < 4; i++) {
                float v = __uint_as_float(a[mt][i]);
                aH[mt][i] = f2tf(v);
                aL[mt][i] = f2tf(v - __uint_as_float(aH[mt][i]));
            }
        #pragma unroll
        for (int p = 0; p < 2; p++) {
            #pragma unroll
            for (int i = 0; i < 4; i++) {
                float v = __uint_as_float(b[p][i]);
                unsigned h = f2tf(v);
                unsigned l = f2tf(v - __uint_as_float(h));
                int nt = 2*p + (i >> 1), cc = i & 1;
                bH[nt][cc] = h; bL[nt][cc] = l;
            }
        }
        #pragma unroll
        for (int mt = 0; mt < 4; mt++)
            #pragma unroll
            for (int nt = 0; nt < 4; nt++) {
                mma_tf32(acc[mt][nt], aH[mt][0], aH[mt][1], aH[mt][2], aH[mt][3], bH[nt][0], bH[nt][1]);
                mma_tf32(acc[mt][nt], aL[mt][0], aL[mt][1], aL[mt][2], aL[mt][3], bH[nt][0], bH[nt][1]);
                mma_tf32(acc[mt][nt], aH[mt][0], aH[mt][1], aH[mt][2], aH[mt][3], bL[nt][0], bL[nt][1]);
            }
    }
}

// ---------------- MMA stage: 1x (128x128) ----------------
__device__ __forceinline__ void mma_ldsm_1x(unsigned baseA, unsigned baseB,
    const unsigned* aOff, const unsigned* bOff, float (*acc)[4][4])
{
    #pragma unroll
    for (int ks = 0; ks < 32; ks += 8) {
        unsigned a[4][4], b[2][4];
        #pragma unroll
        for (int mt = 0; mt < 4; mt++)
            ldsm4(a[mt][0], a[mt][1], a[mt][2], a[mt][3], baseA + aOff[mt] + ks*4);
        #pragma unroll
        for (int p = 0; p < 2; p++)
            ldsm4(b[p][0], b[p][1], b[p][2], b[p][3], baseB + bOff[p] + ks*4);
        unsigned aT[4][4], bT[4][2];
        #pragma unroll
        for (int mt = 0; mt < 4; mt++)
            #pragma unroll
            for (int i = 0; i < 4; i++)
                aT[mt][i] = f2tf(__uint_as_float(a[mt][i]));
        #pragma unroll
        for (int p = 0; p < 2; p++) {
            bT[2*p][0]   = f2tf(__uint_as_float(b[p][0]));
            bT[2*p][1]   = f2tf(__uint_as_float(b[p][1]));
            bT[2*p+1][0] = f2tf(__uint_as_float(b[p][2]));
            bT[2*p+1][1] = f2tf(__uint_as_float(b[p][3]));
        }
        #pragma unroll
        for (int mt = 0; mt < 4; mt++)
            #pragma unroll
            for (int nt = 0; nt < 4; nt++)
                mma_tf32(acc[mt][nt], aT[mt][0], aT[mt][1], aT[mt][2], aT[mt][3],
                         bT[nt][0], bT[nt][1]);
    }
}

// ---------------- MMA stage: fused gate+up 1x (A 128 rows, Bg/Bu 64 rows; warp 32x32) ----------------
__device__ __forceinline__ void mma_ldsm_gu(unsigned baseA, unsigned baseBg, unsigned baseBu,
    const unsigned* aOff, const unsigned* bOff,
    float (*accg)[4][4], float (*accu)[4][4])
{
    #pragma unroll
    for (int ks = 0; ks < 32; ks += 8) {
        unsigned a[2][4], bg[2][4], bu[2][4];
        #pragma unroll
        for (int mt = 0; mt < 2; mt++)
            ldsm4(a[mt][0], a[mt][1], a[mt][2], a[mt][3], baseA + aOff[mt] + ks*4);
        #pragma unroll
        for (int p = 0; p < 2; p++) {
            ldsm4(bg[p][0], bg[p][1], bg[p][2], bg[p][3], baseBg + bOff[p] + ks*4);
            ldsm4(bu[p][0], bu[p][1], bu[p][2], bu[p][3], baseBu + bOff[p] + ks*4);
        }
        unsigned aT[2][4], bgT[4][2], buT[4][2];
        #pragma unroll
        for (int mt = 0; mt < 2; mt++)
            #pragma unroll
            for (int i = 0; i < 4; i++)
                aT[mt][i] = f2tf(__uint_as_float(a[mt][i]));
        #pragma unroll
        for (int p = 0; p < 2; p++) {
            bgT[2*p][0]   = f2tf(__uint_as_float(bg[p][0]));
            bgT[2*p][1]   = f2tf(__uint_as_float(bg[p][1]));
            bgT[2*p+1][0] = f2tf(__uint_as_float(bg[p][2]));
            bgT[2*p+1][1] = f2tf(__uint_as_float(bg[p][3]));
            buT[2*p][0]   = f2tf(__uint_as_float(bu[p][0]));
            buT[2*p][1]   = f2tf(__uint_as_float(bu[p][1]));
            buT[2*p+1][0] = f2tf(__uint_as_float(bu[p][2]));
            buT[2*p+1][1] = f2tf(__uint_as_float(bu[p][3]));
        }
        #pragma unroll
        for (int mt = 0; mt < 2; mt++)
            #pragma unroll
            for (int nt = 0; nt < 4; nt++) {
                mma_tf32(accg[mt][nt], aT[mt][0], aT[mt][1], aT[mt][2], aT[mt][3],
                         bgT[nt][0], bgT[nt][1]);
                mma_tf32(accu[mt][nt], aT[mt][0], aT[mt][1], aT[mt][2], aT[mt][3],
                         buT[nt][0], buT[nt][1]);
            }
    }
}

// ============ fused QKV projection (3xTF32, 3-stage pipeline) ============
__global__ __launch_bounds__(256, 2) void qkv3_kernel(const float* __restrict__ A,
    const float* __restrict__ wq, const float* __restrict__ wk, const float* __restrict__ wv)
{
    extern __shared__ float sm[];
    float* As = sm;
    float* Bs = sm + 3*TSTAGE;
    const int K = DMODEL;
    int tid = threadIdx.x, lane = tid & 31, warp = tid >> 5;
    int m0 = blockIdx.y * 128, n0 = blockIdx.x * 128;
    int wm = (warp & 1) * 64, wn = (warp >> 1) * 32;

    const float* B; float* Cp; int ldc, ncol0;
    if (n0 < 2048)      { B = wq + (size_t)n0 * K;          Cp = g_q; ldc = NH*HDIM;   ncol0 = n0; }
    else if (n0 < 2560) { B = wk + (size_t)(n0 - 2048) * K; Cp = g_k; ldc = NKVH*HDIM; ncol0 = n0 - 2048; }
    else                { B = wv + (size_t)(n0 - 2560) * K; Cp = g_v; ldc = NKVH*HDIM; ncol0 = n0 - 2560; }

    unsigned aOff[4], bOff[2];
    frag_offsets(lane, wm, wn, aOff, bOff);
    unsigned sA[3] = { sptr(As), sptr(As + TSTAGE), sptr(As + 2*TSTAGE) };
    unsigned sB[3] = { sptr(Bs), sptr(Bs + TSTAGE), sptr(Bs + 2*TSTAGE) };

    const float* aSrc[4]; const float* bSrc[4]; unsigned soff[4];
    #pragma unroll
    for (int i = 0; i < 4; i++) {
        int idx = tid + i * 256, row = idx >> 3, ch = idx & 7;
        soff[i] = (row * TSTRIDE + ch * 4) * 4;
        aSrc[i] = A + (size_t)(m0 + row) * K + ch * 4;
        bSrc[i] = B + (size_t)row * K + ch * 4;
    }
    #pragma unroll
    for (int s = 0; s < 2; s++) {
        #pragma unroll
        for (int i = 0; i < 4; i++) {
            CPA16(sA[s] + soff[i], aSrc[i] + s*32, 16);
            CPA16(sB[s] + soff[i], bSrc[i] + s*32, 16);
        }
        CPCOMMIT();
    }

    float acc[4][4][4] = {};
    const int nst = K / 32;
    for (int it = 0; it < nst; it++) {
        if (it + 1 < nst) { CPWAIT1(); } else { CPWAIT0(); }
        __syncthreads();
        int cur = it % 3;
        int pf = it + 2;
        if (pf < nst) {
            int buf = pf % 3;
            #pragma unroll
            for (int i = 0; i < 4; i++) {
                CPA16(sA[buf] + soff[i], aSrc[i] + pf*32, 16);
                CPA16(sB[buf] + soff[i], bSrc[i] + pf*32, 16);
            }
            CPCOMMIT();
        }
        mma_ldsm_3x(sA[cur], sB[cur], aOff, bOff, acc);
    }
    int r = lane >> 2, c2 = (lane & 3) * 2;
    #pragma unroll
    for (int mt = 0; mt < 4; mt++) {
        int mrow = m0 + wm + mt * 16 + r;
        #pragma unroll
        for (int nt = 0; nt < 4; nt++) {
            int col = ncol0 + wn + nt * 8 + c2;
            size_t i00 = (size_t)mrow * ldc + col;
            size_t i10 = (size_t)(mrow + 8) * ldc + col;
            Cp[i00] = acc[mt][nt][0]; Cp[i00+1] = acc[mt][nt][1];
            Cp[i10] = acc[mt][nt][2]; Cp[i10+1] = acc[mt][nt][3];
        }
    }
}

// ============ o-proj + residual (3xTF32, 3-stage) ============
__global__ __launch_bounds__(256, 2) void gemm3o_kernel(const float* __restrict__ A,
    const float* __restrict__ B, float* __restrict__ C, const float* __restrict__ R)
{
    extern __shared__ float sm[];
    float* As = sm;
    float* Bs = sm + 3*TSTAGE;
    const int K = NH*HDIM, N = DMODEL;
    int tid = threadIdx.x, lane = tid & 31, warp = tid >> 5;
    int m0 = blockIdx.y * 128, n0 = blockIdx.x * 128;
    int wm = (warp & 1) * 64, wn = (warp >> 1) * 32;

    unsigned aOff[4], bOff[2];
    frag_offsets(lane, wm, wn, aOff, bOff);
    unsigned sA[3] = { sptr(As), sptr(As + TSTAGE), sptr(As + 2*TSTAGE) };
    unsigned sB[3] = { sptr(Bs), sptr(Bs + TSTAGE), sptr(Bs + 2*TSTAGE) };

    const float* aSrc[4]; const float* bSrc[4]; unsigned soff[4];
    #pragma unroll
    for (int i = 0; i < 4; i++) {
        int idx = tid + i * 256, row = idx >> 3, ch = idx & 7;
        soff[i] = (row * TSTRIDE + ch * 4) * 4;
        aSrc[i] = A + (size_t)(m0 + row) * K + ch * 4;
        bSrc[i] = B + (size_t)(n0 + row) * K + ch * 4;
    }
    #pragma unroll
    for (int s = 0; s < 2; s++) {
        #pragma unroll
        for (int i = 0; i < 4; i++) {
            CPA16(sA[s] + soff[i], aSrc[i] + s*32, 16);
            CPA16(sB[s] + soff[i], bSrc[i] + s*32, 16);
        }
        CPCOMMIT();
    }

    float acc[4][4][4] = {};
    const int nst = K / 32;
    for (int it = 0; it < nst; it++) {
        if (it + 1 < nst) { CPWAIT1(); } else { CPWAIT0(); }
        __syncthreads();
        int cur = it % 3;
        int pf = it + 2;
        if (pf < nst) {
            int buf = pf % 3;
            #pragma unroll
            for (int i = 0; i < 4; i++) {
                CPA16(sA[buf] + soff[i], aSrc[i] + pf*32, 16);
                CPA16(sB[buf] + soff[i], bSrc[i] + pf*32, 16);
            }
            CPCOMMIT();
        }
        mma_ldsm_3x(sA[cur], sB[cur], aOff, bOff, acc);
    }
    int r = lane >> 2, c2 = (lane & 3) * 2;
    #pragma unroll
    for (int mt = 0; mt < 4; mt++) {
        int mrow = m0 + wm + mt * 16 + r;
        #pragma unroll
        for (int nt = 0; nt < 4; nt++) {
            int col = n0 + wn + nt * 8 + c2;
            size_t i00 = (size_t)mrow * N + col;
            size_t i10 = (size_t)(mrow + 8) * N + col;
            C[i00] = acc[mt][nt][0] + R[i00]; C[i00+1] = acc[mt][nt][1] + R[i00+1];
            C[i10] = acc[mt][nt][2] + R[i10]; C[i10+1] = acc[mt][nt][3] + R[i10+1];
        }
    }
}

// ============ shared expert fused gate+up: g_sg = silu(t@shg^T)*(t@shu^T) ============
// Tile: A 128 rows x (Bg 64 | Bu 64). Warp 32x32 on each of gate/up.
__global__ __launch_bounds__(256, 2) void shgu_kernel(const float* __restrict__ A,
    const float* __restrict__ shg, const float* __restrict__ shu)
{
    extern __shared__ float sm[];
    float* As  = sm;                      // 3 x 128 rows
    float* Bgs = sm + 3*TSTAGE;           // 3 x 64 rows
    float* Bus = sm + 3*TSTAGE + 3*(64*TSTRIDE);
    const int K = DMODEL;
    int tid = threadIdx.x, lane = tid & 31, warp = tid >> 5;
    int m0 = blockIdx.y * 128, n0 = blockIdx.x * 64;
    int wm = (warp >> 1) * 32, wn = (warp & 1) * 32;

    unsigned aOff[2], bOff[2];
    frag_offsets32(lane, wm, wn, aOff, bOff);
    unsigned sA[3]  = { sptr(As), sptr(As + TSTAGE), sptr(As + 2*TSTAGE) };
    unsigned sBg[3] = { sptr(Bgs), sptr(Bgs + 64*TSTRIDE), sptr(Bgs + 2*64*TSTRIDE) };
    unsigned sBu[3] = { sptr(Bus), sptr(Bus + 64*TSTRIDE), sptr(Bus + 2*64*TSTRIDE) };

    const float* aSrc[4]; unsigned aSoff[4];
    const float* gSrc[2]; const float* uSrc[2]; unsigned bSoff[2];
    #pragma unroll
    for (int i = 0; i < 4; i++) {
        int idx = tid + i * 256, row = idx >> 3, ch = idx & 7;
        aSoff[i] = (row * TSTRIDE + ch * 4) * 4;
        aSrc[i] = A + (size_t)(m0 + row) * K + ch * 4;
    }
    #pragma unroll
    for (int i = 0; i < 2; i++) {
        int idx = tid + i * 256, row = idx >> 3, ch = idx & 7;
        bSoff[i] = (row * TSTRIDE + ch * 4) * 4;
        gSrc[i] = shg + (size_t)(n0 + row) * K + ch * 4;
        uSrc[i] = shu + (size_t)(n0 + row) * K + ch * 4;
    }
    #pragma unroll
    for (int s = 0; s < 2; s++) {
        #pragma unroll
        for (int i = 0; i < 4; i++) CPA16(sA[s] + aSoff[i], aSrc[i] + s*32, 16);
        #pragma unroll
        for (int i = 0; i < 2; i++) {
            CPA16(sBg[s] + bSoff[i], gSrc[i] + s*32, 16);
            CPA16(sBu[s] + bSoff[i], uSrc[i] + s*32, 16);
        }
        CPCOMMIT();
    }

    float accg[2][4][4] = {}, accu[2][4][4] = {};
    const int nst = K / 32;
    for (int it = 0; it < nst; it++) {
        if (it + 1 < nst) { CPWAIT1(); } else { CPWAIT0(); }
        __syncthreads();
        int cur = it % 3;
        int pf = it + 2;
        if (pf < nst) {
            int buf = pf % 3;
            #pragma unroll
            for (int i = 0; i < 4; i++) CPA16(sA[buf] + aSoff[i], aSrc[i] + pf*32, 16);
            #pragma unroll
            for (int i = 0; i < 2; i++) {
                CPA16(sBg[buf] + bSoff[i], gSrc[i] + pf*32, 16);
                CPA16(sBu[buf] + bSoff[i], uSrc[i] + pf*32, 16);
            }
            CPCOMMIT();
        }
        mma_ldsm_gu(sA[cur], sBg[cur], sBu[cur], aOff, bOff, accg, accu);
    }
    int r = lane >> 2, c2 = (lane & 3) * 2;
    #pragma unroll
    for (int mt = 0; mt < 2; mt++) {
        int mrow = m0 + wm + mt * 16 + r;
        #pragma unroll
        for (int nt = 0; nt < 4; nt++) {
            int col = n0 + wn + nt * 8 + c2;
            #pragma unroll
            for (int half = 0; half < 2; half++) {
                int rr = mrow + half * 8;
                float gv = accg[mt][nt][half*2], uv = accu[mt][nt][half*2];
                float gv1 = accg[mt][nt][half*2+1], uv1 = accu[mt][nt][half*2+1];
                size_t o = (size_t)rr * SHI + col;
                g_sg[o]   = (gv  / (1.f + expf(-gv)))  * uv;
                g_sg[o+1] = (gv1 / (1.f + expf(-gv1))) * uv1;
            }
        }
    }
}

// ============ routed expert fused gate+up: g_eg = silu(t@wg^T)*(t@wu^T)*Cw (gathered) ============
__global__ __launch_bounds__(256, 2) void egu_kernel(const float* __restrict__ wg,
    const float* __restrict__ wu)
{
    int e = blockIdx.z;
    int cnt = g_cnt[e];
    int m0 = blockIdx.y * 128;
    if (m0 >= cnt) return;
    int n0 = blockIdx.x * 64;
    extern __shared__ float sm[];
    float* As  = sm;
    float* Bgs = sm + 3*TSTAGE;
    float* Bus = sm + 3*TSTAGE + 3*(64*TSTRIDE);
    __shared__ int toks[128];
    const int K = DMODEL;
    int tid = threadIdx.x, lane = tid & 31, warp = tid >> 5;
    if (tid < 128) {
        int m = m0 + tid;
        toks[tid] = (m < cnt) ? g_bucket[e * NT + m] : -1;
    }
    __syncthreads();
    const float* Bg = wg + (size_t)e * EI * DMODEL + (size_t)n0 * K;
    const float* Bu = wu + (size_t)e * EI * DMODEL + (size_t)n0 * K;
    int wm = (warp >> 1) * 32, wn = (warp & 1) * 32;

    unsigned aOff[2], bOff[2];
    frag_offsets32(lane, wm, wn, aOff, bOff);
    unsigned sA[3]  = { sptr(As), sptr(As + TSTAGE), sptr(As + 2*TSTAGE) };
    unsigned sBg[3] = { sptr(Bgs), sptr(Bgs + 64*TSTRIDE), sptr(Bgs + 2*64*TSTRIDE) };
    unsigned sBu[3] = { sptr(Bus), sptr(Bus + 64*TSTRIDE), sptr(Bus + 2*64*TSTRIDE) };

    const float* aSrc[4]; unsigned aSoff[4]; int aBytes[4];
    const float* gSrc[2]; const float* uSrc[2]; unsigned bSoff[2];
    #pragma unroll
    for (int i = 0; i < 4; i++) {
        int idx = tid + i * 256, row = idx >> 3, ch = idx & 7;
        aSoff[i] = (row * TSTRIDE + ch * 4) * 4;
        int tok = toks[row];
        aBytes[i] = (tok >= 0) ? 16 : 0;
        aSrc[i] = g_t + (size_t)(tok >= 0 ? tok : 0) * K + ch * 4;
    }
    #pragma unroll
    for (int i = 0; i < 2; i++) {
        int idx = tid + i * 256, row = idx >> 3, ch = idx & 7;
        bSoff[i] = (row * TSTRIDE + ch * 4) * 4;
        gSrc[i] = Bg + (size_t)row * K + ch * 4;
        uSrc[i] = Bu + (size_t)row * K + ch * 4;
    }
    #pragma unroll
    for (int s = 0; s < 2; s++) {
        #pragma unroll
        for (int i = 0; i < 4; i++) CPA16(sA[s] + aSoff[i], aSrc[i] + s*32, aBytes[i]);
        #pragma unroll
        for (int i = 0; i < 2; i++) {
            CPA16(sBg[s] + bSoff[i], gSrc[i] + s*32, 16);
            CPA16(sBu[s] + bSoff[i], uSrc[i] + s*32, 16);
        }
        CPCOMMIT();
    }

    float accg[2][4][4] = {}, accu[2][4][4] = {};
    const int nst = K / 32;
    for (int it = 0; it < nst; it++) {
        if (it + 1 < nst) { CPWAIT1(); } else { CPWAIT0(); }
        __syncthreads();
        int cur = it % 3;
        int pf = it + 2;
        if (pf < nst) {
            int buf = pf % 3;
            #pragma unroll
            for (int i = 0; i < 4; i++) CPA16(sA[buf] + aSoff[i], aSrc[i] + pf*32, aBytes[i]);
            #pragma unroll
            for (int i = 0; i < 2; i++) {
                CPA16(sBg[buf] + bSoff[i], gSrc[i] + pf*32, 16);
                CPA16(sBu[buf] + bSoff[i], uSrc[i] + pf*32, 16);
            }
            CPCOMMIT();
        }
        mma_ldsm_gu(sA[cur], sBg[cur], sBu[cur], aOff, bOff, accg, accu);
    }
    int r = lane >> 2, c2 = (lane & 3) * 2;
    #pragma unroll
    for (int mt = 0; mt < 2; mt++) {
        int mloc = wm + mt * 16 + r;
        #pragma unroll
        for (int half = 0; half < 2; half++) {
            int m = m0 + mloc + half * 8;
            if (m >= cnt) continue;
            int tok = toks[mloc + half * 8];
            float wgt = g_Cw[tok * NE + e];
            #pragma unroll
            for (int nt = 0; nt < 4; nt++) {
                int col = n0 + wn + nt * 8 + c2;
                float gv = accg[mt][nt][half*2], uv = accu[mt][nt][half*2];
                float gv1 = accg[mt][nt][half*2+1], uv1 = accu[mt][nt][half*2+1];
                size_t o = ((size_t)e * NT + m) * EI + col;
                g_eg[o]   = (gv  / (1.f + expf(-gv)))  * uv  * wgt;
                g_eg[o+1] = (gv1 / (1.f + expf(-gv1))) * uv1 * wgt;
            }
        }
    }
}

// ============ dense 1xTF32 GEMM (128x128): shared-expert down, STORES C ============
__global__ __launch_bounds__(256, 2) void dense1_kernel(const float* __restrict__ A,
    const float* __restrict__ B, float* __restrict__ C, int N, int K)
{
    extern __shared__ float sm[];
    float* As = sm;
    float* Bs = sm + 3*TSTAGE;
    int tid = threadIdx.x, lane = tid & 31, warp = tid >> 5;
    int m0 = blockIdx.y * 128, n0 = blockIdx.x * 128;
    int wm = (warp & 1) * 64, wn = (warp >> 1) * 32;

    unsigned aOff[4], bOff[2];
    frag_offsets(lane, wm, wn, aOff, bOff);
    unsigned sA[3] = { sptr(As), sptr(As + TSTAGE), sptr(As + 2*TSTAGE) };
    unsigned sB[3] = { sptr(Bs), sptr(Bs + TSTAGE), sptr(Bs + 2*TSTAGE) };

    const float* aSrc[4]; const float* bSrc[4]; unsigned soff[4];
    #pragma unroll
    for (int i = 0; i < 4; i++) {
        int idx = tid + i * 256, row = idx >> 3, ch = idx & 7;
        soff[i] = (row * TSTRIDE + ch * 4) * 4;
        aSrc[i] = A + (size_t)(m0 + row) * K + ch * 4;
        bSrc[i] = B + (size_t)(n0 + row) * K + ch * 4;
    }
    #pragma unroll
    for (int s = 0; s < 2; s++) {
        #pragma unroll
        for (int i = 0; i < 4; i++) {
            CPA16(sA[s] + soff[i], aSrc[i] + s*32, 16);
            CPA16(sB[s] + soff[i], bSrc[i] + s*32, 16);
        }
        CPCOMMIT();
    }

    float acc[4][4][4] = {};
    const int nst = K / 32;
    for (int it = 0; it < nst; it++) {
        if (it + 1 < nst) { CPWAIT1(); } else { CPWAIT0(); }
        __syncthreads();
        int cur = it % 3;
        int pf = it + 2;
        if (pf < nst) {
            int buf = pf % 3;
            #pragma unroll
            for (int i = 0; i < 4; i++) {
                CPA16(sA[buf] + soff[i], aSrc[i] + pf*32, 16);
                CPA16(sB[buf] + soff[i], bSrc[i] + pf*32, 16);
            }
            CPCOMMIT();
        }
        mma_ldsm_1x(sA[cur], sB[cur], aOff, bOff, acc);
    }
    int r = lane >> 2, c2 = (lane & 3) * 2;
    #pragma unroll
    for (int mt = 0; mt < 4; mt++) {
        int mrow = m0 + wm + mt * 16 + r;
        #pragma unroll
        for (int nt = 0; nt < 4; nt++) {
            int col = n0 + wn + nt * 8 + c2;
            size_t i00 = (size_t)mrow * N + col;
            size_t i10 = (size_t)(mrow + 8) * N + col;
            C[i00] = acc[mt][nt][0]; C[i00+1] = acc[mt][nt][1];
            C[i10] = acc[mt][nt][2]; C[i10+1] = acc[mt][nt][3];
        }
    }
}

// ============ expert down GEMM (1x, 128x128) + scatter atomicAdd ============
__global__ __launch_bounds__(256, 2) void edown1_kernel(const float* __restrict__ wd)
{
    int e = blockIdx.z;
    int cnt = g_cnt[e];
    int m0 = blockIdx.y * 128;
    if (m0 >= cnt) return;
    int n0 = blockIdx.x * 128;
    extern __shared__ float sm[];
    float* As = sm;
    float* Bs = sm + 3*TSTAGE;
    __shared__ int toks[128];
    const int K = EI;
    int tid = threadIdx.x, lane = tid & 31, warp = tid >> 5;
    if (tid < 128) {
        int m = m0 + tid;
        toks[tid] = (m < cnt) ? g_bucket[e * NT + m] : -1;
    }
    __syncthreads();
    const float* Ae = g_eg + ((size_t)e * NT + m0) * EI;
    const float* B = wd + (size_t)e * DMODEL * EI + (size_t)n0 * K;
    int wm = (warp & 1) * 64, wn = (warp >> 1) * 32;

    unsigned aOff[4], bOff[2];
    frag_offsets(lane, wm, wn, aOff, bOff);
    unsigned sA[3] = { sptr(As), sptr(As + TSTAGE), sptr(As + 2*TSTAGE) };
    unsigned sB[3] = { sptr(Bs), sptr(Bs + TSTAGE), sptr(Bs + 2*TSTAGE) };

    const float* aSrc[4]; const float* bSrc[4]; unsigned soff[4]; int aBytes[4];
    #pragma unroll
    for (int i = 0; i < 4; i++) {
        int idx = tid + i * 256, row = idx >> 3, ch = idx & 7;
        soff[i] = (row * TSTRIDE + ch * 4) * 4;
        bool ok = (m0 + row) < cnt;
        aBytes[i] = ok ? 16 : 0;
        aSrc[i] = Ae + (size_t)(ok ? row : 0) * K + ch * 4;
        bSrc[i] = B + (size_t)row * K + ch * 4;
    }
    #pragma unroll
    for (int s = 0; s < 2; s++) {
        #pragma unroll
        for (int i = 0; i < 4; i++) {
            CPA16(sA[s] + soff[i], aSrc[i] + s*32, aBytes[i]);
            CPA16(sB[s] + soff[i], bSrc[i] + s*32, 16);
        }
        CPCOMMIT();
    }

    float acc[4][4][4] = {};
    const int nst = K / 32;
    for (int it = 0; it < nst; it++) {
        if (it + 1 < nst) { CPWAIT1(); } else { CPWAIT0(); }
        __syncthreads();
        int cur = it % 3;
        int pf = it + 2;
        if (pf < nst) {
            int buf = pf % 3;
            #pragma unroll
            for (int i = 0; i < 4; i++) {
                CPA16(sA[buf] + soff[i], aSrc[i] + pf*32, aBytes[i]);
                CPA16(sB[buf] + soff[i], bSrc[i] + pf*32, 16);
            }
            CPCOMMIT();
        }
        mma_ldsm_1x(sA[cur], sB[cur], aOff, bOff, acc);
    }
    int r = lane >> 2, c2 = (lane & 3) * 2;
    #pragma unroll
    for (int mt = 0; mt < 4; mt++) {
        int mloc = wm + mt * 16 + r;
        #pragma unroll
        for (int nt = 0; nt < 4; nt++) {
            int col = n0 + wn + nt * 8 + c2;
            if (m0 + mloc < cnt) {
                int tok = toks[mloc];
                atomicAdd(&g_y[(size_t)tok * DMODEL + col],     acc[mt][nt][0]);
                atomicAdd(&g_y[(size_t)tok * DMODEL + col + 1], acc[mt][nt][1]);
            }
            if (m0 + mloc + 8 < cnt) {
                int tok = toks[mloc + 8];
                atomicAdd(&g_y[(size_t)tok * DMODEL + col],     acc[mt][nt][2]);
                atomicAdd(&g_y[(size_t)tok * DMODEL + col + 1], acc[mt][nt][3]);
            }
        }
    }
}

// ---------------- RMSNorm ----------------
__global__ __launch_bounds__(256) void rmsnorm_kernel(const float* __restrict__ x,
                                                      const float* __restrict__ w,
                                                      float* __restrict__ out)
{
    int row = blockIdx.x;
    const float* xr = x + (size_t)row * DMODEL;
    float ss = 0.f;
    for (int d = threadIdx.x; d < DMODEL; d += 256) { float v = xr[d]; ss += v * v; }
    __shared__ float red[8];
    #pragma unroll
    for (int off = 16; off; off >>= 1) ss += __shfl_xor_sync(0xffffffffu, ss, off);
    if ((threadIdx.x & 31) == 0) red[threadIdx.x >> 5] = ss;
    __syncthreads();
    __shared__ float sinv;
    if (threadIdx.x == 0) {
        float tot = 0.f;
        #pragma unroll
        for (int i = 0; i < 8; i++) tot += red[i];
        sinv = 1.f / sqrtf(tot / (float)DMODEL + EPSV);
    }
    __syncthreads();
    float si = sinv;
    for (int d = threadIdx.x; d < DMODEL; d += 256)
        out[(size_t)row * DMODEL + d] = xr[d] * si * w[d];
}

// ---------------- fused per-(token,head) RMSNorm + RoPE (inline fp32 trig) ----------------
// 2*pi = 6.28125 + 4059*2^-21 + residual; k = rint(ang/2pi) <= 326 so k*H1, k*H2 exact.
// Block 0 also zeroes expert counters (gate runs much later).
__global__ __launch_bounds__(128) void qknorm_rope_kernel(const float* __restrict__ qw,
                                                          const float* __restrict__ kw,
                                                          Freqs fr)
{
    int row = blockIdx.x;
    if (row == 0 && threadIdx.x < NE) g_cnt[threadIdx.x] = 0;
    float* buf; const float* w; int nh;
    if (row < LSEQ * NH) { buf = g_q; w = qw; nh = NH; }
    else { row -= LSEQ * NH; buf = g_k; w = kw; nh = NKVH; }
    int pos = row / nh;
    float* p = buf + (size_t)row * HDIM;
    int tid = threadIdx.x;
    float v = p[tid];
    float ss = v * v;
    #pragma unroll
    for (int off = 16; off; off >>= 1) ss += __shfl_xor_sync(0xffffffffu, ss, off);
    __shared__ float red_s[4];
    if ((tid & 31) == 0) red_s[tid >> 5] = ss;
    __syncthreads();
    __shared__ float sinv;
    if (tid == 0) sinv = 1.f / sqrtf((red_s[0] + red_s[1] + red_s[2] + red_s[3]) / (float)HDIM + EPSV);
    __shared__ float shn[HDIM];
    __syncthreads();
    shn[tid] = v * sinv * w[tid];
    __syncthreads();
    if (tid < 64) {
        float x1 = shn[tid], x2 = shn[tid + 64];
        float ang = (float)pos * fr.f[tid];
        float k = rintf(ang * 0.15915494309189535f);
        float red = ang - k * 6.28125f;
        red = red - k * 0.0019354820251464844f;
        red = red - k * (-1.7484556e-7f);
        float s, c;
        sincosf(red, &s, &c);
        p[tid]      = x1 * c - x2 * s;
        p[tid + 64] = x2 * c + x1 * s;
    }
}

// ---------------- flash attention (fp32 via f32x2, causal, GQA) ----------------
__global__ __launch_bounds__(128) void attn_kernel()
{
    __shared__ __align__(16) float Qs[32][HDIM];
    __shared__ __align__(16) float Ks[32][HDIM];
    __shared__ __align__(16) float Vs[32][HDIM];
    int h = blockIdx.y;
    int q0 = blockIdx.x * 32;
    int kvh = h >> 2;
    int tid = threadIdx.x;
    int r = tid >> 2, qd = tid & 3;

    for (int i = tid; i < 32 * 32; i += 128) {
        int row = i >> 5, d4 = i & 31;
        ((float4*)&Qs[row][0])[d4] =
            *(const float4*)(g_q + (size_t)(q0 + row) * (NH * HDIM) + h * HDIM + d4 * 4);
    }
    __syncthreads();
    ull qq[16];
    #pragma unroll
    for (int i = 0; i < 16; i++) qq[i] = *(const ull*)&Qs[r][qd * 32 + i * 2];

    ull o2[16];
    #pragma unroll
    for (int i = 0; i < 16; i++) o2[i] = 0ULL;
    float mrow = -INFINITY, lrow = 0.f;

    for (int k0 = 0; k0 <= q0; k0 += 32) {
        __syncthreads();
        for (int i = tid; i < 32 * 32; i += 128) {
            int row = i >> 5, d4 = i & 31;
            size_t base = (size_t)(k0 + row) * (NKVH * HDIM) + kvh * HDIM + d4 * 4;
            ((float4*)&Ks[row][0])[d4] = *(const float4*)(g_k + base);
            ((float4*)&Vs[row][0])[d4] = *(const float4*)(g_v + base);
        }
        __syncthreads();

        float s[32];
        float tmax = -INFINITY;
        #pragma unroll
        for (int j = 0; j < 32; j++) {
            const ull* K2 = (const ull*)&Ks[j][qd * 32];
            ull acc2 = 0ULL;
            #pragma unroll
            for (int i = 0; i < 16; i++) acc2 = fma2(qq[i], K2[i], acc2);
            float elo, ehi; unpack2(acc2, elo, ehi);
            float pacc = elo + ehi;
            pacc += __shfl_xor_sync(0xffffffffu, pacc, 1);
            pacc += __shfl_xor_sync(0xffffffffu, pacc, 2);
            pacc *= ATTN_SCALE;
            if (k0 + j > q0 + r) pacc = -INFINITY;
            s[j] = pacc;
            tmax = fmaxf(tmax, pacc);
        }
        float mnew = fmaxf(mrow, tmax);
        float alpha = __expf(mrow - mnew);
        lrow *= alpha;
        ull al2 = pack2(alpha, alpha);
        #pragma unroll
        for (int i = 0; i < 16; i++) o2[i] = mul2(o2[i], al2);
        #pragma unroll
        for (int j = 0; j < 32; j++) {
            float pv = __expf(s[j] - mnew);
            lrow += pv;
            ull pv2 = pack2(pv, pv);
            const ull* V2 = (const ull*)&Vs[j][qd * 32];
            #pragma unroll
            for (int i = 0; i < 16; i++) o2[i] = fma2(pv2, V2[i], o2[i]);
        }
        mrow = mnew;
    }
    float inv = 1.f / lrow;
    size_t base = (size_t)(q0 + r) * (NH * HDIM) + h * HDIM + qd * 32;
    #pragma unroll
    for (int i = 0; i < 16; i++) {
        float lo, hi; unpack2(o2[i], lo, hi);
        g_attn[base + i * 2]     = lo * inv;
        g_attn[base + i * 2 + 1] = hi * inv;
    }
}

// ---------------- gating / routing (fp32 exact; coalesced: warp handles 2 experts) ----------------
__global__ __launch_bounds__(256) void gate_kernel(const float* __restrict__ gate_w,
                                                   const float* __restrict__ gate_bias)
{
    int t = blockIdx.x;
    const float4* t4 = (const float4*)(g_t + (size_t)t * DMODEL);
    int warp = threadIdx.x >> 5, lane = threadIdx.x & 31;
    int e0 = warp * 2;
    const float4* g0 = (const float4*)(gate_w + (size_t)e0 * DMODEL);
    const float4* g1 = (const float4*)(gate_w + (size_t)(e0 + 1) * DMODEL);
    float a0 = 0.f, a1 = 0.f;
    for (int i = lane; i < DMODEL / 4; i += 32) {
        float4 tv = t4[i], v0 = g0[i], v1 = g1[i];
        a0 += tv.x*v0.x + tv.y*v0.y + tv.z*v0.z + tv.w*v0.w;
        a1 += tv.x*v1.x + tv.y*v1.y + tv.z*v1.z + tv.w*v1.w;
    }
    #pragma unroll
    for (int off = 16; off; off >>= 1) {
        a0 += __shfl_xor_sync(0xffffffffu, a0, off);
        a1 += __shfl_xor_sync(0xffffffffu, a1, off);
    }
    __shared__ float sc_s[NE];
    if (lane == 0) {
        sc_s[e0]     = 1.f / (1.f + expf(-a0));
        sc_s[e0 + 1] = 1.f / (1.f + expf(-a1));
    }
    __syncthreads();
    if (threadIdx.x == 0) {
        float sc[NE], s2[NE];
        #pragma unroll
        for (int e = 0; e < NE; e++) { sc[e] = sc_s[e]; s2[e] = sc[e] + gate_bias[e]; }
        float gs[NG];
        #pragma unroll
        for (int gq = 0; gq < NG; gq++) {
            float m1 = -INFINITY, m2 = -INFINITY;
            #pragma unroll
            for (int j = 0; j < NE / NG; j++) {
                float vv = s2[gq * (NE / NG) + j];
                if (vv > m1) { m2 = m1; m1 = vv; }
                else if (vv > m2) { m2 = vv; }
            }
            gs[gq] = m1 + m2;
        }
        bool gsel[NG] = {false, false, false, false};
        {
            float gtmp[NG];
            #pragma unroll
            for (int gq = 0; gq < NG; gq++) gtmp[gq] = gs[gq];
            for (int it = 0; it < NTKG; it++) {
                int bi = 0; float bv = -INFINITY;
                #pragma unroll
                for (int gq = 0; gq < NG; gq++)
                    if (gtmp[gq] > bv) { bv = gtmp[gq]; bi = gq; }
                gsel[bi] = true; gtmp[bi] = -INFINITY;
            }
        }
        float masked[NE];
        #pragma unroll
        for (int e = 0; e < NE; e++) masked[e] = gsel[e >> 2] ? s2[e] : 0.f;
        int inds[NTOPK];
        for (int it = 0; it < NTOPK; it++) {
            int bi = 0; float bv = -INFINITY;
            #pragma unroll
            for (int e = 0; e < NE; e++)
                if (masked[e] > bv) { bv = masked[e]; bi = e; }
            inds[it] = bi; masked[bi] = -INFINITY;
        }
        float wv[NTOPK], wsum = 0.f;
        #pragma unroll
        for (int i = 0; i < NTOPK; i++) { wv[i] = sc[inds[i]]; wsum += wv[i]; }
        float invw = RSF / (wsum + 1e-20f);
        float crow[NE];
        #pragma unroll
        for (int e = 0; e < NE; e++) crow[e] = 0.f;
        #pragma unroll
        for (int i = 0; i < NTOPK; i++) crow[inds[i]] += wv[i] * invw;
        #pragma unroll
        for (int e = 0; e < NE; e++) g_Cw[t * NE + e] = crow[e];
        #pragma unroll
        for (int i = 0; i < NTOPK; i++) {
            int e = inds[i];
            int posn = atomicAdd(&g_cnt[e], 1);
            g_bucket[e * NT + posn] = t;
        }
    }
}

// ---------------- final: out = h1 + y ----------------
__global__ void final_add_kernel(float* __restrict__ out)
{
    int i = blockIdx.x * blockDim.x + threadIdx.x;
    if (i < NT * DMODEL) out[i] = g_h1[i] + g_y[i];
}

// ---------------- launch ----------------
extern "C" void kernel_launch(void* const* d_in, const int* in_sizes, int n_in,
                              void* d_out, int out_size)
{
    const float* x        = (const float*)d_in[0];
    const float* w_q      = (const float*)d_in[1];
    const float* w_k      = (const float*)d_in[2];
    const float* w_v      = (const float*)d_in[3];
    const float* w_o      = (const float*)d_in[4];
    const float* q_norm_w = (const float*)d_in[5];
    const float* k_norm_w = (const float*)d_in[6];
    const float* ln1_w    = (const float*)d_in[7];
    const float* ln2_w    = (const float*)d_in[8];
    const float* gate_w   = (const float*)d_in[9];
    const float* gate_b   = (const float*)d_in[10];
    const float* wg       = (const float*)d_in[11];
    const float* wu       = (const float*)d_in[12];
    const float* wd       = (const float*)d_in[13];
    const float* sh_g     = (const float*)d_in[14];
    const float* sh_u     = (const float*)d_in[15];
    const float* sh_d     = (const float*)d_in[16];
    float* out = (float*)d_out;

    static int attr_done = 0;
    if (!attr_done) {
        cudaFuncSetAttribute(qkv3_kernel,   cudaFuncAttributeMaxDynamicSharedMemorySize, GEMM_SMEM3);
        cudaFuncSetAttribute(gemm3o_kernel, cudaFuncAttributeMaxDynamicSharedMemorySize, GEMM_SMEM3);
        cudaFuncSetAttribute(shgu_kernel,   cudaFuncAttributeMaxDynamicSharedMemorySize, GEMM_SMEM3);
        cudaFuncSetAttribute(egu_kernel,    cudaFuncAttributeMaxDynamicSharedMemorySize, GEMM_SMEM3);
        cudaFuncSetAttribute(dense1_kernel, cudaFuncAttributeMaxDynamicSharedMemorySize, GEMM_SMEM3);
        cudaFuncSetAttribute(edown1_kernel, cudaFuncAttributeMaxDynamicSharedMemorySize, GEMM_SMEM3);
        attr_done = 1;
    }

    // host-side RoPE frequency table (double pow, fp32-rounded == reference)
    Freqs fr;
    for (int j = 0; j < 64; j++)
        fr.f[j] = (float)(1.0 / pow(1000000.0, (double)j / 64.0));

    float *ph, *ph1, *pt, *psg, *py, *pattn;
    cudaGetSymbolAddress((void**)&ph,    g_h);
    cudaGetSymbolAddress((void**)&ph1,   g_h1);
    cudaGetSymbolAddress((void**)&pt,    g_t);
    cudaGetSymbolAddress((void**)&psg,   g_sg);
    cudaGetSymbolAddress((void**)&py,    g_y);
    cudaGetSymbolAddress((void**)&pattn, g_attn);

    // 0. pre-attn norm
    rmsnorm_kernel<<<LSEQ, 256>>>(x, ln1_w, ph);
    // 1. fused QKV projection (3xTF32, 3-stage)
    qkv3_kernel<<<dim3(24, 16), 256, GEMM_SMEM3>>>(ph, w_q, w_k, w_v);
    // 2. fused q/k rmsnorm + rope (inline fp32 trig) + cnt zeroing
    qknorm_rope_kernel<<<LSEQ * (NH + NKVH), 128>>>(q_norm_w, k_norm_w, fr);
    // 3. attention  <- profiled slot
    attn_kernel<<<dim3(LSEQ / 32, NH), 128>>>();
    // 4. output proj + residual (3xTF32)
    gemm3o_kernel<<<dim3(16, 16), 256, GEMM_SMEM3>>>(pattn, w_o, ph1, x);
    // 5. post-attn norm
    rmsnorm_kernel<<<LSEQ, 256>>>(ph1, ln2_w, pt);
    // 6. routing (fp32, exact, coalesced)
    gate_kernel<<<NT, 256>>>(gate_w, gate_b);
    // 7. shared expert fused gate+up+silu-mul -> g_sg
    shgu_kernel<<<dim3(SHI / 64, NT / 128), 256, GEMM_SMEM3>>>(pt, sh_g, sh_u);
    // 8. shared expert down (STORES y)
    dense1_kernel<<<dim3(DMODEL / 128, NT / 128), 256, GEMM_SMEM3>>>(psg, sh_d, py, DMODEL, SHI);
    // 9. routed experts fused gate+up+silu-mul-scale -> g_eg
    egu_kernel<<<dim3(EI / 64, NT / 128, NE), 256, GEMM_SMEM3>>>(wg, wu);
    // 10. routed down (atomicAdd y)
    edown1_kernel<<<dim3(DMODEL / 128, NT / 128, NE), 256, GEMM_SMEM3>>>(wd);
    // 11. final residual add
    final_add_kernel<<<(NT * DMODEL + 255) / 256, 256>>>(out);
    (void)in_sizes; (void)n_in; (void)out_size;
}

// round 15
// speedup vs baseline: 1.6384x; 1.0180x over previous
#include <cuda_runtime.h>
#include <math.h>

#define LSEQ 2048
#define DMODEL 2048
#define NH 16
#define NKVH 4
#define HDIM 128
#define NE 16
#define NTOPK 4
#define NG 4
#define NTKG 2
#define EI 1024
#define SHI 2048
#define NT 2048
#define EPSV 1e-5f
#define ATTN_SCALE 0.08838834764831845f
#define RSF 2.5f

#define TSTRIDE 36
#define TSTAGE  (128*TSTRIDE)
#define GEMM_SMEM3 (6*TSTAGE*4)        // 110592 B

typedef unsigned long long ull;

struct Freqs { float f[64]; };

// ---------------- scratch ----------------
__device__ float g_h   [LSEQ*DMODEL];
__device__ float g_q   [LSEQ*NH*HDIM];
__device__ float g_k   [LSEQ*NKVH*HDIM];
__device__ float g_v   [LSEQ*NKVH*HDIM];
__device__ float g_attn[LSEQ*NH*HDIM];
__device__ float g_h1  [LSEQ*DMODEL];
__device__ float g_t   [LSEQ*DMODEL];     // full precision (gate)
__device__ float g_tr  [LSEQ*DMODEL];     // tf32-rounded copy (MoE A-side)
__device__ float g_Cw  [NT*NE];
__device__ int   g_cnt [NE];
__device__ int   g_bucket[NE*NT];
__device__ float g_eg  [(size_t)NE*NT*EI];
__device__ float g_sg  [(size_t)NT*SHI];
__device__ float g_y   [(size_t)NT*DMODEL];
// rounded weight copies (written once per launch by round_kernel)
__device__ float g_wgr [(size_t)NE*EI*DMODEL];
__device__ float g_wur [(size_t)NE*EI*DMODEL];
__device__ float g_wdr [(size_t)NE*DMODEL*EI];
__device__ float g_shgr[(size_t)SHI*DMODEL];
__device__ float g_shur[(size_t)SHI*DMODEL];
__device__ float g_shdr[(size_t)DMODEL*SHI];

// ---------------- helpers ----------------
__device__ __forceinline__ unsigned f2tf(float f){
    unsigned u; asm("cvt.rna.tf32.f32 %0,%1;" : "=r"(u) : "f"(f)); return u;
}
__device__ __forceinline__ float roundtf(float f){
    return __uint_as_float(f2tf(f));
}
__device__ __forceinline__ void mma_tf32(float c[4],
    unsigned a0, unsigned a1, unsigned a2, unsigned a3, unsigned b0, unsigned b1)
{
    asm volatile("mma.sync.aligned.m16n8k8.row.col.f32.tf32.tf32.f32 "
        "{%0,%1,%2,%3},{%4,%5,%6,%7},{%8,%9},{%0,%1,%2,%3};"
        : "+f"(c[0]), "+f"(c[1]), "+f"(c[2]), "+f"(c[3])
        : "r"(a0), "r"(a1), "r"(a2), "r"(a3), "r"(b0), "r"(b1));
}
__device__ __forceinline__ unsigned sptr(const void* p){
    return (unsigned)__cvta_generic_to_shared(p);
}
__device__ __forceinline__ void ldsm4(unsigned &r0, unsigned &r1, unsigned &r2, unsigned &r3,
                                      unsigned addr)
{
    asm volatile("ldmatrix.sync.aligned.m8n8.x4.shared.b16 {%0,%1,%2,%3}, [%4];"
        : "=r"(r0), "=r"(r1), "=r"(r2), "=r"(r3) : "r"(addr));
}
#define CPA16(dst, src, n) asm volatile( \
    "cp.async.cg.shared.global [%0], [%1], 16, %2;\n" :: "r"(dst), "l"(src), "r"(n))
#define CPCOMMIT() asm volatile("cp.async.commit_group;\n" ::: "memory")
#define CPWAIT0()  asm volatile("cp.async.wait_group 0;\n" ::: "memory")
#define CPWAIT1()  asm volatile("cp.async.wait_group 1;\n" ::: "memory")

// f32x2 packed math
__device__ __forceinline__ ull pack2(float lo, float hi){
    ull r; asm("mov.b64 %0,{%1,%2};" : "=l"(r) : "f"(lo), "f"(hi)); return r;
}
__device__ __forceinline__ void unpack2(ull v, float &lo, float &hi){
    asm("mov.b64 {%0,%1},%2;" : "=f"(lo), "=f"(hi) : "l"(v));
}
__device__ __forceinline__ ull fma2(ull a, ull b, ull c){
    ull d; asm("fma.rn.f32x2 %0,%1,%2,%3;" : "=l"(d) : "l"(a), "l"(b), "l"(c)); return d;
}
__device__ __forceinline__ ull mul2(ull a, ull b){
    ull d; asm("mul.rn.f32x2 %0,%1,%2;" : "=l"(d) : "l"(a), "l"(b)); return d;
}

// ---------------- fragment lane offsets ----------------
__device__ __forceinline__ void frag_offsets(int lane, int wm, int wn,
                                             unsigned* aOff, unsigned* bOff)
{
    int g = lane >> 3, lr = lane & 7;
    #pragma unroll
    for (int mt = 0; mt < 4; mt++)
        aOff[mt] = ((wm + mt*16 + (g & 1)*8 + lr) * TSTRIDE + (g >> 1)*4) * 4;
    #pragma unroll
    for (int p = 0; p < 2; p++)
        bOff[p] = ((wn + (2*p + (g >> 1))*8 + lr) * TSTRIDE + (g & 1)*4) * 4;
}
__device__ __forceinline__ void frag_offsets32(int lane, int wm, int wn,
                                               unsigned* aOff, unsigned* bOff)
{
    int g = lane >> 3, lr = lane & 7;
    #pragma unroll
    for (int mt = 0; mt < 2; mt++)
        aOff[mt] = ((wm + mt*16 + (g & 1)*8 + lr) * TSTRIDE + (g >> 1)*4) * 4;
    #pragma unroll
    for (int p = 0; p < 2; p++)
        bOff[p] = ((wn + (2*p + (g >> 1))*8 + lr) * TSTRIDE + (g & 1)*4) * 4;
}

// ---------------- MMA stage: 3x compensated (128x128), cvt in-loop (unchanged) ----------------
__device__ __forceinline__ void mma_ldsm_3x(unsigned baseA, unsigned baseB,
    const unsigned* aOff, const unsigned* bOff, float (*acc)[4][4])
{
    #pragma unroll
    for (int ks = 0; ks < 32; ks += 8) {
        unsigned a[4][4], b[2][4];
        #pragma unroll
        for (int mt = 0; mt < 4; mt++)
            ldsm4(a[mt][0], a[mt][1], a[mt][2], a[mt][3], baseA + aOff[mt] + ks*4);
        #pragma unroll
        for (int p = 0; p < 2; p++)
            ldsm4(b[p][0], b[p][1], b[p][2], b[p][3], baseB + bOff[p] + ks*4);
        unsigned aH[4][4], aL[4][4], bH[4][2], bL[4][2];
        #pragma unroll
        for (int mt = 0; mt < 4; mt++)
            #pragma unroll
            for (int i = 0; i < 4; i++) {
                float v = __uint_as_float(a[mt][i]);
                aH[mt][i] = f2tf(v);
                aL[mt][i] = f2tf(v - __uint_as_float(aH[mt][i]));
            }
        #pragma unroll
        for (int p = 0; p < 2; p++) {
            #pragma unroll
            for (int i = 0; i < 4; i++) {
                float v = __uint_as_float(b[p][i]);
                unsigned h = f2tf(v);
                unsigned l = f2tf(v - __uint_as_float(h));
                int nt = 2*p + (i >> 1), cc = i & 1;
                bH[nt][cc] = h; bL[nt][cc] = l;
            }
        }
        #pragma unroll
        for (int mt = 0; mt < 4; mt++)
            #pragma unroll
            for (int nt = 0; nt < 4; nt++) {
                mma_tf32(acc[mt][nt], aH[mt][0], aH[mt][1], aH[mt][2], aH[mt][3], bH[nt][0], bH[nt][1]);
                mma_tf32(acc[mt][nt], aL[mt][0], aL[mt][1], aL[mt][2], aL[mt][3], bH[nt][0], bH[nt][1]);
                mma_tf32(acc[mt][nt], aH[mt][0], aH[mt][1], aH[mt][2], aH[mt][3], bL[nt][0], bL[nt][1]);
            }
    }
}

// ---------------- MMA stage: 1x (128x128), NO cvt (data pre-rounded) ----------------
__device__ __forceinline__ void mma_ldsm_1x(unsigned baseA, unsigned baseB,
    const unsigned* aOff, const unsigned* bOff, float (*acc)[4][4])
{
    #pragma unroll
    for (int ks = 0; ks < 32; ks += 8) {
        unsigned a[4][4], b[2][4];
        #pragma unroll
        for (int mt = 0; mt < 4; mt++)
            ldsm4(a[mt][0], a[mt][1], a[mt][2], a[mt][3], baseA + aOff[mt] + ks*4);
        #pragma unroll
        for (int p = 0; p < 2; p++)
            ldsm4(b[p][0], b[p][1], b[p][2], b[p][3], baseB + bOff[p] + ks*4);
        #pragma unroll
        for (int mt = 0; mt < 4; mt++)
            #pragma unroll
            for (int nt = 0; nt < 4; nt++) {
                int p = nt >> 1, hi = (nt & 1) << 1;
                mma_tf32(acc[mt][nt], a[mt][0], a[mt][1], a[mt][2], a[mt][3],
                         b[p][hi], b[p][hi + 1]);
            }
    }
}

// ---------------- MMA stage: fused gate+up 1x, NO cvt ----------------
__device__ __forceinline__ void mma_ldsm_gu(unsigned baseA, unsigned baseBg, unsigned baseBu,
    const unsigned* aOff, const unsigned* bOff,
    float (*accg)[4][4], float (*accu)[4][4])
{
    #pragma unroll
    for (int ks = 0; ks < 32; ks += 8) {
        unsigned a[2][4], bg[2][4], bu[2][4];
        #pragma unroll
        for (int mt = 0; mt < 2; mt++)
            ldsm4(a[mt][0], a[mt][1], a[mt][2], a[mt][3], baseA + aOff[mt] + ks*4);
        #pragma unroll
        for (int p = 0; p < 2; p++) {
            ldsm4(bg[p][0], bg[p][1], bg[p][2], bg[p][3], baseBg + bOff[p] + ks*4);
            ldsm4(bu[p][0], bu[p][1], bu[p][2], bu[p][3], baseBu + bOff[p] + ks*4);
        }
        #pragma unroll
        for (int mt = 0; mt < 2; mt++)
            #pragma unroll
            for (int nt = 0; nt < 4; nt++) {
                int p = nt >> 1, hi = (nt & 1) << 1;
                mma_tf32(accg[mt][nt], a[mt][0], a[mt][1], a[mt][2], a[mt][3],
                         bg[p][hi], bg[p][hi + 1]);
                mma_tf32(accu[mt][nt], a[mt][0], a[mt][1], a[mt][2], a[mt][3],
                         bu[p][hi], bu[p][hi + 1]);
            }
    }
}

// ============ weight rounding pass (RNE tf32 pre-conversion) ============
__global__ __launch_bounds__(256) void round_kernel(const float* __restrict__ src,
                                                    float* __restrict__ dst, size_t n)
{
    size_t stride = (size_t)gridDim.x * 256;
    for (size_t i = (size_t)blockIdx.x * 256 + threadIdx.x; i < n; i += stride) {
        float4 v = *(const float4*)(src + i * 4);
        float4 o;
        o.x = roundtf(v.x); o.y = roundtf(v.y);
        o.z = roundtf(v.z); o.w = roundtf(v.w);
        *(float4*)(dst + i * 4) = o;
    }
}

// ============ fused QKV projection (3xTF32, 3-stage pipeline) ============
__global__ __launch_bounds__(256, 2) void qkv3_kernel(const float* __restrict__ A,
    const float* __restrict__ wq, const float* __restrict__ wk, const float* __restrict__ wv)
{
    extern __shared__ float sm[];
    float* As = sm;
    float* Bs = sm + 3*TSTAGE;
    const int K = DMODEL;
    int tid = threadIdx.x, lane = tid & 31, warp = tid >> 5;
    int m0 = blockIdx.y * 128, n0 = blockIdx.x * 128;
    int wm = (warp & 1) * 64, wn = (warp >> 1) * 32;

    const float* B; float* Cp; int ldc, ncol0;
    if (n0 < 2048)      { B = wq + (size_t)n0 * K;          Cp = g_q; ldc = NH*HDIM;   ncol0 = n0; }
    else if (n0 < 2560) { B = wk + (size_t)(n0 - 2048) * K; Cp = g_k; ldc = NKVH*HDIM; ncol0 = n0 - 2048; }
    else                { B = wv + (size_t)(n0 - 2560) * K; Cp = g_v; ldc = NKVH*HDIM; ncol0 = n0 - 2560; }

    unsigned aOff[4], bOff[2];
    frag_offsets(lane, wm, wn, aOff, bOff);
    unsigned sA[3] = { sptr(As), sptr(As + TSTAGE), sptr(As + 2*TSTAGE) };
    unsigned sB[3] = { sptr(Bs), sptr(Bs + TSTAGE), sptr(Bs + 2*TSTAGE) };

    const float* aSrc[4]; const float* bSrc[4]; unsigned soff[4];
    #pragma unroll
    for (int i = 0; i < 4; i++) {
        int idx = tid + i * 256, row = idx >> 3, ch = idx & 7;
        soff[i] = (row * TSTRIDE + ch * 4) * 4;
        aSrc[i] = A + (size_t)(m0 + row) * K + ch * 4;
        bSrc[i] = B + (size_t)row * K + ch * 4;
    }
    #pragma unroll
    for (int s = 0; s < 2; s++) {
        #pragma unroll
        for (int i = 0; i < 4; i++) {
            CPA16(sA[s] + soff[i], aSrc[i] + s*32, 16);
            CPA16(sB[s] + soff[i], bSrc[i] + s*32, 16);
        }
        CPCOMMIT();
    }

    float acc[4][4][4] = {};
    const int nst = K / 32;
    for (int it = 0; it < nst; it++) {
        if (it + 1 < nst) { CPWAIT1(); } else { CPWAIT0(); }
        __syncthreads();
        int cur = it % 3;
        int pf = it + 2;
        if (pf < nst) {
            int buf = pf % 3;
            #pragma unroll
            for (int i = 0; i < 4; i++) {
                CPA16(sA[buf] + soff[i], aSrc[i] + pf*32, 16);
                CPA16(sB[buf] + soff[i], bSrc[i] + pf*32, 16);
            }
            CPCOMMIT();
        }
        mma_ldsm_3x(sA[cur], sB[cur], aOff, bOff, acc);
    }
    int r = lane >> 2, c2 = (lane & 3) * 2;
    #pragma unroll
    for (int mt = 0; mt < 4; mt++) {
        int mrow = m0 + wm + mt * 16 + r;
        #pragma unroll
        for (int nt = 0; nt < 4; nt++) {
            int col = ncol0 + wn + nt * 8 + c2;
            size_t i00 = (size_t)mrow * ldc + col;
            size_t i10 = (size_t)(mrow + 8) * ldc + col;
            Cp[i00] = acc[mt][nt][0]; Cp[i00+1] = acc[mt][nt][1];
            Cp[i10] = acc[mt][nt][2]; Cp[i10+1] = acc[mt][nt][3];
        }
    }
}

// ============ o-proj + residual (3xTF32, 3-stage) ============
__global__ __launch_bounds__(256, 2) void gemm3o_kernel(const float* __restrict__ A,
    const float* __restrict__ B, float* __restrict__ C, const float* __restrict__ R)
{
    extern __shared__ float sm[];
    float* As = sm;
    float* Bs = sm + 3*TSTAGE;
    const int K = NH*HDIM, N = DMODEL;
    int tid = threadIdx.x, lane = tid & 31, warp = tid >> 5;
    int m0 = blockIdx.y * 128, n0 = blockIdx.x * 128;
    int wm = (warp & 1) * 64, wn = (warp >> 1) * 32;

    unsigned aOff[4], bOff[2];
    frag_offsets(lane, wm, wn, aOff, bOff);
    unsigned sA[3] = { sptr(As), sptr(As + TSTAGE), sptr(As + 2*TSTAGE) };
    unsigned sB[3] = { sptr(Bs), sptr(Bs + TSTAGE), sptr(Bs + 2*TSTAGE) };

    const float* aSrc[4]; const float* bSrc[4]; unsigned soff[4];
    #pragma unroll
    for (int i = 0; i < 4; i++) {
        int idx = tid + i * 256, row = idx >> 3, ch = idx & 7;
        soff[i] = (row * TSTRIDE + ch * 4) * 4;
        aSrc[i] = A + (size_t)(m0 + row) * K + ch * 4;
        bSrc[i] = B + (size_t)(n0 + row) * K + ch * 4;
    }
    #pragma unroll
    for (int s = 0; s < 2; s++) {
        #pragma unroll
        for (int i = 0; i < 4; i++) {
            CPA16(sA[s] + soff[i], aSrc[i] + s*32, 16);
            CPA16(sB[s] + soff[i], bSrc[i] + s*32, 16);
        }
        CPCOMMIT();
    }

    float acc[4][4][4] = {};
    const int nst = K / 32;
    for (int it = 0; it < nst; it++) {
        if (it + 1 < nst) { CPWAIT1(); } else { CPWAIT0(); }
        __syncthreads();
        int cur = it % 3;
        int pf = it + 2;
        if (pf < nst) {
            int buf = pf % 3;
            #pragma unroll
            for (int i = 0; i < 4; i++) {
                CPA16(sA[buf] + soff[i], aSrc[i] + pf*32, 16);
                CPA16(sB[buf] + soff[i], bSrc[i] + pf*32, 16);
            }
            CPCOMMIT();
        }
        mma_ldsm_3x(sA[cur], sB[cur], aOff, bOff, acc);
    }
    int r = lane >> 2, c2 = (lane & 3) * 2;
    #pragma unroll
    for (int mt = 0; mt < 4; mt++) {
        int mrow = m0 + wm + mt * 16 + r;
        #pragma unroll
        for (int nt = 0; nt < 4; nt++) {
            int col = n0 + wn + nt * 8 + c2;
            size_t i00 = (size_t)mrow * N + col;
            size_t i10 = (size_t)(mrow + 8) * N + col;
            C[i00] = acc[mt][nt][0] + R[i00]; C[i00+1] = acc[mt][nt][1] + R[i00+1];
            C[i10] = acc[mt][nt][2] + R[i10]; C[i10+1] = acc[mt][nt][3] + R[i10+1];
        }
    }
}

// ============ shared expert fused gate+up (pre-rounded inputs, rounded output) ============
__global__ __launch_bounds__(256, 2) void shgu_kernel(const float* __restrict__ A,
    const float* __restrict__ shg, const float* __restrict__ shu)
{
    extern __shared__ float sm[];
    float* As  = sm;
    float* Bgs = sm + 3*TSTAGE;
    float* Bus = sm + 3*TSTAGE + 3*(64*TSTRIDE);
    const int K = DMODEL;
    int tid = threadIdx.x, lane = tid & 31, warp = tid >> 5;
    int m0 = blockIdx.y * 128, n0 = blockIdx.x * 64;
    int wm = (warp >> 1) * 32, wn = (warp & 1) * 32;

    unsigned aOff[2], bOff[2];
    frag_offsets32(lane, wm, wn, aOff, bOff);
    unsigned sA[3]  = { sptr(As), sptr(As + TSTAGE), sptr(As + 2*TSTAGE) };
    unsigned sBg[3] = { sptr(Bgs), sptr(Bgs + 64*TSTRIDE), sptr(Bgs + 2*64*TSTRIDE) };
    unsigned sBu[3] = { sptr(Bus), sptr(Bus + 64*TSTRIDE), sptr(Bus + 2*64*TSTRIDE) };

    const float* aSrc[4]; unsigned aSoff[4];
    const float* gSrc[2]; const float* uSrc[2]; unsigned bSoff[2];
    #pragma unroll
    for (int i = 0; i < 4; i++) {
        int idx = tid + i * 256, row = idx >> 3, ch = idx & 7;
        aSoff[i] = (row * TSTRIDE + ch * 4) * 4;
        aSrc[i] = A + (size_t)(m0 + row) * K + ch * 4;
    }
    #pragma unroll
    for (int i = 0; i < 2; i++) {
        int idx = tid + i * 256, row = idx >> 3, ch = idx & 7;
        bSoff[i] = (row * TSTRIDE + ch * 4) * 4;
        gSrc[i] = shg + (size_t)(n0 + row) * K + ch * 4;
        uSrc[i] = shu + (size_t)(n0 + row) * K + ch * 4;
    }
    #pragma unroll
    for (int s = 0; s < 2; s++) {
        #pragma unroll
        for (int i = 0; i < 4; i++) CPA16(sA[s] + aSoff[i], aSrc[i] + s*32, 16);
        #pragma unroll
        for (int i = 0; i < 2; i++) {
            CPA16(sBg[s] + bSoff[i], gSrc[i] + s*32, 16);
            CPA16(sBu[s] + bSoff[i], uSrc[i] + s*32, 16);
        }
        CPCOMMIT();
    }

    float accg[2][4][4] = {}, accu[2][4][4] = {};
    const int nst = K / 32;
    for (int it = 0; it < nst; it++) {
        if (it + 1 < nst) { CPWAIT1(); } else { CPWAIT0(); }
        __syncthreads();
        int cur = it % 3;
        int pf = it + 2;
        if (pf < nst) {
            int buf = pf % 3;
            #pragma unroll
            for (int i = 0; i < 4; i++) CPA16(sA[buf] + aSoff[i], aSrc[i] + pf*32, 16);
            #pragma unroll
            for (int i = 0; i < 2; i++) {
                CPA16(sBg[buf] + bSoff[i], gSrc[i] + pf*32, 16);
                CPA16(sBu[buf] + bSoff[i], uSrc[i] + pf*32, 16);
            }
            CPCOMMIT();
        }
        mma_ldsm_gu(sA[cur], sBg[cur], sBu[cur], aOff, bOff, accg, accu);
    }
    int r = lane >> 2, c2 = (lane & 3) * 2;
    #pragma unroll
    for (int mt = 0; mt < 2; mt++) {
        int mrow = m0 + wm + mt * 16 + r;
        #pragma unroll
        for (int nt = 0; nt < 4; nt++) {
            int col = n0 + wn + nt * 8 + c2;
            #pragma unroll
            for (int half = 0; half < 2; half++) {
                int rr = mrow + half * 8;
                float gv = accg[mt][nt][half*2], uv = accu[mt][nt][half*2];
                float gv1 = accg[mt][nt][half*2+1], uv1 = accu[mt][nt][half*2+1];
                size_t o = (size_t)rr * SHI + col;
                g_sg[o]   = roundtf((gv  / (1.f + expf(-gv)))  * uv);
                g_sg[o+1] = roundtf((gv1 / (1.f + expf(-gv1))) * uv1);
            }
        }
    }
}

// ============ routed expert fused gate+up (pre-rounded inputs, rounded output) ============
__global__ __launch_bounds__(256, 2) void egu_kernel(const float* __restrict__ wg,
    const float* __restrict__ wu)
{
    int e = blockIdx.z;
    int cnt = g_cnt[e];
    int m0 = blockIdx.y * 128;
    if (m0 >= cnt) return;
    int n0 = blockIdx.x * 64;
    extern __shared__ float sm[];
    float* As  = sm;
    float* Bgs = sm + 3*TSTAGE;
    float* Bus = sm + 3*TSTAGE + 3*(64*TSTRIDE);
    __shared__ int toks[128];
    const int K = DMODEL;
    int tid = threadIdx.x, lane = tid & 31, warp = tid >> 5;
    if (tid < 128) {
        int m = m0 + tid;
        toks[tid] = (m < cnt) ? g_bucket[e * NT + m] : -1;
    }
    __syncthreads();
    const float* Bg = wg + (size_t)e * EI * DMODEL + (size_t)n0 * K;
    const float* Bu = wu + (size_t)e * EI * DMODEL + (size_t)n0 * K;
    int wm = (warp >> 1) * 32, wn = (warp & 1) * 32;

    unsigned aOff[2], bOff[2];
    frag_offsets32(lane, wm, wn, aOff, bOff);
    unsigned sA[3]  = { sptr(As), sptr(As + TSTAGE), sptr(As + 2*TSTAGE) };
    unsigned sBg[3] = { sptr(Bgs), sptr(Bgs + 64*TSTRIDE), sptr(Bgs + 2*64*TSTRIDE) };
    unsigned sBu[3] = { sptr(Bus), sptr(Bus + 64*TSTRIDE), sptr(Bus + 2*64*TSTRIDE) };

    const float* aSrc[4]; unsigned aSoff[4]; int aBytes[4];
    const float* gSrc[2]; const float* uSrc[2]; unsigned bSoff[2];
    #pragma unroll
    for (int i = 0; i < 4; i++) {
        int idx = tid + i * 256, row = idx >> 3, ch = idx & 7;
        aSoff[i] = (row * TSTRIDE + ch * 4) * 4;
        int tok = toks[row];
        aBytes[i] = (tok >= 0) ? 16 : 0;
        aSrc[i] = g_tr + (size_t)(tok >= 0 ? tok : 0) * K + ch * 4;
    }
    #pragma unroll
    for (int i = 0; i < 2; i++) {
        int idx = tid + i * 256, row = idx >> 3, ch = idx & 7;
        bSoff[i] = (row * TSTRIDE + ch * 4) * 4;
        gSrc[i] = Bg + (size_t)row * K + ch * 4;
        uSrc[i] = Bu + (size_t)row * K + ch * 4;
    }
    #pragma unroll
    for (int s = 0; s < 2; s++) {
        #pragma unroll
        for (int i = 0; i < 4; i++) CPA16(sA[s] + aSoff[i], aSrc[i] + s*32, aBytes[i]);
        #pragma unroll
        for (int i = 0; i < 2; i++) {
            CPA16(sBg[s] + bSoff[i], gSrc[i] + s*32, 16);
            CPA16(sBu[s] + bSoff[i], uSrc[i] + s*32, 16);
        }
        CPCOMMIT();
    }

    float accg[2][4][4] = {}, accu[2][4][4] = {};
    const int nst = K / 32;
    for (int it = 0; it < nst; it++) {
        if (it + 1 < nst) { CPWAIT1(); } else { CPWAIT0(); }
        __syncthreads();
        int cur = it % 3;
        int pf = it + 2;
        if (pf < nst) {
            int buf = pf % 3;
            #pragma unroll
            for (int i = 0; i < 4; i++) CPA16(sA[buf] + aSoff[i], aSrc[i] + pf*32, aBytes[i]);
            #pragma unroll
            for (int i = 0; i < 2; i++) {
                CPA16(sBg[buf] + bSoff[i], gSrc[i] + pf*32, 16);
                CPA16(sBu[buf] + bSoff[i], uSrc[i] + pf*32, 16);
            }
            CPCOMMIT();
        }
        mma_ldsm_gu(sA[cur], sBg[cur], sBu[cur], aOff, bOff, accg, accu);
    }
    int r = lane >> 2, c2 = (lane & 3) * 2;
    #pragma unroll
    for (int mt = 0; mt < 2; mt++) {
        int mloc = wm + mt * 16 + r;
        #pragma unroll
        for (int half = 0; half < 2; half++) {
            int m = m0 + mloc + half * 8;
            if (m >= cnt) continue;
            int tok = toks[mloc + half * 8];
            float wgt = g_Cw[tok * NE + e];
            #pragma unroll
            for (int nt = 0; nt < 4; nt++) {
                int col = n0 + wn + nt * 8 + c2;
                float gv = accg[mt][nt][half*2], uv = accu[mt][nt][half*2];
                float gv1 = accg[mt][nt][half*2+1], uv1 = accu[mt][nt][half*2+1];
                size_t o = ((size_t)e * NT + m) * EI + col;
                g_eg[o]   = roundtf((gv  / (1.f + expf(-gv)))  * uv  * wgt);
                g_eg[o+1] = roundtf((gv1 / (1.f + expf(-gv1))) * uv1 * wgt);
            }
        }
    }
}

// ============ dense 1xTF32 GEMM (128x128, no cvt): shared-expert down, STORES C ============
__global__ __launch_bounds__(256, 2) void dense1_kernel(const float* __restrict__ A,
    const float* __restrict__ B, float* __restrict__ C, int N, int K)
{
    extern __shared__ float sm[];
    float* As = sm;
    float* Bs = sm + 3*TSTAGE;
    int tid = threadIdx.x, lane = tid & 31, warp = tid >> 5;
    int m0 = blockIdx.y * 128, n0 = blockIdx.x * 128;
    int wm = (warp & 1) * 64, wn = (warp >> 1) * 32;

    unsigned aOff[4], bOff[2];
    frag_offsets(lane, wm, wn, aOff, bOff);
    unsigned sA[3] = { sptr(As), sptr(As + TSTAGE), sptr(As + 2*TSTAGE) };
    unsigned sB[3] = { sptr(Bs), sptr(Bs + TSTAGE), sptr(Bs + 2*TSTAGE) };

    const float* aSrc[4]; const float* bSrc[4]; unsigned soff[4];
    #pragma unroll
    for (int i = 0; i < 4; i++) {
        int idx = tid + i * 256, row = idx >> 3, ch = idx & 7;
        soff[i] = (row * TSTRIDE + ch * 4) * 4;
        aSrc[i] = A + (size_t)(m0 + row) * K + ch * 4;
        bSrc[i] = B + (size_t)(n0 + row) * K + ch * 4;
    }
    #pragma unroll
    for (int s = 0; s < 2; s++) {
        #pragma unroll
        for (int i = 0; i < 4; i++) {
            CPA16(sA[s] + soff[i], aSrc[i] + s*32, 16);
            CPA16(sB[s] + soff[i], bSrc[i] + s*32, 16);
        }
        CPCOMMIT();
    }

    float acc[4][4][4] = {};
    const int nst = K / 32;
    for (int it = 0; it < nst; it++) {
        if (it + 1 < nst) { CPWAIT1(); } else { CPWAIT0(); }
        __syncthreads();
        int cur = it % 3;
        int pf = it + 2;
        if (pf < nst) {
            int buf = pf % 3;
            #pragma unroll
            for (int i = 0; i < 4; i++) {
                CPA16(sA[buf] + soff[i], aSrc[i] + pf*32, 16);
                CPA16(sB[buf] + soff[i], bSrc[i] + pf*32, 16);
            }
            CPCOMMIT();
        }
        mma_ldsm_1x(sA[cur], sB[cur], aOff, bOff, acc);
    }
    int r = lane >> 2, c2 = (lane & 3) * 2;
    #pragma unroll
    for (int mt = 0; mt < 4; mt++) {
        int mrow = m0 + wm + mt * 16 + r;
        #pragma unroll
        for (int nt = 0; nt < 4; nt++) {
            int col = n0 + wn + nt * 8 + c2;
            size_t i00 = (size_t)mrow * N + col;
            size_t i10 = (size_t)(mrow + 8) * N + col;
            C[i00] = acc[mt][nt][0]; C[i00+1] = acc[mt][nt][1];
            C[i10] = acc[mt][nt][2]; C[i10+1] = acc[mt][nt][3];
        }
    }
}

// ============ expert down GEMM (1x, 128x128, no cvt) + scatter atomicAdd ============
__global__ __launch_bounds__(256, 2) void edown1_kernel(const float* __restrict__ wd)
{
    int e = blockIdx.z;
    int cnt = g_cnt[e];
    int m0 = blockIdx.y * 128;
    if (m0 >= cnt) return;
    int n0 = blockIdx.x * 128;
    extern __shared__ float sm[];
    float* As = sm;
    float* Bs = sm + 3*TSTAGE;
    __shared__ int toks[128];
    const int K = EI;
    int tid = threadIdx.x, lane = tid & 31, warp = tid >> 5;
    if (tid < 128) {
        int m = m0 + tid;
        toks[tid] = (m < cnt) ? g_bucket[e * NT + m] : -1;
    }
    __syncthreads();
    const float* Ae = g_eg + ((size_t)e * NT + m0) * EI;
    const float* B = wd + (size_t)e * DMODEL * EI + (size_t)n0 * K;
    int wm = (warp & 1) * 64, wn = (warp >> 1) * 32;

    unsigned aOff[4], bOff[2];
    frag_offsets(lane, wm, wn, aOff, bOff);
    unsigned sA[3] = { sptr(As), sptr(As + TSTAGE), sptr(As + 2*TSTAGE) };
    unsigned sB[3] = { sptr(Bs), sptr(Bs + TSTAGE), sptr(Bs + 2*TSTAGE) };

    const float* aSrc[4]; const float* bSrc[4]; unsigned soff[4]; int aBytes[4];
    #pragma unroll
    for (int i = 0; i < 4; i++) {
        int idx = tid + i * 256, row = idx >> 3, ch = idx & 7;
        soff[i] = (row * TSTRIDE + ch * 4) * 4;
        bool ok = (m0 + row) < cnt;
        aBytes[i] = ok ? 16 : 0;
        aSrc[i] = Ae + (size_t)(ok ? row : 0) * K + ch * 4;
        bSrc[i] = B + (size_t)row * K + ch * 4;
    }
    #pragma unroll
    for (int s = 0; s < 2; s++) {
        #pragma unroll
        for (int i = 0; i < 4; i++) {
            CPA16(sA[s] + soff[i], aSrc[i] + s*32, aBytes[i]);
            CPA16(sB[s] + soff[i], bSrc[i] + s*32, 16);
        }
        CPCOMMIT();
    }

    float acc[4][4][4] = {};
    const int nst = K / 32;
    for (int it = 0; it < nst; it++) {
        if (it + 1 < nst) { CPWAIT1(); } else { CPWAIT0(); }
        __syncthreads();
        int cur = it % 3;
        int pf = it + 2;
        if (pf < nst) {
            int buf = pf % 3;
            #pragma unroll
            for (int i = 0; i < 4; i++) {
                CPA16(sA[buf] + soff[i], aSrc[i] + pf*32, aBytes[i]);
                CPA16(sB[buf] + soff[i], bSrc[i] + pf*32, 16);
            }
            CPCOMMIT();
        }
        mma_ldsm_1x(sA[cur], sB[cur], aOff, bOff, acc);
    }
    int r = lane >> 2, c2 = (lane & 3) * 2;
    #pragma unroll
    for (int mt = 0; mt < 4; mt++) {
        int mloc = wm + mt * 16 + r;
        #pragma unroll
        for (int nt = 0; nt < 4; nt++) {
            int col = n0 + wn + nt * 8 + c2;
            if (m0 + mloc < cnt) {
                int tok = toks[mloc];
                atomicAdd(&g_y[(size_t)tok * DMODEL + col],     acc[mt][nt][0]);
                atomicAdd(&g_y[(size_t)tok * DMODEL + col + 1], acc[mt][nt][1]);
            }
            if (m0 + mloc + 8 < cnt) {
                int tok = toks[mloc + 8];
                atomicAdd(&g_y[(size_t)tok * DMODEL + col],     acc[mt][nt][2]);
                atomicAdd(&g_y[(size_t)tok * DMODEL + col + 1], acc[mt][nt][3]);
            }
        }
    }
}

// ---------------- RMSNorm (optional rounded second output) ----------------
__global__ __launch_bounds__(256) void rmsnorm_kernel(const float* __restrict__ x,
                                                      const float* __restrict__ w,
                                                      float* __restrict__ out,
                                                      float* __restrict__ out2)
{
    int row = blockIdx.x;
    const float* xr = x + (size_t)row * DMODEL;
    float ss = 0.f;
    for (int d = threadIdx.x; d < DMODEL; d += 256) { float v = xr[d]; ss += v * v; }
    __shared__ float red[8];
    #pragma unroll
    for (int off = 16; off; off >>= 1) ss += __shfl_xor_sync(0xffffffffu, ss, off);
    if ((threadIdx.x & 31) == 0) red[threadIdx.x >> 5] = ss;
    __syncthreads();
    __shared__ float sinv;
    if (threadIdx.x == 0) {
        float tot = 0.f;
        #pragma unroll
        for (int i = 0; i < 8; i++) tot += red[i];
        sinv = 1.f / sqrtf(tot / (float)DMODEL + EPSV);
    }
    __syncthreads();
    float si = sinv;
    for (int d = threadIdx.x; d < DMODEL; d += 256) {
        float v = xr[d] * si * w[d];
        out[(size_t)row * DMODEL + d] = v;
        if (out2) out2[(size_t)row * DMODEL + d] = roundtf(v);
    }
}

// ---------------- fused per-(token,head) RMSNorm + RoPE (inline fp32 trig) ----------------
__global__ __launch_bounds__(128) void qknorm_rope_kernel(const float* __restrict__ qw,
                                                          const float* __restrict__ kw,
                                                          Freqs fr)
{
    int row = blockIdx.x;
    if (row == 0 && threadIdx.x < NE) g_cnt[threadIdx.x] = 0;
    float* buf; const float* w; int nh;
    if (row < LSEQ * NH) { buf = g_q; w = qw; nh = NH; }
    else { row -= LSEQ * NH; buf = g_k; w = kw; nh = NKVH; }
    int pos = row / nh;
    float* p = buf + (size_t)row * HDIM;
    int tid = threadIdx.x;
    float v = p[tid];
    float ss = v * v;
    #pragma unroll
    for (int off = 16; off; off >>= 1) ss += __shfl_xor_sync(0xffffffffu, ss, off);
    __shared__ float red_s[4];
    if ((tid & 31) == 0) red_s[tid >> 5] = ss;
    __syncthreads();
    __shared__ float sinv;
    if (tid == 0) sinv = 1.f / sqrtf((red_s[0] + red_s[1] + red_s[2] + red_s[3]) / (float)HDIM + EPSV);
    __shared__ float shn[HDIM];
    __syncthreads();
    shn[tid] = v * sinv * w[tid];
    __syncthreads();
    if (tid < 64) {
        float x1 = shn[tid], x2 = shn[tid + 64];
        float ang = (float)pos * fr.f[tid];
        float k = rintf(ang * 0.15915494309189535f);
        float red = ang - k * 6.28125f;
        red = red - k * 0.0019354820251464844f;
        red = red - k * (-1.7484556e-7f);
        float s, c;
        sincosf(red, &s, &c);
        p[tid]      = x1 * c - x2 * s;
        p[tid + 64] = x2 * c + x1 * s;
    }
}

// ---------------- flash attention (fp32 via f32x2, causal, GQA) ----------------
__global__ __launch_bounds__(128) void attn_kernel()
{
    __shared__ __align__(16) float Qs[32][HDIM];
    __shared__ __align__(16) float Ks[32][HDIM];
    __shared__ __align__(16) float Vs[32][HDIM];
    int h = blockIdx.y;
    int q0 = blockIdx.x * 32;
    int kvh = h >> 2;
    int tid = threadIdx.x;
    int r = tid >> 2, qd = tid & 3;

    for (int i = tid; i < 32 * 32; i += 128) {
        int row = i >> 5, d4 = i & 31;
        ((float4*)&Qs[row][0])[d4] =
            *(const float4*)(g_q + (size_t)(q0 + row) * (NH * HDIM) + h * HDIM + d4 * 4);
    }
    __syncthreads();
    ull qq[16];
    #pragma unroll
    for (int i = 0; i < 16; i++) qq[i] = *(const ull*)&Qs[r][qd * 32 + i * 2];

    ull o2[16];
    #pragma unroll
    for (int i = 0; i < 16; i++) o2[i] = 0ULL;
    float mrow = -INFINITY, lrow = 0.f;

    for (int k0 = 0; k0 <= q0; k0 += 32) {
        __syncthreads();
        for (int i = tid; i < 32 * 32; i += 128) {
            int row = i >> 5, d4 = i & 31;
            size_t base = (size_t)(k0 + row) * (NKVH * HDIM) + kvh * HDIM + d4 * 4;
            ((float4*)&Ks[row][0])[d4] = *(const float4*)(g_k + base);
            ((float4*)&Vs[row][0])[d4] = *(const float4*)(g_v + base);
        }
        __syncthreads();

        float s[32];
        float tmax = -INFINITY;
        #pragma unroll
        for (int j = 0; j < 32; j++) {
            const ull* K2 = (const ull*)&Ks[j][qd * 32];
            ull acc2 = 0ULL;
            #pragma unroll
            for (int i = 0; i < 16; i++) acc2 = fma2(qq[i], K2[i], acc2);
            float elo, ehi; unpack2(acc2, elo, ehi);
            float pacc = elo + ehi;
            pacc += __shfl_xor_sync(0xffffffffu, pacc, 1);
            pacc += __shfl_xor_sync(0xffffffffu, pacc, 2);
            pacc *= ATTN_SCALE;
            if (k0 + j > q0 + r) pacc = -INFINITY;
            s[j] = pacc;
            tmax = fmaxf(tmax, pacc);
        }
        float mnew = fmaxf(mrow, tmax);
        float alpha = __expf(mrow - mnew);
        lrow *= alpha;
        ull al2 = pack2(alpha, alpha);
        #pragma unroll
        for (int i = 0; i < 16; i++) o2[i] = mul2(o2[i], al2);
        #pragma unroll
        for (int j = 0; j < 32; j++) {
            float pv = __expf(s[j] - mnew);
            lrow += pv;
            ull pv2 = pack2(pv, pv);
            const ull* V2 = (const ull*)&Vs[j][qd * 32];
            #pragma unroll
            for (int i = 0; i < 16; i++) o2[i] = fma2(pv2, V2[i], o2[i]);
        }
        mrow = mnew;
    }
    float inv = 1.f / lrow;
    size_t base = (size_t)(q0 + r) * (NH * HDIM) + h * HDIM + qd * 32;
    #pragma unroll
    for (int i = 0; i < 16; i++) {
        float lo, hi; unpack2(o2[i], lo, hi);
        g_attn[base + i * 2]     = lo * inv;
        g_attn[base + i * 2 + 1] = hi * inv;
    }
}

// ---------------- gating / routing (fp32 exact; coalesced) ----------------
__global__ __launch_bounds__(256) void gate_kernel(const float* __restrict__ gate_w,
                                                   const float* __restrict__ gate_bias)
{
    int t = blockIdx.x;
    const float4* t4 = (const float4*)(g_t + (size_t)t * DMODEL);
    int warp = threadIdx.x >> 5, lane = threadIdx.x & 31;
    int e0 = warp * 2;
    const float4* g0 = (const float4*)(gate_w + (size_t)e0 * DMODEL);
    const float4* g1 = (const float4*)(gate_w + (size_t)(e0 + 1) * DMODEL);
    float a0 = 0.f, a1 = 0.f;
    for (int i = lane; i < DMODEL / 4; i += 32) {
        float4 tv = t4[i], v0 = g0[i], v1 = g1[i];
        a0 += tv.x*v0.x + tv.y*v0.y + tv.z*v0.z + tv.w*v0.w;
        a1 += tv.x*v1.x + tv.y*v1.y + tv.z*v1.z + tv.w*v1.w;
    }
    #pragma unroll
    for (int off = 16; off; off >>= 1) {
        a0 += __shfl_xor_sync(0xffffffffu, a0, off);
        a1 += __shfl_xor_sync(0xffffffffu, a1, off);
    }
    __shared__ float sc_s[NE];
    if (lane == 0) {
        sc_s[e0]     = 1.f / (1.f + expf(-a0));
        sc_s[e0 + 1] = 1.f / (1.f + expf(-a1));
    }
    __syncthreads();
    if (threadIdx.x == 0) {
        float sc[NE], s2[NE];
        #pragma unroll
        for (int e = 0; e < NE; e++) { sc[e] = sc_s[e]; s2[e] = sc[e] + gate_bias[e]; }
        float gs[NG];
        #pragma unroll
        for (int gq = 0; gq < NG; gq++) {
            float m1 = -INFINITY, m2 = -INFINITY;
            #pragma unroll
            for (int j = 0; j < NE / NG; j++) {
                float vv = s2[gq * (NE / NG) + j];
                if (vv > m1) { m2 = m1; m1 = vv; }
                else if (vv > m2) { m2 = vv; }
            }
            gs[gq] = m1 + m2;
        }
        bool gsel[NG] = {false, false, false, false};
        {
            float gtmp[NG];
            #pragma unroll
            for (int gq = 0; gq < NG; gq++) gtmp[gq] = gs[gq];
            for (int it = 0; it < NTKG; it++) {
                int bi = 0; float bv = -INFINITY;
                #pragma unroll
                for (int gq = 0; gq < NG; gq++)
                    if (gtmp[gq] > bv) { bv = gtmp[gq]; bi = gq; }
                gsel[bi] = true; gtmp[bi] = -INFINITY;
            }
        }
        float masked[NE];
        #pragma unroll
        for (int e = 0; e < NE; e++) masked[e] = gsel[e >> 2] ? s2[e] : 0.f;
        int inds[NTOPK];
        for (int it = 0; it < NTOPK; it++) {
            int bi = 0; float bv = -INFINITY;
            #pragma unroll
            for (int e = 0; e < NE; e++)
                if (masked[e] > bv) { bv = masked[e]; bi = e; }
            inds[it] = bi; masked[bi] = -INFINITY;
        }
        float wv[NTOPK], wsum = 0.f;
        #pragma unroll
        for (int i = 0; i < NTOPK; i++) { wv[i] = sc[inds[i]]; wsum += wv[i]; }
        float invw = RSF / (wsum + 1e-20f);
        float crow[NE];
        #pragma unroll
        for (int e = 0; e < NE; e++) crow[e] = 0.f;
        #pragma unroll
        for (int i = 0; i < NTOPK; i++) crow[inds[i]] += wv[i] * invw;
        #pragma unroll
        for (int e = 0; e < NE; e++) g_Cw[t * NE + e] = crow[e];
        #pragma unroll
        for (int i = 0; i < NTOPK; i++) {
            int e = inds[i];
            int posn = atomicAdd(&g_cnt[e], 1);
            g_bucket[e * NT + posn] = t;
        }
    }
}

// ---------------- final: out = h1 + y ----------------
__global__ void final_add_kernel(float* __restrict__ out)
{
    int i = blockIdx.x * blockDim.x + threadIdx.x;
    if (i < NT * DMODEL) out[i] = g_h1[i] + g_y[i];
}

// ---------------- launch ----------------
extern "C" void kernel_launch(void* const* d_in, const int* in_sizes, int n_in,
                              void* d_out, int out_size)
{
    const float* x        = (const float*)d_in[0];
    const float* w_q      = (const float*)d_in[1];
    const float* w_k      = (const float*)d_in[2];
    const float* w_v      = (const float*)d_in[3];
    const float* w_o      = (const float*)d_in[4];
    const float* q_norm_w = (const float*)d_in[5];
    const float* k_norm_w = (const float*)d_in[6];
    const float* ln1_w    = (const float*)d_in[7];
    const float* ln2_w    = (const float*)d_in[8];
    const float* gate_w   = (const float*)d_in[9];
    const float* gate_b   = (const float*)d_in[10];
    const float* wg       = (const float*)d_in[11];
    const float* wu       = (const float*)d_in[12];
    const float* wd       = (const float*)d_in[13];
    const float* sh_g     = (const float*)d_in[14];
    const float* sh_u     = (const float*)d_in[15];
    const float* sh_d     = (const float*)d_in[16];
    float* out = (float*)d_out;

    static int attr_done = 0;
    if (!attr_done) {
        cudaFuncSetAttribute(qkv3_kernel,   cudaFuncAttributeMaxDynamicSharedMemorySize, GEMM_SMEM3);
        cudaFuncSetAttribute(gemm3o_kernel, cudaFuncAttributeMaxDynamicSharedMemorySize, GEMM_SMEM3);
        cudaFuncSetAttribute(shgu_kernel,   cudaFuncAttributeMaxDynamicSharedMemorySize, GEMM_SMEM3);
        cudaFuncSetAttribute(egu_kernel,    cudaFuncAttributeMaxDynamicSharedMemorySize, GEMM_SMEM3);
        cudaFuncSetAttribute(dense1_kernel, cudaFuncAttributeMaxDynamicSharedMemorySize, GEMM_SMEM3);
        cudaFuncSetAttribute(edown1_kernel, cudaFuncAttributeMaxDynamicSharedMemorySize, GEMM_SMEM3);
        attr_done = 1;
    }

    Freqs fr;
    for (int j = 0; j < 64; j++)
        fr.f[j] = (float)(1.0 / pow(1000000.0, (double)j / 64.0));

    float *ph, *ph1, *pt, *ptr, *psg, *py, *pattn;
    float *pwgr, *pwur, *pwdr, *pshgr, *pshur, *pshdr;
    cudaGetSymbolAddress((void**)&ph,    g_h);
    cudaGetSymbolAddress((void**)&ph1,   g_h1);
    cudaGetSymbolAddress((void**)&pt,    g_t);
    cudaGetSymbolAddress((void**)&ptr,   g_tr);
    cudaGetSymbolAddress((void**)&psg,   g_sg);
    cudaGetSymbolAddress((void**)&py,    g_y);
    cudaGetSymbolAddress((void**)&pattn, g_attn);
    cudaGetSymbolAddress((void**)&pwgr,  g_wgr);
    cudaGetSymbolAddress((void**)&pwur,  g_wur);
    cudaGetSymbolAddress((void**)&pwdr,  g_wdr);
    cudaGetSymbolAddress((void**)&pshgr, g_shgr);
    cudaGetSymbolAddress((void**)&pshur, g_shur);
    cudaGetSymbolAddress((void**)&pshdr, g_shdr);

    // 0. pre-attn norm
    rmsnorm_kernel<<<LSEQ, 256>>>(x, ln1_w, ph, nullptr);
    // 1. fused QKV projection (3xTF32)
    qkv3_kernel<<<dim3(24, 16), 256, GEMM_SMEM3>>>(ph, w_q, w_k, w_v);
    // 2. fused q/k rmsnorm + rope + cnt zeroing
    qknorm_rope_kernel<<<LSEQ * (NH + NKVH), 128>>>(q_norm_w, k_norm_w, fr);
    // 3. attention  <- profiled slot
    attn_kernel<<<dim3(LSEQ / 32, NH), 128>>>();
    // 3b. weight pre-rounding (independent; overlaps nothing but cheap)
    round_kernel<<<2048, 256>>>(wg,   pwgr,  (size_t)NE*EI*DMODEL/4);
    round_kernel<<<2048, 256>>>(wu,   pwur,  (size_t)NE*EI*DMODEL/4);
    round_kernel<<<2048, 256>>>(wd,   pwdr,  (size_t)NE*DMODEL*EI/4);
    round_kernel<<<512, 256>>>(sh_g, pshgr, (size_t)SHI*DMODEL/4);
    round_kernel<<<512, 256>>>(sh_u, pshur, (size_t)SHI*DMODEL/4);
    round_kernel<<<512, 256>>>(sh_d, pshdr, (size_t)DMODEL*SHI/4);
    // 4. output proj + residual (3xTF32)
    gemm3o_kernel<<<dim3(16, 16), 256, GEMM_SMEM3>>>(pattn, w_o, ph1, x);
    // 5. post-attn norm (full-precision g_t for gate, rounded g_tr for MoE)
    rmsnorm_kernel<<<LSEQ, 256>>>(ph1, ln2_w, pt, ptr);
    // 6. routing (fp32, exact)
    gate_kernel<<<NT, 256>>>(gate_w, gate_b);
    // 7. shared expert fused gate+up (rounded operands, no in-loop cvt)
    shgu_kernel<<<dim3(SHI / 64, NT / 128), 256, GEMM_SMEM3>>>(ptr, pshgr, pshur);
    // 8. shared expert down (STORES y)
    dense1_kernel<<<dim3(DMODEL / 128, NT / 128), 256, GEMM_SMEM3>>>(psg, pshdr, py, DMODEL, SHI);
    // 9. routed experts fused gate+up
    egu_kernel<<<dim3(EI / 64, NT / 128, NE), 256, GEMM_SMEM3>>>(pwgr, pwur);
    // 10. routed down (atomicAdd y)
    edown1_kernel<<<dim3(DMODEL / 128, NT / 128, NE), 256, GEMM_SMEM3>>>(pwdr);
    // 11. final residual add
    final_add_kernel<<<(NT * DMODEL + 255) / 256, 256>>>(out);
    (void)in_sizes; (void)n_in; (void)out_size;
}

// round 16
// speedup vs baseline: 1.6417x; 1.0020x over previous
#include <cuda_runtime.h>
#include <math.h>

#define LSEQ 2048
#define DMODEL 2048
#define NH 16
#define NKVH 4
#define HDIM 128
#define NE 16
#define NTOPK 4
#define NG 4
#define NTKG 2
#define EI 1024
#define SHI 2048
#define NT 2048
#define EPSV 1e-5f
#define ATTN_SCALE 0.08838834764831845f
#define RSF 2.5f

#define TSTRIDE 36
#define TSTAGE  (128*TSTRIDE)
#define GEMM_SMEM3 (6*TSTAGE*4)        // 110592 B

typedef unsigned long long ull;

struct Freqs { float f[64]; };

// ---------------- scratch ----------------
__device__ float g_h   [LSEQ*DMODEL];
__device__ float g_q   [LSEQ*NH*HDIM];
__device__ float g_k   [LSEQ*NKVH*HDIM];
__device__ float g_v   [LSEQ*NKVH*HDIM];
__device__ float g_attn[LSEQ*NH*HDIM];
__device__ float g_h1  [LSEQ*DMODEL];
__device__ float g_t   [LSEQ*DMODEL];     // full precision (gate)
__device__ float g_tr  [LSEQ*DMODEL];     // tf32-rounded copy (MoE A-side)
__device__ float g_Cw  [NT*NE];
__device__ int   g_cnt [NE];
__device__ int   g_bucket[NE*NT];
__device__ float g_eg  [(size_t)NE*NT*EI];
__device__ float g_sg  [(size_t)NT*SHI];
__device__ float g_y   [(size_t)NT*DMODEL];
// rounded weight copies (written once per launch by round_kernel)
__device__ float g_wgr [(size_t)NE*EI*DMODEL];
__device__ float g_wur [(size_t)NE*EI*DMODEL];
__device__ float g_wdr [(size_t)NE*DMODEL*EI];
__device__ float g_shgr[(size_t)SHI*DMODEL];
__device__ float g_shur[(size_t)SHI*DMODEL];
__device__ float g_shdr[(size_t)DMODEL*SHI];

// ---------------- helpers ----------------
__device__ __forceinline__ unsigned f2tf(float f){
    unsigned u; asm("cvt.rna.tf32.f32 %0,%1;" : "=r"(u) : "f"(f)); return u;
}
__device__ __forceinline__ float roundtf(float f){
    return __uint_as_float(f2tf(f));
}
__device__ __forceinline__ void mma_tf32(float c[4],
    unsigned a0, unsigned a1, unsigned a2, unsigned a3, unsigned b0, unsigned b1)
{
    asm volatile("mma.sync.aligned.m16n8k8.row.col.f32.tf32.tf32.f32 "
        "{%0,%1,%2,%3},{%4,%5,%6,%7},{%8,%9},{%0,%1,%2,%3};"
        : "+f"(c[0]), "+f"(c[1]), "+f"(c[2]), "+f"(c[3])
        : "r"(a0), "r"(a1), "r"(a2), "r"(a3), "r"(b0), "r"(b1));
}
__device__ __forceinline__ unsigned sptr(const void* p){
    return (unsigned)__cvta_generic_to_shared(p);
}
__device__ __forceinline__ void ldsm4(unsigned &r0, unsigned &r1, unsigned &r2, unsigned &r3,
                                      unsigned addr)
{
    asm volatile("ldmatrix.sync.aligned.m8n8.x4.shared.b16 {%0,%1,%2,%3}, [%4];"
        : "=r"(r0), "=r"(r1), "=r"(r2), "=r"(r3) : "r"(addr));
}
#define CPA16(dst, src, n) asm volatile( \
    "cp.async.cg.shared.global [%0], [%1], 16, %2;\n" :: "r"(dst), "l"(src), "r"(n))
#define CPCOMMIT() asm volatile("cp.async.commit_group;\n" ::: "memory")
#define CPWAIT0()  asm volatile("cp.async.wait_group 0;\n" ::: "memory")
#define CPWAIT1()  asm volatile("cp.async.wait_group 1;\n" ::: "memory")

// f32x2 packed math
__device__ __forceinline__ ull pack2(float lo, float hi){
    ull r; asm("mov.b64 %0,{%1,%2};" : "=l"(r) : "f"(lo), "f"(hi)); return r;
}
__device__ __forceinline__ void unpack2(ull v, float &lo, float &hi){
    asm("mov.b64 {%0,%1},%2;" : "=f"(lo), "=f"(hi) : "l"(v));
}
__device__ __forceinline__ ull fma2(ull a, ull b, ull c){
    ull d; asm("fma.rn.f32x2 %0,%1,%2,%3;" : "=l"(d) : "l"(a), "l"(b), "l"(c)); return d;
}
__device__ __forceinline__ ull mul2(ull a, ull b){
    ull d; asm("mul.rn.f32x2 %0,%1,%2;" : "=l"(d) : "l"(a), "l"(b)); return d;
}

// ---------------- fragment lane offsets ----------------
__device__ __forceinline__ void frag_offsets(int lane, int wm, int wn,
                                             unsigned* aOff, unsigned* bOff)
{
    int g = lane >> 3, lr = lane & 7;
    #pragma unroll
    for (int mt = 0; mt < 4; mt++)
        aOff[mt] = ((wm + mt*16 + (g & 1)*8 + lr) * TSTRIDE + (g >> 1)*4) * 4;
    #pragma unroll
    for (int p = 0; p < 2; p++)
        bOff[p] = ((wn + (2*p + (g >> 1))*8 + lr) * TSTRIDE + (g & 1)*4) * 4;
}
__device__ __forceinline__ void frag_offsets32(int lane, int wm, int wn,
                                               unsigned* aOff, unsigned* bOff)
{
    int g = lane >> 3, lr = lane & 7;
    #pragma unroll
    for (int mt = 0; mt < 2; mt++)
        aOff[mt] = ((wm + mt*16 + (g & 1)*8 + lr) * TSTRIDE + (g >> 1)*4) * 4;
    #pragma unroll
    for (int p = 0; p < 2; p++)
        bOff[p] = ((wn + (2*p + (g >> 1))*8 + lr) * TSTRIDE + (g & 1)*4) * 4;
}

// ---------------- MMA stage: 3x compensated (128x128) ----------------
__device__ __forceinline__ void mma_ldsm_3x(unsigned baseA, unsigned baseB,
    const unsigned* aOff, const unsigned* bOff, float (*acc)[4][4])
{
    #pragma unroll
    for (int ks = 0; ks < 32; ks += 8) {
        unsigned a[4][4], b[2][4];
        #pragma unroll
        for (int mt = 0; mt < 4; mt++)
            ldsm4(a[mt][0], a[mt][1], a[mt][2], a[mt][3], baseA + aOff[mt] + ks*4);
        #pragma unroll
        for (int p = 0; p < 2; p++)
            ldsm4(b[p][0], b[p][1], b[p][2], b[p][3], baseB + bOff[p] + ks*4);
        unsigned aH[4][4], aL[4][4], bH[4][2], bL[4][2];
        #pragma unroll
        for (int mt = 0; mt < 4; mt++)
            #pragma unroll
            for (int i = 0; i < 4; i++) {
                float v = __uint_as_float(a[mt][i]);
                aH[mt][i] = f2tf(v);
                aL[mt][i] = f2tf(v - __uint_as_float(aH[mt][i]));
            }
        #pragma unroll
        for (int p = 0; p < 2; p++) {
            #pragma unroll
            for (int i = 0; i < 4; i++) {
                float v = __uint_as_float(b[p][i]);
                unsigned h = f2tf(v);
                unsigned l = f2tf(v - __uint_as_float(h));
                int nt = 2*p + (i >> 1), cc = i & 1;
                bH[nt][cc] = h; bL[nt][cc] = l;
            }
        }
        #pragma unroll
        for (int mt = 0; mt < 4; mt++)
            #pragma unroll
            for (int nt = 0; nt < 4; nt++) {
                mma_tf32(acc[mt][nt], aH[mt][0], aH[mt][1], aH[mt][2], aH[mt][3], bH[nt][0], bH[nt][1]);
                mma_tf32(acc[mt][nt], aL[mt][0], aL[mt][1], aL[mt][2], aL[mt][3], bH[nt][0], bH[nt][1]);
                mma_tf32(acc[mt][nt], aH[mt][0], aH[mt][1], aH[mt][2], aH[mt][3], bL[nt][0], bL[nt][1]);
            }
    }
}

// ---------------- MMA stage: 1x (128x128), NO cvt (pre-rounded) ----------------
__device__ __forceinline__ void mma_ldsm_1x(unsigned baseA, unsigned baseB,
    const unsigned* aOff, const unsigned* bOff, float (*acc)[4][4])
{
    #pragma unroll
    for (int ks = 0; ks < 32; ks += 8) {
        unsigned a[4][4], b[2][4];
        #pragma unroll
        for (int mt = 0; mt < 4; mt++)
            ldsm4(a[mt][0], a[mt][1], a[mt][2], a[mt][3], baseA + aOff[mt] + ks*4);
        #pragma unroll
        for (int p = 0; p < 2; p++)
            ldsm4(b[p][0], b[p][1], b[p][2], b[p][3], baseB + bOff[p] + ks*4);
        #pragma unroll
        for (int mt = 0; mt < 4; mt++)
            #pragma unroll
            for (int nt = 0; nt < 4; nt++) {
                int p = nt >> 1, hi = (nt & 1) << 1;
                mma_tf32(acc[mt][nt], a[mt][0], a[mt][1], a[mt][2], a[mt][3],
                         b[p][hi], b[p][hi + 1]);
            }
    }
}

// ---------------- MMA stage: fused gate+up 1x, NO cvt ----------------
__device__ __forceinline__ void mma_ldsm_gu(unsigned baseA, unsigned baseBg, unsigned baseBu,
    const unsigned* aOff, const unsigned* bOff,
    float (*accg)[4][4], float (*accu)[4][4])
{
    #pragma unroll
    for (int ks = 0; ks < 32; ks += 8) {
        unsigned a[2][4], bg[2][4], bu[2][4];
        #pragma unroll
        for (int mt = 0; mt < 2; mt++)
            ldsm4(a[mt][0], a[mt][1], a[mt][2], a[mt][3], baseA + aOff[mt] + ks*4);
        #pragma unroll
        for (int p = 0; p < 2; p++) {
            ldsm4(bg[p][0], bg[p][1], bg[p][2], bg[p][3], baseBg + bOff[p] + ks*4);
            ldsm4(bu[p][0], bu[p][1], bu[p][2], bu[p][3], baseBu + bOff[p] + ks*4);
        }
        #pragma unroll
        for (int mt = 0; mt < 2; mt++)
            #pragma unroll
            for (int nt = 0; nt < 4; nt++) {
                int p = nt >> 1, hi = (nt & 1) << 1;
                mma_tf32(accg[mt][nt], a[mt][0], a[mt][1], a[mt][2], a[mt][3],
                         bg[p][hi], bg[p][hi + 1]);
                mma_tf32(accu[mt][nt], a[mt][0], a[mt][1], a[mt][2], a[mt][3],
                         bu[p][hi], bu[p][hi + 1]);
            }
    }
}

// ============ weight rounding pass (RNE tf32 pre-conversion) ============
__global__ __launch_bounds__(256) void round_kernel(const float* __restrict__ src,
                                                    float* __restrict__ dst, size_t n)
{
    size_t stride = (size_t)gridDim.x * 256;
    for (size_t i = (size_t)blockIdx.x * 256 + threadIdx.x; i < n; i += stride) {
        float4 v = *(const float4*)(src + i * 4);
        float4 o;
        o.x = roundtf(v.x); o.y = roundtf(v.y);
        o.z = roundtf(v.z); o.w = roundtf(v.w);
        *(float4*)(dst + i * 4) = o;
    }
}

// ============ fused QKV projection (3xTF32, 3-stage pipeline) ============
__global__ __launch_bounds__(256, 2) void qkv3_kernel(const float* __restrict__ A,
    const float* __restrict__ wq, const float* __restrict__ wk, const float* __restrict__ wv)
{
    extern __shared__ float sm[];
    float* As = sm;
    float* Bs = sm + 3*TSTAGE;
    const int K = DMODEL;
    int tid = threadIdx.x, lane = tid & 31, warp = tid >> 5;
    int m0 = blockIdx.y * 128, n0 = blockIdx.x * 128;
    int wm = (warp & 1) * 64, wn = (warp >> 1) * 32;

    const float* B; float* Cp; int ldc, ncol0;
    if (n0 < 2048)      { B = wq + (size_t)n0 * K;          Cp = g_q; ldc = NH*HDIM;   ncol0 = n0; }
    else if (n0 < 2560) { B = wk + (size_t)(n0 - 2048) * K; Cp = g_k; ldc = NKVH*HDIM; ncol0 = n0 - 2048; }
    else                { B = wv + (size_t)(n0 - 2560) * K; Cp = g_v; ldc = NKVH*HDIM; ncol0 = n0 - 2560; }

    unsigned aOff[4], bOff[2];
    frag_offsets(lane, wm, wn, aOff, bOff);
    unsigned sA[3] = { sptr(As), sptr(As + TSTAGE), sptr(As + 2*TSTAGE) };
    unsigned sB[3] = { sptr(Bs), sptr(Bs + TSTAGE), sptr(Bs + 2*TSTAGE) };

    const float* aSrc[4]; const float* bSrc[4]; unsigned soff[4];
    #pragma unroll
    for (int i = 0; i < 4; i++) {
        int idx = tid + i * 256, row = idx >> 3, ch = idx & 7;
        soff[i] = (row * TSTRIDE + ch * 4) * 4;
        aSrc[i] = A + (size_t)(m0 + row) * K + ch * 4;
        bSrc[i] = B + (size_t)row * K + ch * 4;
    }
    #pragma unroll
    for (int s = 0; s < 2; s++) {
        #pragma unroll
        for (int i = 0; i < 4; i++) {
            CPA16(sA[s] + soff[i], aSrc[i] + s*32, 16);
            CPA16(sB[s] + soff[i], bSrc[i] + s*32, 16);
        }
        CPCOMMIT();
    }

    float acc[4][4][4] = {};
    const int nst = K / 32;
    for (int it = 0; it < nst; it++) {
        if (it + 1 < nst) { CPWAIT1(); } else { CPWAIT0(); }
        __syncthreads();
        int cur = it % 3;
        int pf = it + 2;
        if (pf < nst) {
            int buf = pf % 3;
            #pragma unroll
            for (int i = 0; i < 4; i++) {
                CPA16(sA[buf] + soff[i], aSrc[i] + pf*32, 16);
                CPA16(sB[buf] + soff[i], bSrc[i] + pf*32, 16);
            }
            CPCOMMIT();
        }
        mma_ldsm_3x(sA[cur], sB[cur], aOff, bOff, acc);
    }
    int r = lane >> 2, c2 = (lane & 3) * 2;
    #pragma unroll
    for (int mt = 0; mt < 4; mt++) {
        int mrow = m0 + wm + mt * 16 + r;
        #pragma unroll
        for (int nt = 0; nt < 4; nt++) {
            int col = ncol0 + wn + nt * 8 + c2;
            size_t i00 = (size_t)mrow * ldc + col;
            size_t i10 = (size_t)(mrow + 8) * ldc + col;
            Cp[i00] = acc[mt][nt][0]; Cp[i00+1] = acc[mt][nt][1];
            Cp[i10] = acc[mt][nt][2]; Cp[i10+1] = acc[mt][nt][3];
        }
    }
}

// ============ o-proj + residual (3xTF32, 3-stage) ============
__global__ __launch_bounds__(256, 2) void gemm3o_kernel(const float* __restrict__ A,
    const float* __restrict__ B, float* __restrict__ C, const float* __restrict__ R)
{
    extern __shared__ float sm[];
    float* As = sm;
    float* Bs = sm + 3*TSTAGE;
    const int K = NH*HDIM, N = DMODEL;
    int tid = threadIdx.x, lane = tid & 31, warp = tid >> 5;
    int m0 = blockIdx.y * 128, n0 = blockIdx.x * 128;
    int wm = (warp & 1) * 64, wn = (warp >> 1) * 32;

    unsigned aOff[4], bOff[2];
    frag_offsets(lane, wm, wn, aOff, bOff);
    unsigned sA[3] = { sptr(As), sptr(As + TSTAGE), sptr(As + 2*TSTAGE) };
    unsigned sB[3] = { sptr(Bs), sptr(Bs + TSTAGE), sptr(Bs + 2*TSTAGE) };

    const float* aSrc[4]; const float* bSrc[4]; unsigned soff[4];
    #pragma unroll
    for (int i = 0; i < 4; i++) {
        int idx = tid + i * 256, row = idx >> 3, ch = idx & 7;
        soff[i] = (row * TSTRIDE + ch * 4) * 4;
        aSrc[i] = A + (size_t)(m0 + row) * K + ch * 4;
        bSrc[i] = B + (size_t)(n0 + row) * K + ch * 4;
    }
    #pragma unroll
    for (int s = 0; s < 2; s++) {
        #pragma unroll
        for (int i = 0; i < 4; i++) {
            CPA16(sA[s] + soff[i], aSrc[i] + s*32, 16);
            CPA16(sB[s] + soff[i], bSrc[i] + s*32, 16);
        }
        CPCOMMIT();
    }

    float acc[4][4][4] = {};
    const int nst = K / 32;
    for (int it = 0; it < nst; it++) {
        if (it + 1 < nst) { CPWAIT1(); } else { CPWAIT0(); }
        __syncthreads();
        int cur = it % 3;
        int pf = it + 2;
        if (pf < nst) {
            int buf = pf % 3;
            #pragma unroll
            for (int i = 0; i < 4; i++) {
                CPA16(sA[buf] + soff[i], aSrc[i] + pf*32, 16);
                CPA16(sB[buf] + soff[i], bSrc[i] + pf*32, 16);
            }
            CPCOMMIT();
        }
        mma_ldsm_3x(sA[cur], sB[cur], aOff, bOff, acc);
    }
    int r = lane >> 2, c2 = (lane & 3) * 2;
    #pragma unroll
    for (int mt = 0; mt < 4; mt++) {
        int mrow = m0 + wm + mt * 16 + r;
        #pragma unroll
        for (int nt = 0; nt < 4; nt++) {
            int col = n0 + wn + nt * 8 + c2;
            size_t i00 = (size_t)mrow * N + col;
            size_t i10 = (size_t)(mrow + 8) * N + col;
            C[i00] = acc[mt][nt][0] + R[i00]; C[i00+1] = acc[mt][nt][1] + R[i00+1];
            C[i10] = acc[mt][nt][2] + R[i10]; C[i10+1] = acc[mt][nt][3] + R[i10+1];
        }
    }
}

// ============ shared expert fused gate+up (pre-rounded, rounded output) ============
__global__ __launch_bounds__(256, 2) void shgu_kernel(const float* __restrict__ A,
    const float* __restrict__ shg, const float* __restrict__ shu)
{
    extern __shared__ float sm[];
    float* As  = sm;
    float* Bgs = sm + 3*TSTAGE;
    float* Bus = sm + 3*TSTAGE + 3*(64*TSTRIDE);
    const int K = DMODEL;
    int tid = threadIdx.x, lane = tid & 31, warp = tid >> 5;
    int m0 = blockIdx.y * 128, n0 = blockIdx.x * 64;
    int wm = (warp >> 1) * 32, wn = (warp & 1) * 32;

    unsigned aOff[2], bOff[2];
    frag_offsets32(lane, wm, wn, aOff, bOff);
    unsigned sA[3]  = { sptr(As), sptr(As + TSTAGE), sptr(As + 2*TSTAGE) };
    unsigned sBg[3] = { sptr(Bgs), sptr(Bgs + 64*TSTRIDE), sptr(Bgs + 2*64*TSTRIDE) };
    unsigned sBu[3] = { sptr(Bus), sptr(Bus + 64*TSTRIDE), sptr(Bus + 2*64*TSTRIDE) };

    const float* aSrc[4]; unsigned aSoff[4];
    const float* gSrc[2]; const float* uSrc[2]; unsigned bSoff[2];
    #pragma unroll
    for (int i = 0; i < 4; i++) {
        int idx = tid + i * 256, row = idx >> 3, ch = idx & 7;
        aSoff[i] = (row * TSTRIDE + ch * 4) * 4;
        aSrc[i] = A + (size_t)(m0 + row) * K + ch * 4;
    }
    #pragma unroll
    for (int i = 0; i < 2; i++) {
        int idx = tid + i * 256, row = idx >> 3, ch = idx & 7;
        bSoff[i] = (row * TSTRIDE + ch * 4) * 4;
        gSrc[i] = shg + (size_t)(n0 + row) * K + ch * 4;
        uSrc[i] = shu + (size_t)(n0 + row) * K + ch * 4;
    }
    #pragma unroll
    for (int s = 0; s < 2; s++) {
        #pragma unroll
        for (int i = 0; i < 4; i++) CPA16(sA[s] + aSoff[i], aSrc[i] + s*32, 16);
        #pragma unroll
        for (int i = 0; i < 2; i++) {
            CPA16(sBg[s] + bSoff[i], gSrc[i] + s*32, 16);
            CPA16(sBu[s] + bSoff[i], uSrc[i] + s*32, 16);
        }
        CPCOMMIT();
    }

    float accg[2][4][4] = {}, accu[2][4][4] = {};
    const int nst = K / 32;
    for (int it = 0; it < nst; it++) {
        if (it + 1 < nst) { CPWAIT1(); } else { CPWAIT0(); }
        __syncthreads();
        int cur = it % 3;
        int pf = it + 2;
        if (pf < nst) {
            int buf = pf % 3;
            #pragma unroll
            for (int i = 0; i < 4; i++) CPA16(sA[buf] + aSoff[i], aSrc[i] + pf*32, 16);
            #pragma unroll
            for (int i = 0; i < 2; i++) {
                CPA16(sBg[buf] + bSoff[i], gSrc[i] + pf*32, 16);
                CPA16(sBu[buf] + bSoff[i], uSrc[i] + pf*32, 16);
            }
            CPCOMMIT();
        }
        mma_ldsm_gu(sA[cur], sBg[cur], sBu[cur], aOff, bOff, accg, accu);
    }
    int r = lane >> 2, c2 = (lane & 3) * 2;
    #pragma unroll
    for (int mt = 0; mt < 2; mt++) {
        int mrow = m0 + wm + mt * 16 + r;
        #pragma unroll
        for (int nt = 0; nt < 4; nt++) {
            int col = n0 + wn + nt * 8 + c2;
            #pragma unroll
            for (int half = 0; half < 2; half++) {
                int rr = mrow + half * 8;
                float gv = accg[mt][nt][half*2], uv = accu[mt][nt][half*2];
                float gv1 = accg[mt][nt][half*2+1], uv1 = accu[mt][nt][half*2+1];
                size_t o = (size_t)rr * SHI + col;
                g_sg[o]   = roundtf((gv  / (1.f + expf(-gv)))  * uv);
                g_sg[o+1] = roundtf((gv1 / (1.f + expf(-gv1))) * uv1);
            }
        }
    }
}

// ============ routed expert fused gate+up (pre-rounded, rounded output) ============
__global__ __launch_bounds__(256, 2) void egu_kernel(const float* __restrict__ wg,
    const float* __restrict__ wu)
{
    int e = blockIdx.z;
    int cnt = g_cnt[e];
    int m0 = blockIdx.y * 128;
    if (m0 >= cnt) return;
    int n0 = blockIdx.x * 64;
    extern __shared__ float sm[];
    float* As  = sm;
    float* Bgs = sm + 3*TSTAGE;
    float* Bus = sm + 3*TSTAGE + 3*(64*TSTRIDE);
    __shared__ int toks[128];
    const int K = DMODEL;
    int tid = threadIdx.x, lane = tid & 31, warp = tid >> 5;
    if (tid < 128) {
        int m = m0 + tid;
        toks[tid] = (m < cnt) ? g_bucket[e * NT + m] : -1;
    }
    __syncthreads();
    const float* Bg = wg + (size_t)e * EI * DMODEL + (size_t)n0 * K;
    const float* Bu = wu + (size_t)e * EI * DMODEL + (size_t)n0 * K;
    int wm = (warp >> 1) * 32, wn = (warp & 1) * 32;

    unsigned aOff[2], bOff[2];
    frag_offsets32(lane, wm, wn, aOff, bOff);
    unsigned sA[3]  = { sptr(As), sptr(As + TSTAGE), sptr(As + 2*TSTAGE) };
    unsigned sBg[3] = { sptr(Bgs), sptr(Bgs + 64*TSTRIDE), sptr(Bgs + 2*64*TSTRIDE) };
    unsigned sBu[3] = { sptr(Bus), sptr(Bus + 64*TSTRIDE), sptr(Bus + 2*64*TSTRIDE) };

    const float* aSrc[4]; unsigned aSoff[4]; int aBytes[4];
    const float* gSrc[2]; const float* uSrc[2]; unsigned bSoff[2];
    #pragma unroll
    for (int i = 0; i < 4; i++) {
        int idx = tid + i * 256, row = idx >> 3, ch = idx & 7;
        aSoff[i] = (row * TSTRIDE + ch * 4) * 4;
        int tok = toks[row];
        aBytes[i] = (tok >= 0) ? 16 : 0;
        aSrc[i] = g_tr + (size_t)(tok >= 0 ? tok : 0) * K + ch * 4;
    }
    #pragma unroll
    for (int i = 0; i < 2; i++) {
        int idx = tid + i * 256, row = idx >> 3, ch = idx & 7;
        bSoff[i] = (row * TSTRIDE + ch * 4) * 4;
        gSrc[i] = Bg + (size_t)row * K + ch * 4;
        uSrc[i] = Bu + (size_t)row * K + ch * 4;
    }
    #pragma unroll
    for (int s = 0; s < 2; s++) {
        #pragma unroll
        for (int i = 0; i < 4; i++) CPA16(sA[s] + aSoff[i], aSrc[i] + s*32, aBytes[i]);
        #pragma unroll
        for (int i = 0; i < 2; i++) {
            CPA16(sBg[s] + bSoff[i], gSrc[i] + s*32, 16);
            CPA16(sBu[s] + bSoff[i], uSrc[i] + s*32, 16);
        }
        CPCOMMIT();
    }

    float accg[2][4][4] = {}, accu[2][4][4] = {};
    const int nst = K / 32;
    for (int it = 0; it < nst; it++) {
        if (it + 1 < nst) { CPWAIT1(); } else { CPWAIT0(); }
        __syncthreads();
        int cur = it % 3;
        int pf = it + 2;
        if (pf < nst) {
            int buf = pf % 3;
            #pragma unroll
            for (int i = 0; i < 4; i++) CPA16(sA[buf] + aSoff[i], aSrc[i] + pf*32, aBytes[i]);
            #pragma unroll
            for (int i = 0; i < 2; i++) {
                CPA16(sBg[buf] + bSoff[i], gSrc[i] + pf*32, 16);
                CPA16(sBu[buf] + bSoff[i], uSrc[i] + pf*32, 16);
            }
            CPCOMMIT();
        }
        mma_ldsm_gu(sA[cur], sBg[cur], sBu[cur], aOff, bOff, accg, accu);
    }
    int r = lane >> 2, c2 = (lane & 3) * 2;
    #pragma unroll
    for (int mt = 0; mt < 2; mt++) {
        int mloc = wm + mt * 16 + r;
        #pragma unroll
        for (int half = 0; half < 2; half++) {
            int m = m0 + mloc + half * 8;
            if (m >= cnt) continue;
            int tok = toks[mloc + half * 8];
            float wgt = g_Cw[tok * NE + e];
            #pragma unroll
            for (int nt = 0; nt < 4; nt++) {
                int col = n0 + wn + nt * 8 + c2;
                float gv = accg[mt][nt][half*2], uv = accu[mt][nt][half*2];
                float gv1 = accg[mt][nt][half*2+1], uv1 = accu[mt][nt][half*2+1];
                size_t o = ((size_t)e * NT + m) * EI + col;
                g_eg[o]   = roundtf((gv  / (1.f + expf(-gv)))  * uv  * wgt);
                g_eg[o+1] = roundtf((gv1 / (1.f + expf(-gv1))) * uv1 * wgt);
            }
        }
    }
}

// ============ dense 1xTF32 GEMM (128x128, no cvt): shared-expert down ============
__global__ __launch_bounds__(256, 2) void dense1_kernel(const float* __restrict__ A,
    const float* __restrict__ B, float* __restrict__ C, int N, int K)
{
    extern __shared__ float sm[];
    float* As = sm;
    float* Bs = sm + 3*TSTAGE;
    int tid = threadIdx.x, lane = tid & 31, warp = tid >> 5;
    int m0 = blockIdx.y * 128, n0 = blockIdx.x * 128;
    int wm = (warp & 1) * 64, wn = (warp >> 1) * 32;

    unsigned aOff[4], bOff[2];
    frag_offsets(lane, wm, wn, aOff, bOff);
    unsigned sA[3] = { sptr(As), sptr(As + TSTAGE), sptr(As + 2*TSTAGE) };
    unsigned sB[3] = { sptr(Bs), sptr(Bs + TSTAGE), sptr(Bs + 2*TSTAGE) };

    const float* aSrc[4]; const float* bSrc[4]; unsigned soff[4];
    #pragma unroll
    for (int i = 0; i < 4; i++) {
        int idx = tid + i * 256, row = idx >> 3, ch = idx & 7;
        soff[i] = (row * TSTRIDE + ch * 4) * 4;
        aSrc[i] = A + (size_t)(m0 + row) * K + ch * 4;
        bSrc[i] = B + (size_t)(n0 + row) * K + ch * 4;
    }
    #pragma unroll
    for (int s = 0; s < 2; s++) {
        #pragma unroll
        for (int i = 0; i < 4; i++) {
            CPA16(sA[s] + soff[i], aSrc[i] + s*32, 16);
            CPA16(sB[s] + soff[i], bSrc[i] + s*32, 16);
        }
        CPCOMMIT();
    }

    float acc[4][4][4] = {};
    const int nst = K / 32;
    for (int it = 0; it < nst; it++) {
        if (it + 1 < nst) { CPWAIT1(); } else { CPWAIT0(); }
        __syncthreads();
        int cur = it % 3;
        int pf = it + 2;
        if (pf < nst) {
            int buf = pf % 3;
            #pragma unroll
            for (int i = 0; i < 4; i++) {
                CPA16(sA[buf] + soff[i], aSrc[i] + pf*32, 16);
                CPA16(sB[buf] + soff[i], bSrc[i] + pf*32, 16);
            }
            CPCOMMIT();
        }
        mma_ldsm_1x(sA[cur], sB[cur], aOff, bOff, acc);
    }
    int r = lane >> 2, c2 = (lane & 3) * 2;
    #pragma unroll
    for (int mt = 0; mt < 4; mt++) {
        int mrow = m0 + wm + mt * 16 + r;
        #pragma unroll
        for (int nt = 0; nt < 4; nt++) {
            int col = n0 + wn + nt * 8 + c2;
            size_t i00 = (size_t)mrow * N + col;
            size_t i10 = (size_t)(mrow + 8) * N + col;
            C[i00] = acc[mt][nt][0]; C[i00+1] = acc[mt][nt][1];
            C[i10] = acc[mt][nt][2]; C[i10+1] = acc[mt][nt][3];
        }
    }
}

// ============ expert down GEMM (1x, 128x128, no cvt) + scatter atomicAdd ============
__global__ __launch_bounds__(256, 2) void edown1_kernel(const float* __restrict__ wd)
{
    int e = blockIdx.z;
    int cnt = g_cnt[e];
    int m0 = blockIdx.y * 128;
    if (m0 >= cnt) return;
    int n0 = blockIdx.x * 128;
    extern __shared__ float sm[];
    float* As = sm;
    float* Bs = sm + 3*TSTAGE;
    __shared__ int toks[128];
    const int K = EI;
    int tid = threadIdx.x, lane = tid & 31, warp = tid >> 5;
    if (tid < 128) {
        int m = m0 + tid;
        toks[tid] = (m < cnt) ? g_bucket[e * NT + m] : -1;
    }
    __syncthreads();
    const float* Ae = g_eg + ((size_t)e * NT + m0) * EI;
    const float* B = wd + (size_t)e * DMODEL * EI + (size_t)n0 * K;
    int wm = (warp & 1) * 64, wn = (warp >> 1) * 32;

    unsigned aOff[4], bOff[2];
    frag_offsets(lane, wm, wn, aOff, bOff);
    unsigned sA[3] = { sptr(As), sptr(As + TSTAGE), sptr(As + 2*TSTAGE) };
    unsigned sB[3] = { sptr(Bs), sptr(Bs + TSTAGE), sptr(Bs + 2*TSTAGE) };

    const float* aSrc[4]; const float* bSrc[4]; unsigned soff[4]; int aBytes[4];
    #pragma unroll
    for (int i = 0; i < 4; i++) {
        int idx = tid + i * 256, row = idx >> 3, ch = idx & 7;
        soff[i] = (row * TSTRIDE + ch * 4) * 4;
        bool ok = (m0 + row) < cnt;
        aBytes[i] = ok ? 16 : 0;
        aSrc[i] = Ae + (size_t)(ok ? row : 0) * K + ch * 4;
        bSrc[i] = B + (size_t)row * K + ch * 4;
    }
    #pragma unroll
    for (int s = 0; s < 2; s++) {
        #pragma unroll
        for (int i = 0; i < 4; i++) {
            CPA16(sA[s] + soff[i], aSrc[i] + s*32, aBytes[i]);
            CPA16(sB[s] + soff[i], bSrc[i] + s*32, 16);
        }
        CPCOMMIT();
    }

    float acc[4][4][4] = {};
    const int nst = K / 32;
    for (int it = 0; it < nst; it++) {
        if (it + 1 < nst) { CPWAIT1(); } else { CPWAIT0(); }
        __syncthreads();
        int cur = it % 3;
        int pf = it + 2;
        if (pf < nst) {
            int buf = pf % 3;
            #pragma unroll
            for (int i = 0; i < 4; i++) {
                CPA16(sA[buf] + soff[i], aSrc[i] + pf*32, aBytes[i]);
                CPA16(sB[buf] + soff[i], bSrc[i] + pf*32, 16);
            }
            CPCOMMIT();
        }
        mma_ldsm_1x(sA[cur], sB[cur], aOff, bOff, acc);
    }
    int r = lane >> 2, c2 = (lane & 3) * 2;
    #pragma unroll
    for (int mt = 0; mt < 4; mt++) {
        int mloc = wm + mt * 16 + r;
        #pragma unroll
        for (int nt = 0; nt < 4; nt++) {
            int col = n0 + wn + nt * 8 + c2;
            if (m0 + mloc < cnt) {
                int tok = toks[mloc];
                atomicAdd(&g_y[(size_t)tok * DMODEL + col],     acc[mt][nt][0]);
                atomicAdd(&g_y[(size_t)tok * DMODEL + col + 1], acc[mt][nt][1]);
            }
            if (m0 + mloc + 8 < cnt) {
                int tok = toks[mloc + 8];
                atomicAdd(&g_y[(size_t)tok * DMODEL + col],     acc[mt][nt][2]);
                atomicAdd(&g_y[(size_t)tok * DMODEL + col + 1], acc[mt][nt][3]);
            }
        }
    }
}

// ---------------- RMSNorm (optional rounded second output) ----------------
__global__ __launch_bounds__(256) void rmsnorm_kernel(const float* __restrict__ x,
                                                      const float* __restrict__ w,
                                                      float* __restrict__ out,
                                                      float* __restrict__ out2)
{
    int row = blockIdx.x;
    const float* xr = x + (size_t)row * DMODEL;
    float ss = 0.f;
    for (int d = threadIdx.x; d < DMODEL; d += 256) { float v = xr[d]; ss += v * v; }
    __shared__ float red[8];
    #pragma unroll
    for (int off = 16; off; off >>= 1) ss += __shfl_xor_sync(0xffffffffu, ss, off);
    if ((threadIdx.x & 31) == 0) red[threadIdx.x >> 5] = ss;
    __syncthreads();
    __shared__ float sinv;
    if (threadIdx.x == 0) {
        float tot = 0.f;
        #pragma unroll
        for (int i = 0; i < 8; i++) tot += red[i];
        sinv = 1.f / sqrtf(tot / (float)DMODEL + EPSV);
    }
    __syncthreads();
    float si = sinv;
    for (int d = threadIdx.x; d < DMODEL; d += 256) {
        float v = xr[d] * si * w[d];
        out[(size_t)row * DMODEL + d] = v;
        if (out2) out2[(size_t)row * DMODEL + d] = roundtf(v);
    }
}

// ---------------- fused per-(token,head) RMSNorm + RoPE (inline fp32 trig) ----------------
__global__ __launch_bounds__(128) void qknorm_rope_kernel(const float* __restrict__ qw,
                                                          const float* __restrict__ kw,
                                                          Freqs fr)
{
    int row = blockIdx.x;
    if (row == 0 && threadIdx.x < NE) g_cnt[threadIdx.x] = 0;
    float* buf; const float* w; int nh;
    if (row < LSEQ * NH) { buf = g_q; w = qw; nh = NH; }
    else { row -= LSEQ * NH; buf = g_k; w = kw; nh = NKVH; }
    int pos = row / nh;
    float* p = buf + (size_t)row * HDIM;
    int tid = threadIdx.x;
    float v = p[tid];
    float ss = v * v;
    #pragma unroll
    for (int off = 16; off; off >>= 1) ss += __shfl_xor_sync(0xffffffffu, ss, off);
    __shared__ float red_s[4];
    if ((tid & 31) == 0) red_s[tid >> 5] = ss;
    __syncthreads();
    __shared__ float sinv;
    if (tid == 0) sinv = 1.f / sqrtf((red_s[0] + red_s[1] + red_s[2] + red_s[3]) / (float)HDIM + EPSV);
    __shared__ float shn[HDIM];
    __syncthreads();
    shn[tid] = v * sinv * w[tid];
    __syncthreads();
    if (tid < 64) {
        float x1 = shn[tid], x2 = shn[tid + 64];
        float ang = (float)pos * fr.f[tid];
        float k = rintf(ang * 0.15915494309189535f);
        float red = ang - k * 6.28125f;
        red = red - k * 0.0019354820251464844f;
        red = red - k * (-1.7484556e-7f);
        float s, c;
        sincosf(red, &s, &c);
        p[tid]      = x1 * c - x2 * s;
        p[tid + 64] = x2 * c + x1 * s;
    }
}

// ---------------- flash attention (fp32 f32x2, causal, GQA) ----------------
// Score loop restructured for ILP: j processed in groups of 4, each score
// accumulated in 2 interleaved partial chains (8 independent chains in flight).
__global__ __launch_bounds__(128) void attn_kernel()
{
    __shared__ __align__(16) float Qs[32][HDIM];
    __shared__ __align__(16) float Ks[32][HDIM];
    __shared__ __align__(16) float Vs[32][HDIM];
    int h = blockIdx.y;
    int q0 = blockIdx.x * 32;
    int kvh = h >> 2;
    int tid = threadIdx.x;
    int r = tid >> 2, qd = tid & 3;

    for (int i = tid; i < 32 * 32; i += 128) {
        int row = i >> 5, d4 = i & 31;
        ((float4*)&Qs[row][0])[d4] =
            *(const float4*)(g_q + (size_t)(q0 + row) * (NH * HDIM) + h * HDIM + d4 * 4);
    }
    __syncthreads();
    ull qq[16];
    #pragma unroll
    for (int i = 0; i < 16; i++) qq[i] = *(const ull*)&Qs[r][qd * 32 + i * 2];

    ull o2[16];
    #pragma unroll
    for (int i = 0; i < 16; i++) o2[i] = 0ULL;
    float mrow = -INFINITY, lrow = 0.f;

    for (int k0 = 0; k0 <= q0; k0 += 32) {
        __syncthreads();
        for (int i = tid; i < 32 * 32; i += 128) {
            int row = i >> 5, d4 = i & 31;
            size_t base = (size_t)(k0 + row) * (NKVH * HDIM) + kvh * HDIM + d4 * 4;
            ((float4*)&Ks[row][0])[d4] = *(const float4*)(g_k + base);
            ((float4*)&Vs[row][0])[d4] = *(const float4*)(g_v + base);
        }
        __syncthreads();

        float s[32];
        float tmax = -INFINITY;
        #pragma unroll
        for (int j4 = 0; j4 < 32; j4 += 4) {
            const ull* K0 = (const ull*)&Ks[j4 + 0][qd * 32];
            const ull* K1 = (const ull*)&Ks[j4 + 1][qd * 32];
            const ull* K2 = (const ull*)&Ks[j4 + 2][qd * 32];
            const ull* K3 = (const ull*)&Ks[j4 + 3][qd * 32];
            ull a0 = 0ULL, b0 = 0ULL, a1 = 0ULL, b1 = 0ULL;
            ull a2 = 0ULL, b2 = 0ULL, a3 = 0ULL, b3 = 0ULL;
            #pragma unroll
            for (int i = 0; i < 16; i += 2) {
                a0 = fma2(qq[i], K0[i], a0); b0 = fma2(qq[i+1], K0[i+1], b0);
                a1 = fma2(qq[i], K1[i], a1); b1 = fma2(qq[i+1], K1[i+1], b1);
                a2 = fma2(qq[i], K2[i], a2); b2 = fma2(qq[i+1], K2[i+1], b2);
                a3 = fma2(qq[i], K3[i], a3); b3 = fma2(qq[i+1], K3[i+1], b3);
            }
            ull t0 = pack2(0.f, 0.f), one = pack2(1.f, 1.f);
            (void)t0; (void)one;
            float lo, hi, lo2, hi2;
            #pragma unroll
            for (int jj = 0; jj < 4; jj++) {
                ull pa = (jj == 0) ? a0 : (jj == 1) ? a1 : (jj == 2) ? a2 : a3;
                ull pb = (jj == 0) ? b0 : (jj == 1) ? b1 : (jj == 2) ? b2 : b3;
                unpack2(pa, lo, hi);
                unpack2(pb, lo2, hi2);
                float pacc = (lo + hi) + (lo2 + hi2);
                pacc += __shfl_xor_sync(0xffffffffu, pacc, 1);
                pacc += __shfl_xor_sync(0xffffffffu, pacc, 2);
                pacc *= ATTN_SCALE;
                int j = j4 + jj;
                if (k0 + j > q0 + r) pacc = -INFINITY;
                s[j] = pacc;
                tmax = fmaxf(tmax, pacc);
            }
        }
        float mnew = fmaxf(mrow, tmax);
        float alpha = __expf(mrow - mnew);
        lrow *= alpha;
        ull al2 = pack2(alpha, alpha);
        #pragma unroll
        for (int i = 0; i < 16; i++) o2[i] = mul2(o2[i], al2);
        #pragma unroll
        for (int j = 0; j < 32; j++) {
            float pv = __expf(s[j] - mnew);
            lrow += pv;
            ull pv2 = pack2(pv, pv);
            const ull* V2 = (const ull*)&Vs[j][qd * 32];
            #pragma unroll
            for (int i = 0; i < 16; i++) o2[i] = fma2(pv2, V2[i], o2[i]);
        }
        mrow = mnew;
    }
    float inv = 1.f / lrow;
    size_t base = (size_t)(q0 + r) * (NH * HDIM) + h * HDIM + qd * 32;
    #pragma unroll
    for (int i = 0; i < 16; i++) {
        float lo, hi; unpack2(o2[i], lo, hi);
        g_attn[base + i * 2]     = lo * inv;
        g_attn[base + i * 2 + 1] = hi * inv;
    }
}

// ---------------- gating / routing (fp32 exact; coalesced) ----------------
__global__ __launch_bounds__(256) void gate_kernel(const float* __restrict__ gate_w,
                                                   const float* __restrict__ gate_bias)
{
    int t = blockIdx.x;
    const float4* t4 = (const float4*)(g_t + (size_t)t * DMODEL);
    int warp = threadIdx.x >> 5, lane = threadIdx.x & 31;
    int e0 = warp * 2;
    const float4* g0 = (const float4*)(gate_w + (size_t)e0 * DMODEL);
    const float4* g1 = (const float4*)(gate_w + (size_t)(e0 + 1) * DMODEL);
    float a0 = 0.f, a1 = 0.f;
    for (int i = lane; i < DMODEL / 4; i += 32) {
        float4 tv = t4[i], v0 = g0[i], v1 = g1[i];
        a0 += tv.x*v0.x + tv.y*v0.y + tv.z*v0.z + tv.w*v0.w;
        a1 += tv.x*v1.x + tv.y*v1.y + tv.z*v1.z + tv.w*v1.w;
    }
    #pragma unroll
    for (int off = 16; off; off >>= 1) {
        a0 += __shfl_xor_sync(0xffffffffu, a0, off);
        a1 += __shfl_xor_sync(0xffffffffu, a1, off);
    }
    __shared__ float sc_s[NE];
    if (lane == 0) {
        sc_s[e0]     = 1.f / (1.f + expf(-a0));
        sc_s[e0 + 1] = 1.f / (1.f + expf(-a1));
    }
    __syncthreads();
    if (threadIdx.x == 0) {
        float sc[NE], s2[NE];
        #pragma unroll
        for (int e = 0; e < NE; e++) { sc[e] = sc_s[e]; s2[e] = sc[e] + gate_bias[e]; }
        float gs[NG];
        #pragma unroll
        for (int gq = 0; gq < NG; gq++) {
            float m1 = -INFINITY, m2 = -INFINITY;
            #pragma unroll
            for (int j = 0; j < NE / NG; j++) {
                float vv = s2[gq * (NE / NG) + j];
                if (vv > m1) { m2 = m1; m1 = vv; }
                else if (vv > m2) { m2 = vv; }
            }
            gs[gq] = m1 + m2;
        }
        bool gsel[NG] = {false, false, false, false};
        {
            float gtmp[NG];
            #pragma unroll
            for (int gq = 0; gq < NG; gq++) gtmp[gq] = gs[gq];
            for (int it = 0; it < NTKG; it++) {
                int bi = 0; float bv = -INFINITY;
                #pragma unroll
                for (int gq = 0; gq < NG; gq++)
                    if (gtmp[gq] > bv) { bv = gtmp[gq]; bi = gq; }
                gsel[bi] = true; gtmp[bi] = -INFINITY;
            }
        }
        float masked[NE];
        #pragma unroll
        for (int e = 0; e < NE; e++) masked[e] = gsel[e >> 2] ? s2[e] : 0.f;
        int inds[NTOPK];
        for (int it = 0; it < NTOPK; it++) {
            int bi = 0; float bv = -INFINITY;
            #pragma unroll
            for (int e = 0; e < NE; e++)
                if (masked[e] > bv) { bv = masked[e]; bi = e; }
            inds[it] = bi; masked[bi] = -INFINITY;
        }
        float wv[NTOPK], wsum = 0.f;
        #pragma unroll
        for (int i = 0; i < NTOPK; i++) { wv[i] = sc[inds[i]]; wsum += wv[i]; }
        float invw = RSF / (wsum + 1e-20f);
        float crow[NE];
        #pragma unroll
        for (int e = 0; e < NE; e++) crow[e] = 0.f;
        #pragma unroll
        for (int i = 0; i < NTOPK; i++) crow[inds[i]] += wv[i] * invw;
        #pragma unroll
        for (int e = 0; e < NE; e++) g_Cw[t * NE + e] = crow[e];
        #pragma unroll
        for (int i = 0; i < NTOPK; i++) {
            int e = inds[i];
            int posn = atomicAdd(&g_cnt[e], 1);
            g_bucket[e * NT + posn] = t;
        }
    }
}

// ---------------- final: out = h1 + y ----------------
__global__ void final_add_kernel(float* __restrict__ out)
{
    int i = blockIdx.x * blockDim.x + threadIdx.x;
    if (i < NT * DMODEL) out[i] = g_h1[i] + g_y[i];
}

// ---------------- launch ----------------
extern "C" void kernel_launch(void* const* d_in, const int* in_sizes, int n_in,
                              void* d_out, int out_size)
{
    const float* x        = (const float*)d_in[0];
    const float* w_q      = (const float*)d_in[1];
    const float* w_k      = (const float*)d_in[2];
    const float* w_v      = (const float*)d_in[3];
    const float* w_o      = (const float*)d_in[4];
    const float* q_norm_w = (const float*)d_in[5];
    const float* k_norm_w = (const float*)d_in[6];
    const float* ln1_w    = (const float*)d_in[7];
    const float* ln2_w    = (const float*)d_in[8];
    const float* gate_w   = (const float*)d_in[9];
    const float* gate_b   = (const float*)d_in[10];
    const float* wg       = (const float*)d_in[11];
    const float* wu       = (const float*)d_in[12];
    const float* wd       = (const float*)d_in[13];
    const float* sh_g     = (const float*)d_in[14];
    const float* sh_u     = (const float*)d_in[15];
    const float* sh_d     = (const float*)d_in[16];
    float* out = (float*)d_out;

    static int attr_done = 0;
    if (!attr_done) {
        cudaFuncSetAttribute(qkv3_kernel,   cudaFuncAttributeMaxDynamicSharedMemorySize, GEMM_SMEM3);
        cudaFuncSetAttribute(gemm3o_kernel, cudaFuncAttributeMaxDynamicSharedMemorySize, GEMM_SMEM3);
        cudaFuncSetAttribute(shgu_kernel,   cudaFuncAttributeMaxDynamicSharedMemorySize, GEMM_SMEM3);
        cudaFuncSetAttribute(egu_kernel,    cudaFuncAttributeMaxDynamicSharedMemorySize, GEMM_SMEM3);
        cudaFuncSetAttribute(dense1_kernel, cudaFuncAttributeMaxDynamicSharedMemorySize, GEMM_SMEM3);
        cudaFuncSetAttribute(edown1_kernel, cudaFuncAttributeMaxDynamicSharedMemorySize, GEMM_SMEM3);
        attr_done = 1;
    }

    Freqs fr;
    for (int j = 0; j < 64; j++)
        fr.f[j] = (float)(1.0 / pow(1000000.0, (double)j / 64.0));

    float *ph, *ph1, *pt, *ptr, *psg, *py, *pattn;
    float *pwgr, *pwur, *pwdr, *pshgr, *pshur, *pshdr;
    cudaGetSymbolAddress((void**)&ph,    g_h);
    cudaGetSymbolAddress((void**)&ph1,   g_h1);
    cudaGetSymbolAddress((void**)&pt,    g_t);
    cudaGetSymbolAddress((void**)&ptr,   g_tr);
    cudaGetSymbolAddress((void**)&psg,   g_sg);
    cudaGetSymbolAddress((void**)&py,    g_y);
    cudaGetSymbolAddress((void**)&pattn, g_attn);
    cudaGetSymbolAddress((void**)&pwgr,  g_wgr);
    cudaGetSymbolAddress((void**)&pwur,  g_wur);
    cudaGetSymbolAddress((void**)&pwdr,  g_wdr);
    cudaGetSymbolAddress((void**)&pshgr, g_shgr);
    cudaGetSymbolAddress((void**)&pshur, g_shur);
    cudaGetSymbolAddress((void**)&pshdr, g_shdr);

    // 0. pre-attn norm
    rmsnorm_kernel<<<LSEQ, 256>>>(x, ln1_w, ph, nullptr);
    // 1. fused QKV projection (3xTF32)
    qkv3_kernel<<<dim3(24, 16), 256, GEMM_SMEM3>>>(ph, w_q, w_k, w_v);
    // 2. fused q/k rmsnorm + rope + cnt zeroing
    qknorm_rope_kernel<<<LSEQ * (NH + NKVH), 128>>>(q_norm_w, k_norm_w, fr);
    // 3. attention (ILP-restructured score loop)  <- profiled slot
    attn_kernel<<<dim3(LSEQ / 32, NH), 128>>>();
    // 3b. weight pre-rounding
    round_kernel<<<2048, 256>>>(wg,   pwgr,  (size_t)NE*EI*DMODEL/4);
    round_kernel<<<2048, 256>>>(wu,   pwur,  (size_t)NE*EI*DMODEL/4);
    round_kernel<<<2048, 256>>>(wd,   pwdr,  (size_t)NE*DMODEL*EI/4);
    round_kernel<<<512, 256>>>(sh_g, pshgr, (size_t)SHI*DMODEL/4);
    round_kernel<<<512, 256>>>(sh_u, pshur, (size_t)SHI*DMODEL/4);
    round_kernel<<<512, 256>>>(sh_d, pshdr, (size_t)DMODEL*SHI/4);
    // 4. output proj + residual (3xTF32)
    gemm3o_kernel<<<dim3(16, 16), 256, GEMM_SMEM3>>>(pattn, w_o, ph1, x);
    // 5. post-attn norm (full-precision g_t for gate, rounded g_tr for MoE)
    rmsnorm_kernel<<<LSEQ, 256>>>(ph1, ln2_w, pt, ptr);
    // 6. routing (fp32, exact)
    gate_kernel<<<NT, 256>>>(gate_w, gate_b);
    // 7. shared expert fused gate+up
    shgu_kernel<<<dim3(SHI / 64, NT / 128), 256, GEMM_SMEM3>>>(ptr, pshgr, pshur);
    // 8. shared expert down (STORES y)
    dense1_kernel<<<dim3(DMODEL / 128, NT / 128), 256, GEMM_SMEM3>>>(psg, pshdr, py, DMODEL, SHI);
    // 9. routed experts fused gate+up
    egu_kernel<<<dim3(EI / 64, NT / 128, NE), 256, GEMM_SMEM3>>>(pwgr, pwur);
    // 10. routed down (atomicAdd y)
    edown1_kernel<<<dim3(DMODEL / 128, NT / 128, NE), 256, GEMM_SMEM3>>>(pwdr);
    // 11. final residual add
    final_add_kernel<<<(NT * DMODEL + 255) / 256, 256>>>(out);
    (void)in_sizes; (void)n_in; (void)out_size;
}

// round 17
// speedup vs baseline: 4.3235x; 2.6336x over previous
#include <cuda_runtime.h>
#include <math.h>

#define LSEQ 2048
#define DMODEL 2048
#define NH 16
#define NKVH 4
#define HDIM 128
#define NE 16
#define NTOPK 4
#define NG 4
#define NTKG 2
#define EI 1024
#define SHI 2048
#define NT 2048
#define EPSV 1e-5f
#define ATTN_SCALE 0.08838834764831845f
#define RSF 2.5f

#define TSTRIDE 36
#define TSTAGE  (128*TSTRIDE)
#define GEMM_SMEM3 (6*TSTAGE*4)        // 110592 B

typedef unsigned long long ull;

struct Freqs { float f[64]; };

// ---------------- scratch ----------------
__device__ float g_h   [LSEQ*DMODEL];
__device__ float g_q   [LSEQ*NH*HDIM];
__device__ float g_k   [LSEQ*NKVH*HDIM];
__device__ float g_v   [LSEQ*NKVH*HDIM];
__device__ float g_vt  [NKVH*HDIM*LSEQ];          // V transposed per kv-head
__device__ float g_S   [(size_t)NH*LSEQ*LSEQ];    // logits -> probs (268 MB)
__device__ float g_attn[LSEQ*NH*HDIM];
__device__ float g_h1  [LSEQ*DMODEL];
__device__ float g_t   [LSEQ*DMODEL];
__device__ float g_tr  [LSEQ*DMODEL];
__device__ float g_Cw  [NT*NE];
__device__ int   g_cnt [NE];
__device__ int   g_bucket[NE*NT];
__device__ float g_eg  [(size_t)NE*NT*EI];
__device__ float g_sg  [(size_t)NT*SHI];
__device__ float g_y   [(size_t)NT*DMODEL];
__device__ float g_wgr [(size_t)NE*EI*DMODEL];
__device__ float g_wur [(size_t)NE*EI*DMODEL];
__device__ float g_wdr [(size_t)NE*DMODEL*EI];
__device__ float g_shgr[(size_t)SHI*DMODEL];
__device__ float g_shur[(size_t)SHI*DMODEL];
__device__ float g_shdr[(size_t)DMODEL*SHI];

// ---------------- helpers ----------------
__device__ __forceinline__ unsigned f2tf(float f){
    unsigned u; asm("cvt.rna.tf32.f32 %0,%1;" : "=r"(u) : "f"(f)); return u;
}
__device__ __forceinline__ float roundtf(float f){
    return __uint_as_float(f2tf(f));
}
__device__ __forceinline__ void mma_tf32(float c[4],
    unsigned a0, unsigned a1, unsigned a2, unsigned a3, unsigned b0, unsigned b1)
{
    asm volatile("mma.sync.aligned.m16n8k8.row.col.f32.tf32.tf32.f32 "
        "{%0,%1,%2,%3},{%4,%5,%6,%7},{%8,%9},{%0,%1,%2,%3};"
        : "+f"(c[0]), "+f"(c[1]), "+f"(c[2]), "+f"(c[3])
        : "r"(a0), "r"(a1), "r"(a2), "r"(a3), "r"(b0), "r"(b1));
}
__device__ __forceinline__ unsigned sptr(const void* p){
    return (unsigned)__cvta_generic_to_shared(p);
}
__device__ __forceinline__ void ldsm4(unsigned &r0, unsigned &r1, unsigned &r2, unsigned &r3,
                                      unsigned addr)
{
    asm volatile("ldmatrix.sync.aligned.m8n8.x4.shared.b16 {%0,%1,%2,%3}, [%4];"
        : "=r"(r0), "=r"(r1), "=r"(r2), "=r"(r3) : "r"(addr));
}
#define CPA16(dst, src, n) asm volatile( \
    "cp.async.cg.shared.global [%0], [%1], 16, %2;\n" :: "r"(dst), "l"(src), "r"(n))
#define CPCOMMIT() asm volatile("cp.async.commit_group;\n" ::: "memory")
#define CPWAIT0()  asm volatile("cp.async.wait_group 0;\n" ::: "memory")
#define CPWAIT1()  asm volatile("cp.async.wait_group 1;\n" ::: "memory")

// ---------------- fragment lane offsets ----------------
__device__ __forceinline__ void frag_offsets(int lane, int wm, int wn,
                                             unsigned* aOff, unsigned* bOff)
{
    int g = lane >> 3, lr = lane & 7;
    #pragma unroll
    for (int mt = 0; mt < 4; mt++)
        aOff[mt] = ((wm + mt*16 + (g & 1)*8 + lr) * TSTRIDE + (g >> 1)*4) * 4;
    #pragma unroll
    for (int p = 0; p < 2; p++)
        bOff[p] = ((wn + (2*p + (g >> 1))*8 + lr) * TSTRIDE + (g & 1)*4) * 4;
}
__device__ __forceinline__ void frag_offsets32(int lane, int wm, int wn,
                                               unsigned* aOff, unsigned* bOff)
{
    int g = lane >> 3, lr = lane & 7;
    #pragma unroll
    for (int mt = 0; mt < 2; mt++)
        aOff[mt] = ((wm + mt*16 + (g & 1)*8 + lr) * TSTRIDE + (g >> 1)*4) * 4;
    #pragma unroll
    for (int p = 0; p < 2; p++)
        bOff[p] = ((wn + (2*p + (g >> 1))*8 + lr) * TSTRIDE + (g & 1)*4) * 4;
}

// ---------------- MMA stage: 3x compensated (128x128) ----------------
__device__ __forceinline__ void mma_ldsm_3x(unsigned baseA, unsigned baseB,
    const unsigned* aOff, const unsigned* bOff, float (*acc)[4][4])
{
    #pragma unroll
    for (int ks = 0; ks < 32; ks += 8) {
        unsigned a[4][4], b[2][4];
        #pragma unroll
        for (int mt = 0; mt < 4; mt++)
            ldsm4(a[mt][0], a[mt][1], a[mt][2], a[mt][3], baseA + aOff[mt] + ks*4);
        #pragma unroll
        for (int p = 0; p < 2; p++)
            ldsm4(b[p][0], b[p][1], b[p][2], b[p][3], baseB + bOff[p] + ks*4);
        unsigned aH[4][4], aL[4][4], bH[4][2], bL[4][2];
        #pragma unroll
        for (int mt = 0; mt < 4; mt++)
            #pragma unroll
            for (int i = 0; i < 4; i++) {
                float v = __uint_as_float(a[mt][i]);
                aH[mt][i] = f2tf(v);
                aL[mt][i] = f2tf(v - __uint_as_float(aH[mt][i]));
            }
        #pragma unroll
        for (int p = 0; p < 2; p++) {
            #pragma unroll
            for (int i = 0; i < 4; i++) {
                float v = __uint_as_float(b[p][i]);
                unsigned h = f2tf(v);
                unsigned l = f2tf(v - __uint_as_float(h));
                int nt = 2*p + (i >> 1), cc = i & 1;
                bH[nt][cc] = h; bL[nt][cc] = l;
            }
        }
        #pragma unroll
        for (int mt = 0; mt < 4; mt++)
            #pragma unroll
            for (int nt = 0; nt < 4; nt++) {
                mma_tf32(acc[mt][nt], aH[mt][0], aH[mt][1], aH[mt][2], aH[mt][3], bH[nt][0], bH[nt][1]);
                mma_tf32(acc[mt][nt], aL[mt][0], aL[mt][1], aL[mt][2], aL[mt][3], bH[nt][0], bH[nt][1]);
                mma_tf32(acc[mt][nt], aH[mt][0], aH[mt][1], aH[mt][2], aH[mt][3], bL[nt][0], bL[nt][1]);
            }
    }
}

// ---------------- MMA stage: 1x (128x128), NO cvt (pre-rounded) ----------------
__device__ __forceinline__ void mma_ldsm_1x(unsigned baseA, unsigned baseB,
    const unsigned* aOff, const unsigned* bOff, float (*acc)[4][4])
{
    #pragma unroll
    for (int ks = 0; ks < 32; ks += 8) {
        unsigned a[4][4], b[2][4];
        #pragma unroll
        for (int mt = 0; mt < 4; mt++)
            ldsm4(a[mt][0], a[mt][1], a[mt][2], a[mt][3], baseA + aOff[mt] + ks*4);
        #pragma unroll
        for (int p = 0; p < 2; p++)
            ldsm4(b[p][0], b[p][1], b[p][2], b[p][3], baseB + bOff[p] + ks*4);
        #pragma unroll
        for (int mt = 0; mt < 4; mt++)
            #pragma unroll
            for (int nt = 0; nt < 4; nt++) {
                int p = nt >> 1, hi = (nt & 1) << 1;
                mma_tf32(acc[mt][nt], a[mt][0], a[mt][1], a[mt][2], a[mt][3],
                         b[p][hi], b[p][hi + 1]);
            }
    }
}

// ---------------- MMA stage: fused gate+up 1x, NO cvt ----------------
__device__ __forceinline__ void mma_ldsm_gu(unsigned baseA, unsigned baseBg, unsigned baseBu,
    const unsigned* aOff, const unsigned* bOff,
    float (*accg)[4][4], float (*accu)[4][4])
{
    #pragma unroll
    for (int ks = 0; ks < 32; ks += 8) {
        unsigned a[2][4], bg[2][4], bu[2][4];
        #pragma unroll
        for (int mt = 0; mt < 2; mt++)
            ldsm4(a[mt][0], a[mt][1], a[mt][2], a[mt][3], baseA + aOff[mt] + ks*4);
        #pragma unroll
        for (int p = 0; p < 2; p++) {
            ldsm4(bg[p][0], bg[p][1], bg[p][2], bg[p][3], baseBg + bOff[p] + ks*4);
            ldsm4(bu[p][0], bu[p][1], bu[p][2], bu[p][3], baseBu + bOff[p] + ks*4);
        }
        #pragma unroll
        for (int mt = 0; mt < 2; mt++)
            #pragma unroll
            for (int nt = 0; nt < 4; nt++) {
                int p = nt >> 1, hi = (nt & 1) << 1;
                mma_tf32(accg[mt][nt], a[mt][0], a[mt][1], a[mt][2], a[mt][3],
                         bg[p][hi], bg[p][hi + 1]);
                mma_tf32(accu[mt][nt], a[mt][0], a[mt][1], a[mt][2], a[mt][3],
                         bu[p][hi], bu[p][hi + 1]);
            }
    }
}

// ============ weight rounding pass ============
__global__ __launch_bounds__(256) void round_kernel(const float* __restrict__ src,
                                                    float* __restrict__ dst, size_t n)
{
    size_t stride = (size_t)gridDim.x * 256;
    for (size_t i = (size_t)blockIdx.x * 256 + threadIdx.x; i < n; i += stride) {
        float4 v = *(const float4*)(src + i * 4);
        float4 o;
        o.x = roundtf(v.x); o.y = roundtf(v.y);
        o.z = roundtf(v.z); o.w = roundtf(v.w);
        *(float4*)(dst + i * 4) = o;
    }
}

// ============ fused QKV projection (3xTF32, 3-stage pipeline) ============
__global__ __launch_bounds__(256, 2) void qkv3_kernel(const float* __restrict__ A,
    const float* __restrict__ wq, const float* __restrict__ wk, const float* __restrict__ wv)
{
    extern __shared__ float sm[];
    float* As = sm;
    float* Bs = sm + 3*TSTAGE;
    const int K = DMODEL;
    int tid = threadIdx.x, lane = tid & 31, warp = tid >> 5;
    int m0 = blockIdx.y * 128, n0 = blockIdx.x * 128;
    int wm = (warp & 1) * 64, wn = (warp >> 1) * 32;

    const float* B; float* Cp; int ldc, ncol0;
    if (n0 < 2048)      { B = wq + (size_t)n0 * K;          Cp = g_q; ldc = NH*HDIM;   ncol0 = n0; }
    else if (n0 < 2560) { B = wk + (size_t)(n0 - 2048) * K; Cp = g_k; ldc = NKVH*HDIM; ncol0 = n0 - 2048; }
    else                { B = wv + (size_t)(n0 - 2560) * K; Cp = g_v; ldc = NKVH*HDIM; ncol0 = n0 - 2560; }

    unsigned aOff[4], bOff[2];
    frag_offsets(lane, wm, wn, aOff, bOff);
    unsigned sA[3] = { sptr(As), sptr(As + TSTAGE), sptr(As + 2*TSTAGE) };
    unsigned sB[3] = { sptr(Bs), sptr(Bs + TSTAGE), sptr(Bs + 2*TSTAGE) };

    const float* aSrc[4]; const float* bSrc[4]; unsigned soff[4];
    #pragma unroll
    for (int i = 0; i < 4; i++) {
        int idx = tid + i * 256, row = idx >> 3, ch = idx & 7;
        soff[i] = (row * TSTRIDE + ch * 4) * 4;
        aSrc[i] = A + (size_t)(m0 + row) * K + ch * 4;
        bSrc[i] = B + (size_t)row * K + ch * 4;
    }
    #pragma unroll
    for (int s = 0; s < 2; s++) {
        #pragma unroll
        for (int i = 0; i < 4; i++) {
            CPA16(sA[s] + soff[i], aSrc[i] + s*32, 16);
            CPA16(sB[s] + soff[i], bSrc[i] + s*32, 16);
        }
        CPCOMMIT();
    }

    float acc[4][4][4] = {};
    const int nst = K / 32;
    for (int it = 0; it < nst; it++) {
        if (it + 1 < nst) { CPWAIT1(); } else { CPWAIT0(); }
        __syncthreads();
        int cur = it % 3;
        int pf = it + 2;
        if (pf < nst) {
            int buf = pf % 3;
            #pragma unroll
            for (int i = 0; i < 4; i++) {
                CPA16(sA[buf] + soff[i], aSrc[i] + pf*32, 16);
                CPA16(sB[buf] + soff[i], bSrc[i] + pf*32, 16);
            }
            CPCOMMIT();
        }
        mma_ldsm_3x(sA[cur], sB[cur], aOff, bOff, acc);
    }
    int r = lane >> 2, c2 = (lane & 3) * 2;
    #pragma unroll
    for (int mt = 0; mt < 4; mt++) {
        int mrow = m0 + wm + mt * 16 + r;
        #pragma unroll
        for (int nt = 0; nt < 4; nt++) {
            int col = ncol0 + wn + nt * 8 + c2;
            size_t i00 = (size_t)mrow * ldc + col;
            size_t i10 = (size_t)(mrow + 8) * ldc + col;
            Cp[i00] = acc[mt][nt][0]; Cp[i00+1] = acc[mt][nt][1];
            Cp[i10] = acc[mt][nt][2]; Cp[i10+1] = acc[mt][nt][3];
        }
    }
}

// ============ QK^T logits (3xTF32): S[h] = scale*(q_h @ k_kvh^T), causal mask ============
__global__ __launch_bounds__(256, 2) void qk3_kernel()
{
    int kx = blockIdx.x, qy = blockIdx.y, h = blockIdx.z;
    if (kx > qy) return;
    extern __shared__ float sm[];
    float* As = sm;
    float* Bs = sm + 3*TSTAGE;
    const int K = HDIM;
    int tid = threadIdx.x, lane = tid & 31, warp = tid >> 5;
    int m0 = qy * 128, n0 = kx * 128, kvh = h >> 2;
    int wm = (warp & 1) * 64, wn = (warp >> 1) * 32;

    unsigned aOff[4], bOff[2];
    frag_offsets(lane, wm, wn, aOff, bOff);
    unsigned sA[3] = { sptr(As), sptr(As + TSTAGE), sptr(As + 2*TSTAGE) };
    unsigned sB[3] = { sptr(Bs), sptr(Bs + TSTAGE), sptr(Bs + 2*TSTAGE) };

    const float* aSrc[4]; const float* bSrc[4]; unsigned soff[4];
    #pragma unroll
    for (int i = 0; i < 4; i++) {
        int idx = tid + i * 256, row = idx >> 3, ch = idx & 7;
        soff[i] = (row * TSTRIDE + ch * 4) * 4;
        aSrc[i] = g_q + (size_t)(m0 + row) * (NH*HDIM) + h * HDIM + ch * 4;
        bSrc[i] = g_k + (size_t)(n0 + row) * (NKVH*HDIM) + kvh * HDIM + ch * 4;
    }
    #pragma unroll
    for (int s = 0; s < 2; s++) {
        #pragma unroll
        for (int i = 0; i < 4; i++) {
            CPA16(sA[s] + soff[i], aSrc[i] + s*32, 16);
            CPA16(sB[s] + soff[i], bSrc[i] + s*32, 16);
        }
        CPCOMMIT();
    }

    float acc[4][4][4] = {};
    const int nst = K / 32;     // 4
    for (int it = 0; it < nst; it++) {
        if (it + 1 < nst) { CPWAIT1(); } else { CPWAIT0(); }
        __syncthreads();
        int cur = it % 3;
        int pf = it + 2;
        if (pf < nst) {
            int buf = pf % 3;
            #pragma unroll
            for (int i = 0; i < 4; i++) {
                CPA16(sA[buf] + soff[i], aSrc[i] + pf*32, 16);
                CPA16(sB[buf] + soff[i], bSrc[i] + pf*32, 16);
            }
            CPCOMMIT();
        }
        mma_ldsm_3x(sA[cur], sB[cur], aOff, bOff, acc);
    }
    float* S = g_S + (size_t)h * LSEQ * LSEQ;
    int r = lane >> 2, c2 = (lane & 3) * 2;
    #pragma unroll
    for (int mt = 0; mt < 4; mt++) {
        int r0 = m0 + wm + mt * 16 + r;
        int r1 = r0 + 8;
        #pragma unroll
        for (int nt = 0; nt < 4; nt++) {
            int col = n0 + wn + nt * 8 + c2;
            float v0 = acc[mt][nt][0] * ATTN_SCALE;
            float v1 = acc[mt][nt][1] * ATTN_SCALE;
            float v2 = acc[mt][nt][2] * ATTN_SCALE;
            float v3 = acc[mt][nt][3] * ATTN_SCALE;
            if (col     > r0) v0 = -1e30f;
            if (col + 1 > r0) v1 = -1e30f;
            if (col     > r1) v2 = -1e30f;
            if (col + 1 > r1) v3 = -1e30f;
            S[(size_t)r0 * LSEQ + col]     = v0;
            S[(size_t)r0 * LSEQ + col + 1] = v1;
            S[(size_t)r1 * LSEQ + col]     = v2;
            S[(size_t)r1 * LSEQ + col + 1] = v3;
        }
    }
}

// ============ row softmax over S (in place), zeros beyond causal limit ============
__global__ __launch_bounds__(256) void softmax_kernel()
{
    int row = blockIdx.x, h = blockIdx.y;
    float* S = g_S + (size_t)h * LSEQ * LSEQ + (size_t)row * LSEQ;
    int valid = row + 1;
    int tid = threadIdx.x;
    float vals[8];
    float vmax = -INFINITY;
    #pragma unroll
    for (int i = 0; i < 8; i++) {
        int c = tid + i * 256;
        vals[i] = (c < valid) ? S[c] : -INFINITY;
        vmax = fmaxf(vmax, vals[i]);
    }
    #pragma unroll
    for (int off = 16; off; off >>= 1) vmax = fmaxf(vmax, __shfl_xor_sync(0xffffffffu, vmax, off));
    __shared__ float red[8];
    if ((tid & 31) == 0) red[tid >> 5] = vmax;
    __syncthreads();
    __shared__ float smax, ssum;
    if (tid == 0) {
        float m = red[0];
        #pragma unroll
        for (int i = 1; i < 8; i++) m = fmaxf(m, red[i]);
        smax = m;
    }
    __syncthreads();
    float m = smax;
    float lsum = 0.f;
    #pragma unroll
    for (int i = 0; i < 8; i++) {
        int c = tid + i * 256;
        float p = (c < valid) ? __expf(vals[i] - m) : 0.f;
        vals[i] = p;
        lsum += p;
    }
    #pragma unroll
    for (int off = 16; off; off >>= 1) lsum += __shfl_xor_sync(0xffffffffu, lsum, off);
    if ((tid & 31) == 0) red[tid >> 5] = lsum;
    __syncthreads();
    if (tid == 0) {
        float s = 0.f;
        #pragma unroll
        for (int i = 0; i < 8; i++) s += red[i];
        ssum = 1.f / s;
    }
    __syncthreads();
    float inv = ssum;
    #pragma unroll
    for (int i = 0; i < 8; i++) {
        int c = tid + i * 256;
        S[c] = vals[i] * inv;
    }
}

// ============ V transpose: g_vt[kvh*128+d][l] = g_v[l][kvh*128+d] ============
__global__ __launch_bounds__(256) void vtrans_kernel()
{
    int row = blockIdx.x;       // 0..511 = kvh*128+d
    float* dst = g_vt + (size_t)row * LSEQ;
    for (int l = threadIdx.x; l < LSEQ; l += 256)
        dst[l] = g_v[(size_t)l * (NKVH*HDIM) + row];
}

// ============ P@V (3xTF32): g_attn[l][h*128+d] = P[h] @ Vt[kvh]^T ============
__global__ __launch_bounds__(256, 2) void pv3_kernel()
{
    int my = blockIdx.x, h = blockIdx.y;
    extern __shared__ float sm[];
    float* As = sm;
    float* Bs = sm + 3*TSTAGE;
    int tid = threadIdx.x, lane = tid & 31, warp = tid >> 5;
    int m0 = my * 128, kvh = h >> 2;
    int wm = (warp & 1) * 64, wn = (warp >> 1) * 32;
    const float* P = g_S + (size_t)h * LSEQ * LSEQ;
    const float* Vt = g_vt + (size_t)kvh * HDIM * LSEQ;
    const int KEFF = m0 + 128;          // causal: P cols >= KEFF are exactly zero

    unsigned aOff[4], bOff[2];
    frag_offsets(lane, wm, wn, aOff, bOff);
    unsigned sA[3] = { sptr(As), sptr(As + TSTAGE), sptr(As + 2*TSTAGE) };
    unsigned sB[3] = { sptr(Bs), sptr(Bs + TSTAGE), sptr(Bs + 2*TSTAGE) };

    const float* aSrc[4]; const float* bSrc[4]; unsigned soff[4];
    #pragma unroll
    for (int i = 0; i < 4; i++) {
        int idx = tid + i * 256, row = idx >> 3, ch = idx & 7;
        soff[i] = (row * TSTRIDE + ch * 4) * 4;
        aSrc[i] = P + (size_t)(m0 + row) * LSEQ + ch * 4;
        bSrc[i] = Vt + (size_t)row * LSEQ + ch * 4;
    }
    #pragma unroll
    for (int s = 0; s < 2; s++) {
        #pragma unroll
        for (int i = 0; i < 4; i++) {
            CPA16(sA[s] + soff[i], aSrc[i] + s*32, 16);
            CPA16(sB[s] + soff[i], bSrc[i] + s*32, 16);
        }
        CPCOMMIT();
    }

    float acc[4][4][4] = {};
    const int nst = KEFF / 32;
    for (int it = 0; it < nst; it++) {
        if (it + 1 < nst) { CPWAIT1(); } else { CPWAIT0(); }
        __syncthreads();
        int cur = it % 3;
        int pf = it + 2;
        if (pf < nst) {
            int buf = pf % 3;
            #pragma unroll
            for (int i = 0; i < 4; i++) {
                CPA16(sA[buf] + soff[i], aSrc[i] + pf*32, 16);
                CPA16(sB[buf] + soff[i], bSrc[i] + pf*32, 16);
            }
            CPCOMMIT();
        }
        mma_ldsm_3x(sA[cur], sB[cur], aOff, bOff, acc);
    }
    int r = lane >> 2, c2 = (lane & 3) * 2;
    #pragma unroll
    for (int mt = 0; mt < 4; mt++) {
        int mrow = m0 + wm + mt * 16 + r;
        #pragma unroll
        for (int nt = 0; nt < 4; nt++) {
            int col = h * HDIM + wn + nt * 8 + c2;
            size_t i00 = (size_t)mrow * (NH*HDIM) + col;
            size_t i10 = (size_t)(mrow + 8) * (NH*HDIM) + col;
            g_attn[i00] = acc[mt][nt][0]; g_attn[i00+1] = acc[mt][nt][1];
            g_attn[i10] = acc[mt][nt][2]; g_attn[i10+1] = acc[mt][nt][3];
        }
    }
}

// ============ o-proj + residual (3xTF32, 3-stage) ============
__global__ __launch_bounds__(256, 2) void gemm3o_kernel(const float* __restrict__ A,
    const float* __restrict__ B, float* __restrict__ C, const float* __restrict__ R)
{
    extern __shared__ float sm[];
    float* As = sm;
    float* Bs = sm + 3*TSTAGE;
    const int K = NH*HDIM, N = DMODEL;
    int tid = threadIdx.x, lane = tid & 31, warp = tid >> 5;
    int m0 = blockIdx.y * 128, n0 = blockIdx.x * 128;
    int wm = (warp & 1) * 64, wn = (warp >> 1) * 32;

    unsigned aOff[4], bOff[2];
    frag_offsets(lane, wm, wn, aOff, bOff);
    unsigned sA[3] = { sptr(As), sptr(As + TSTAGE), sptr(As + 2*TSTAGE) };
    unsigned sB[3] = { sptr(Bs), sptr(Bs + TSTAGE), sptr(Bs + 2*TSTAGE) };

    const float* aSrc[4]; const float* bSrc[4]; unsigned soff[4];
    #pragma unroll
    for (int i = 0; i < 4; i++) {
        int idx = tid + i * 256, row = idx >> 3, ch = idx & 7;
        soff[i] = (row * TSTRIDE + ch * 4) * 4;
        aSrc[i] = A + (size_t)(m0 + row) * K + ch * 4;
        bSrc[i] = B + (size_t)(n0 + row) * K + ch * 4;
    }
    #pragma unroll
    for (int s = 0; s < 2; s++) {
        #pragma unroll
        for (int i = 0; i < 4; i++) {
            CPA16(sA[s] + soff[i], aSrc[i] + s*32, 16);
            CPA16(sB[s] + soff[i], bSrc[i] + s*32, 16);
        }
        CPCOMMIT();
    }

    float acc[4][4][4] = {};
    const int nst = K / 32;
    for (int it = 0; it < nst; it++) {
        if (it + 1 < nst) { CPWAIT1(); } else { CPWAIT0(); }
        __syncthreads();
        int cur = it % 3;
        int pf = it + 2;
        if (pf < nst) {
            int buf = pf % 3;
            #pragma unroll
            for (int i = 0; i < 4; i++) {
                CPA16(sA[buf] + soff[i], aSrc[i] + pf*32, 16);
                CPA16(sB[buf] + soff[i], bSrc[i] + pf*32, 16);
            }
            CPCOMMIT();
        }
        mma_ldsm_3x(sA[cur], sB[cur], aOff, bOff, acc);
    }
    int r = lane >> 2, c2 = (lane & 3) * 2;
    #pragma unroll
    for (int mt = 0; mt < 4; mt++) {
        int mrow = m0 + wm + mt * 16 + r;
        #pragma unroll
        for (int nt = 0; nt < 4; nt++) {
            int col = n0 + wn + nt * 8 + c2;
            size_t i00 = (size_t)mrow * N + col;
            size_t i10 = (size_t)(mrow + 8) * N + col;
            C[i00] = acc[mt][nt][0] + R[i00]; C[i00+1] = acc[mt][nt][1] + R[i00+1];
            C[i10] = acc[mt][nt][2] + R[i10]; C[i10+1] = acc[mt][nt][3] + R[i10+1];
        }
    }
}

// ============ shared expert fused gate+up ============
__global__ __launch_bounds__(256, 2) void shgu_kernel(const float* __restrict__ A,
    const float* __restrict__ shg, const float* __restrict__ shu)
{
    extern __shared__ float sm[];
    float* As  = sm;
    float* Bgs = sm + 3*TSTAGE;
    float* Bus = sm + 3*TSTAGE + 3*(64*TSTRIDE);
    const int K = DMODEL;
    int tid = threadIdx.x, lane = tid & 31, warp = tid >> 5;
    int m0 = blockIdx.y * 128, n0 = blockIdx.x * 64;
    int wm = (warp >> 1) * 32, wn = (warp & 1) * 32;

    unsigned aOff[2], bOff[2];
    frag_offsets32(lane, wm, wn, aOff, bOff);
    unsigned sA[3]  = { sptr(As), sptr(As + TSTAGE), sptr(As + 2*TSTAGE) };
    unsigned sBg[3] = { sptr(Bgs), sptr(Bgs + 64*TSTRIDE), sptr(Bgs + 2*64*TSTRIDE) };
    unsigned sBu[3] = { sptr(Bus), sptr(Bus + 64*TSTRIDE), sptr(Bus + 2*64*TSTRIDE) };

    const float* aSrc[4]; unsigned aSoff[4];
    const float* gSrc[2]; const float* uSrc[2]; unsigned bSoff[2];
    #pragma unroll
    for (int i = 0; i < 4; i++) {
        int idx = tid + i * 256, row = idx >> 3, ch = idx & 7;
        aSoff[i] = (row * TSTRIDE + ch * 4) * 4;
        aSrc[i] = A + (size_t)(m0 + row) * K + ch * 4;
    }
    #pragma unroll
    for (int i = 0; i < 2; i++) {
        int idx = tid + i * 256, row = idx >> 3, ch = idx & 7;
        bSoff[i] = (row * TSTRIDE + ch * 4) * 4;
        gSrc[i] = shg + (size_t)(n0 + row) * K + ch * 4;
        uSrc[i] = shu + (size_t)(n0 + row) * K + ch * 4;
    }
    #pragma unroll
    for (int s = 0; s < 2; s++) {
        #pragma unroll
        for (int i = 0; i < 4; i++) CPA16(sA[s] + aSoff[i], aSrc[i] + s*32, 16);
        #pragma unroll
        for (int i = 0; i < 2; i++) {
            CPA16(sBg[s] + bSoff[i], gSrc[i] + s*32, 16);
            CPA16(sBu[s] + bSoff[i], uSrc[i] + s*32, 16);
        }
        CPCOMMIT();
    }

    float accg[2][4][4] = {}, accu[2][4][4] = {};
    const int nst = K / 32;
    for (int it = 0; it < nst; it++) {
        if (it + 1 < nst) { CPWAIT1(); } else { CPWAIT0(); }
        __syncthreads();
        int cur = it % 3;
        int pf = it + 2;
        if (pf < nst) {
            int buf = pf % 3;
            #pragma unroll
            for (int i = 0; i < 4; i++) CPA16(sA[buf] + aSoff[i], aSrc[i] + pf*32, 16);
            #pragma unroll
            for (int i = 0; i < 2; i++) {
                CPA16(sBg[buf] + bSoff[i], gSrc[i] + pf*32, 16);
                CPA16(sBu[buf] + bSoff[i], uSrc[i] + pf*32, 16);
            }
            CPCOMMIT();
        }
        mma_ldsm_gu(sA[cur], sBg[cur], sBu[cur], aOff, bOff, accg, accu);
    }
    int r = lane >> 2, c2 = (lane & 3) * 2;
    #pragma unroll
    for (int mt = 0; mt < 2; mt++) {
        int mrow = m0 + wm + mt * 16 + r;
        #pragma unroll
        for (int nt = 0; nt < 4; nt++) {
            int col = n0 + wn + nt * 8 + c2;
            #pragma unroll
            for (int half = 0; half < 2; half++) {
                int rr = mrow + half * 8;
                float gv = accg[mt][nt][half*2], uv = accu[mt][nt][half*2];
                float gv1 = accg[mt][nt][half*2+1], uv1 = accu[mt][nt][half*2+1];
                size_t o = (size_t)rr * SHI + col;
                g_sg[o]   = roundtf((gv  / (1.f + expf(-gv)))  * uv);
                g_sg[o+1] = roundtf((gv1 / (1.f + expf(-gv1))) * uv1);
            }
        }
    }
}

// ============ routed expert fused gate+up ============
__global__ __launch_bounds__(256, 2) void egu_kernel(const float* __restrict__ wg,
    const float* __restrict__ wu)
{
    int e = blockIdx.z;
    int cnt = g_cnt[e];
    int m0 = blockIdx.y * 128;
    if (m0 >= cnt) return;
    int n0 = blockIdx.x * 64;
    extern __shared__ float sm[];
    float* As  = sm;
    float* Bgs = sm + 3*TSTAGE;
    float* Bus = sm + 3*TSTAGE + 3*(64*TSTRIDE);
    __shared__ int toks[128];
    const int K = DMODEL;
    int tid = threadIdx.x, lane = tid & 31, warp = tid >> 5;
    if (tid < 128) {
        int m = m0 + tid;
        toks[tid] = (m < cnt) ? g_bucket[e * NT + m] : -1;
    }
    __syncthreads();
    const float* Bg = wg + (size_t)e * EI * DMODEL + (size_t)n0 * K;
    const float* Bu = wu + (size_t)e * EI * DMODEL + (size_t)n0 * K;
    int wm = (warp >> 1) * 32, wn = (warp & 1) * 32;

    unsigned aOff[2], bOff[2];
    frag_offsets32(lane, wm, wn, aOff, bOff);
    unsigned sA[3]  = { sptr(As), sptr(As + TSTAGE), sptr(As + 2*TSTAGE) };
    unsigned sBg[3] = { sptr(Bgs), sptr(Bgs + 64*TSTRIDE), sptr(Bgs + 2*64*TSTRIDE) };
    unsigned sBu[3] = { sptr(Bus), sptr(Bus + 64*TSTRIDE), sptr(Bus + 2*64*TSTRIDE) };

    const float* aSrc[4]; unsigned aSoff[4]; int aBytes[4];
    const float* gSrc[2]; const float* uSrc[2]; unsigned bSoff[2];
    #pragma unroll
    for (int i = 0; i < 4; i++) {
        int idx = tid + i * 256, row = idx >> 3, ch = idx & 7;
        aSoff[i] = (row * TSTRIDE + ch * 4) * 4;
        int tok = toks[row];
        aBytes[i] = (tok >= 0) ? 16 : 0;
        aSrc[i] = g_tr + (size_t)(tok >= 0 ? tok : 0) * K + ch * 4;
    }
    #pragma unroll
    for (int i = 0; i < 2; i++) {
        int idx = tid + i * 256, row = idx >> 3, ch = idx & 7;
        bSoff[i] = (row * TSTRIDE + ch * 4) * 4;
        gSrc[i] = Bg + (size_t)row * K + ch * 4;
        uSrc[i] = Bu + (size_t)row * K + ch * 4;
    }
    #pragma unroll
    for (int s = 0; s < 2; s++) {
        #pragma unroll
        for (int i = 0; i < 4; i++) CPA16(sA[s] + aSoff[i], aSrc[i] + s*32, aBytes[i]);
        #pragma unroll
        for (int i = 0; i < 2; i++) {
            CPA16(sBg[s] + bSoff[i], gSrc[i] + s*32, 16);
            CPA16(sBu[s] + bSoff[i], uSrc[i] + s*32, 16);
        }
        CPCOMMIT();
    }

    float accg[2][4][4] = {}, accu[2][4][4] = {};
    const int nst = K / 32;
    for (int it = 0; it < nst; it++) {
        if (it + 1 < nst) { CPWAIT1(); } else { CPWAIT0(); }
        __syncthreads();
        int cur = it % 3;
        int pf = it + 2;
        if (pf < nst) {
            int buf = pf % 3;
            #pragma unroll
            for (int i = 0; i < 4; i++) CPA16(sA[buf] + aSoff[i], aSrc[i] + pf*32, aBytes[i]);
            #pragma unroll
            for (int i = 0; i < 2; i++) {
                CPA16(sBg[buf] + bSoff[i], gSrc[i] + pf*32, 16);
                CPA16(sBu[buf] + bSoff[i], uSrc[i] + pf*32, 16);
            }
            CPCOMMIT();
        }
        mma_ldsm_gu(sA[cur], sBg[cur], sBu[cur], aOff, bOff, accg, accu);
    }
    int r = lane >> 2, c2 = (lane & 3) * 2;
    #pragma unroll
    for (int mt = 0; mt < 2; mt++) {
        int mloc = wm + mt * 16 + r;
        #pragma unroll
        for (int half = 0; half < 2; half++) {
            int m = m0 + mloc + half * 8;
            if (m >= cnt) continue;
            int tok = toks[mloc + half * 8];
            float wgt = g_Cw[tok * NE + e];
            #pragma unroll
            for (int nt = 0; nt < 4; nt++) {
                int col = n0 + wn + nt * 8 + c2;
                float gv = accg[mt][nt][half*2], uv = accu[mt][nt][half*2];
                float gv1 = accg[mt][nt][half*2+1], uv1 = accu[mt][nt][half*2+1];
                size_t o = ((size_t)e * NT + m) * EI + col;
                g_eg[o]   = roundtf((gv  / (1.f + expf(-gv)))  * uv  * wgt);
                g_eg[o+1] = roundtf((gv1 / (1.f + expf(-gv1))) * uv1 * wgt);
            }
        }
    }
}

// ============ dense 1xTF32 GEMM (128x128, no cvt): shared-expert down ============
__global__ __launch_bounds__(256, 2) void dense1_kernel(const float* __restrict__ A,
    const float* __restrict__ B, float* __restrict__ C, int N, int K)
{
    extern __shared__ float sm[];
    float* As = sm;
    float* Bs = sm + 3*TSTAGE;
    int tid = threadIdx.x, lane = tid & 31, warp = tid >> 5;
    int m0 = blockIdx.y * 128, n0 = blockIdx.x * 128;
    int wm = (warp & 1) * 64, wn = (warp >> 1) * 32;

    unsigned aOff[4], bOff[2];
    frag_offsets(lane, wm, wn, aOff, bOff);
    unsigned sA[3] = { sptr(As), sptr(As + TSTAGE), sptr(As + 2*TSTAGE) };
    unsigned sB[3] = { sptr(Bs), sptr(Bs + TSTAGE), sptr(Bs + 2*TSTAGE) };

    const float* aSrc[4]; const float* bSrc[4]; unsigned soff[4];
    #pragma unroll
    for (int i = 0; i < 4; i++) {
        int idx = tid + i * 256, row = idx >> 3, ch = idx & 7;
        soff[i] = (row * TSTRIDE + ch * 4) * 4;
        aSrc[i] = A + (size_t)(m0 + row) * K + ch * 4;
        bSrc[i] = B + (size_t)(n0 + row) * K + ch * 4;
    }
    #pragma unroll
    for (int s = 0; s < 2; s++) {
        #pragma unroll
        for (int i = 0; i < 4; i++) {
            CPA16(sA[s] + soff[i], aSrc[i] + s*32, 16);
            CPA16(sB[s] + soff[i], bSrc[i] + s*32, 16);
        }
        CPCOMMIT();
    }

    float acc[4][4][4] = {};
    const int nst = K / 32;
    for (int it = 0; it < nst; it++) {
        if (it + 1 < nst) { CPWAIT1(); } else { CPWAIT0(); }
        __syncthreads();
        int cur = it % 3;
        int pf = it + 2;
        if (pf < nst) {
            int buf = pf % 3;
            #pragma unroll
            for (int i = 0; i < 4; i++) {
                CPA16(sA[buf] + soff[i], aSrc[i] + pf*32, 16);
                CPA16(sB[buf] + soff[i], bSrc[i] + pf*32, 16);
            }
            CPCOMMIT();
        }
        mma_ldsm_1x(sA[cur], sB[cur], aOff, bOff, acc);
    }
    int r = lane >> 2, c2 = (lane & 3) * 2;
    #pragma unroll
    for (int mt = 0; mt < 4; mt++) {
        int mrow = m0 + wm + mt * 16 + r;
        #pragma unroll
        for (int nt = 0; nt < 4; nt++) {
            int col = n0 + wn + nt * 8 + c2;
            size_t i00 = (size_t)mrow * N + col;
            size_t i10 = (size_t)(mrow + 8) * N + col;
            C[i00] = acc[mt][nt][0]; C[i00+1] = acc[mt][nt][1];
            C[i10] = acc[mt][nt][2]; C[i10+1] = acc[mt][nt][3];
        }
    }
}

// ============ expert down GEMM (1x, 128x128, no cvt) + scatter atomicAdd ============
__global__ __launch_bounds__(256, 2) void edown1_kernel(const float* __restrict__ wd)
{
    int e = blockIdx.z;
    int cnt = g_cnt[e];
    int m0 = blockIdx.y * 128;
    if (m0 >= cnt) return;
    int n0 = blockIdx.x * 128;
    extern __shared__ float sm[];
    float* As = sm;
    float* Bs = sm + 3*TSTAGE;
    __shared__ int toks[128];
    const int K = EI;
    int tid = threadIdx.x, lane = tid & 31, warp = tid >> 5;
    if (tid < 128) {
        int m = m0 + tid;
        toks[tid] = (m < cnt) ? g_bucket[e * NT + m] : -1;
    }
    __syncthreads();
    const float* Ae = g_eg + ((size_t)e * NT + m0) * EI;
    const float* B = wd + (size_t)e * DMODEL * EI + (size_t)n0 * K;
    int wm = (warp & 1) * 64, wn = (warp >> 1) * 32;

    unsigned aOff[4], bOff[2];
    frag_offsets(lane, wm, wn, aOff, bOff);
    unsigned sA[3] = { sptr(As), sptr(As + TSTAGE), sptr(As + 2*TSTAGE) };
    unsigned sB[3] = { sptr(Bs), sptr(Bs + TSTAGE), sptr(Bs + 2*TSTAGE) };

    const float* aSrc[4]; const float* bSrc[4]; unsigned soff[4]; int aBytes[4];
    #pragma unroll
    for (int i = 0; i < 4; i++) {
        int idx = tid + i * 256, row = idx >> 3, ch = idx & 7;
        soff[i] = (row * TSTRIDE + ch * 4) * 4;
        bool ok = (m0 + row) < cnt;
        aBytes[i] = ok ? 16 : 0;
        aSrc[i] = Ae + (size_t)(ok ? row : 0) * K + ch * 4;
        bSrc[i] = B + (size_t)row * K + ch * 4;
    }
    #pragma unroll
    for (int s = 0; s < 2; s++) {
        #pragma unroll
        for (int i = 0; i < 4; i++) {
            CPA16(sA[s] + soff[i], aSrc[i] + s*32, aBytes[i]);
            CPA16(sB[s] + soff[i], bSrc[i] + s*32, 16);
        }
        CPCOMMIT();
    }

    float acc[4][4][4] = {};
    const int nst = K / 32;
    for (int it = 0; it < nst; it++) {
        if (it + 1 < nst) { CPWAIT1(); } else { CPWAIT0(); }
        __syncthreads();
        int cur = it % 3;
        int pf = it + 2;
        if (pf < nst) {
            int buf = pf % 3;
            #pragma unroll
            for (int i = 0; i < 4; i++) {
                CPA16(sA[buf] + soff[i], aSrc[i] + pf*32, aBytes[i]);
                CPA16(sB[buf] + soff[i], bSrc[i] + pf*32, 16);
            }
            CPCOMMIT();
        }
        mma_ldsm_1x(sA[cur], sB[cur], aOff, bOff, acc);
    }
    int r = lane >> 2, c2 = (lane & 3) * 2;
    #pragma unroll
    for (int mt = 0; mt < 4; mt++) {
        int mloc = wm + mt * 16 + r;
        #pragma unroll
        for (int nt = 0; nt < 4; nt++) {
            int col = n0 + wn + nt * 8 + c2;
            if (m0 + mloc < cnt) {
                int tok = toks[mloc];
                atomicAdd(&g_y[(size_t)tok * DMODEL + col],     acc[mt][nt][0]);
                atomicAdd(&g_y[(size_t)tok * DMODEL + col + 1], acc[mt][nt][1]);
            }
            if (m0 + mloc + 8 < cnt) {
                int tok = toks[mloc + 8];
                atomicAdd(&g_y[(size_t)tok * DMODEL + col],     acc[mt][nt][2]);
                atomicAdd(&g_y[(size_t)tok * DMODEL + col + 1], acc[mt][nt][3]);
            }
        }
    }
}

// ---------------- RMSNorm (optional rounded second output) ----------------
__global__ __launch_bounds__(256) void rmsnorm_kernel(const float* __restrict__ x,
                                                      const float* __restrict__ w,
                                                      float* __restrict__ out,
                                                      float* __restrict__ out2)
{
    int row = blockIdx.x;
    const float* xr = x + (size_t)row * DMODEL;
    float ss = 0.f;
    for (int d = threadIdx.x; d < DMODEL; d += 256) { float v = xr[d]; ss += v * v; }
    __shared__ float red[8];
    #pragma unroll
    for (int off = 16; off; off >>= 1) ss += __shfl_xor_sync(0xffffffffu, ss, off);
    if ((threadIdx.x & 31) == 0) red[threadIdx.x >> 5] = ss;
    __syncthreads();
    __shared__ float sinv;
    if (threadIdx.x == 0) {
        float tot = 0.f;
        #pragma unroll
        for (int i = 0; i < 8; i++) tot += red[i];
        sinv = 1.f / sqrtf(tot / (float)DMODEL + EPSV);
    }
    __syncthreads();
    float si = sinv;
    for (int d = threadIdx.x; d < DMODEL; d += 256) {
        float v = xr[d] * si * w[d];
        out[(size_t)row * DMODEL + d] = v;
        if (out2) out2[(size_t)row * DMODEL + d] = roundtf(v);
    }
}

// ---------------- fused per-(token,head) RMSNorm + RoPE (inline fp32 trig) ----------------
__global__ __launch_bounds__(128) void qknorm_rope_kernel(const float* __restrict__ qw,
                                                          const float* __restrict__ kw,
                                                          Freqs fr)
{
    int row = blockIdx.x;
    if (row == 0 && threadIdx.x < NE) g_cnt[threadIdx.x] = 0;
    float* buf; const float* w; int nh;
    if (row < LSEQ * NH) { buf = g_q; w = qw; nh = NH; }
    else { row -= LSEQ * NH; buf = g_k; w = kw; nh = NKVH; }
    int pos = row / nh;
    float* p = buf + (size_t)row * HDIM;
    int tid = threadIdx.x;
    float v = p[tid];
    float ss = v * v;
    #pragma unroll
    for (int off = 16; off; off >>= 1) ss += __shfl_xor_sync(0xffffffffu, ss, off);
    __shared__ float red_s[4];
    if ((tid & 31) == 0) red_s[tid >> 5] = ss;
    __syncthreads();
    __shared__ float sinv;
    if (tid == 0) sinv = 1.f / sqrtf((red_s[0] + red_s[1] + red_s[2] + red_s[3]) / (float)HDIM + EPSV);
    __shared__ float shn[HDIM];
    __syncthreads();
    shn[tid] = v * sinv * w[tid];
    __syncthreads();
    if (tid < 64) {
        float x1 = shn[tid], x2 = shn[tid + 64];
        float ang = (float)pos * fr.f[tid];
        float k = rintf(ang * 0.15915494309189535f);
        float red = ang - k * 6.28125f;
        red = red - k * 0.0019354820251464844f;
        red = red - k * (-1.7484556e-7f);
        float s, c;
        sincosf(red, &s, &c);
        p[tid]      = x1 * c - x2 * s;
        p[tid + 64] = x2 * c + x1 * s;
    }
}

// ---------------- gating / routing (fp32 exact; coalesced) ----------------
__global__ __launch_bounds__(256) void gate_kernel(const float* __restrict__ gate_w,
                                                   const float* __restrict__ gate_bias)
{
    int t = blockIdx.x;
    const float4* t4 = (const float4*)(g_t + (size_t)t * DMODEL);
    int warp = threadIdx.x >> 5, lane = threadIdx.x & 31;
    int e0 = warp * 2;
    const float4* g0 = (const float4*)(gate_w + (size_t)e0 * DMODEL);
    const float4* g1 = (const float4*)(gate_w + (size_t)(e0 + 1) * DMODEL);
    float a0 = 0.f, a1 = 0.f;
    for (int i = lane; i < DMODEL / 4; i += 32) {
        float4 tv = t4[i], v0 = g0[i], v1 = g1[i];
        a0 += tv.x*v0.x + tv.y*v0.y + tv.z*v0.z + tv.w*v0.w;
        a1 += tv.x*v1.x + tv.y*v1.y + tv.z*v1.z + tv.w*v1.w;
    }
    #pragma unroll
    for (int off = 16; off; off >>= 1) {
        a0 += __shfl_xor_sync(0xffffffffu, a0, off);
        a1 += __shfl_xor_sync(0xffffffffu, a1, off);
    }
    __shared__ float sc_s[NE];
    if (lane == 0) {
        sc_s[e0]     = 1.f / (1.f + expf(-a0));
        sc_s[e0 + 1] = 1.f / (1.f + expf(-a1));
    }
    __syncthreads();
    if (threadIdx.x == 0) {
        float sc[NE], s2[NE];
        #pragma unroll
        for (int e = 0; e < NE; e++) { sc[e] = sc_s[e]; s2[e] = sc[e] + gate_bias[e]; }
        float gs[NG];
        #pragma unroll
        for (int gq = 0; gq < NG; gq++) {
            float m1 = -INFINITY, m2 = -INFINITY;
            #pragma unroll
            for (int j = 0; j < NE / NG; j++) {
                float vv = s2[gq * (NE / NG) + j];
                if (vv > m1) { m2 = m1; m1 = vv; }
                else if (vv > m2) { m2 = vv; }
            }
            gs[gq] = m1 + m2;
        }
        bool gsel[NG] = {false, false, false, false};
        {
            float gtmp[NG];
            #pragma unroll
            for (int gq = 0; gq < NG; gq++) gtmp[gq] = gs[gq];
            for (int it = 0; it < NTKG; it++) {
                int bi = 0; float bv = -INFINITY;
                #pragma unroll
                for (int gq = 0; gq < NG; gq++)
                    if (gtmp[gq] > bv) { bv = gtmp[gq]; bi = gq; }
                gsel[bi] = true; gtmp[bi] = -INFINITY;
            }
        }
        float masked[NE];
        #pragma unroll
        for (int e = 0; e < NE; e++) masked[e] = gsel[e >> 2] ? s2[e] : 0.f;
        int inds[NTOPK];
        for (int it = 0; it < NTOPK; it++) {
            int bi = 0; float bv = -INFINITY;
            #pragma unroll
            for (int e = 0; e < NE; e++)
                if (masked[e] > bv) { bv = masked[e]; bi = e; }
            inds[it] = bi; masked[bi] = -INFINITY;
        }
        float wv[NTOPK], wsum = 0.f;
        #pragma unroll
        for (int i = 0; i < NTOPK; i++) { wv[i] = sc[inds[i]]; wsum += wv[i]; }
        float invw = RSF / (wsum + 1e-20f);
        float crow[NE];
        #pragma unroll
        for (int e = 0; e < NE; e++) crow[e] = 0.f;
        #pragma unroll
        for (int i = 0; i < NTOPK; i++) crow[inds[i]] += wv[i] * invw;
        #pragma unroll
        for (int e = 0; e < NE; e++) g_Cw[t * NE + e] = crow[e];
        #pragma unroll
        for (int i = 0; i < NTOPK; i++) {
            int e = inds[i];
            int posn = atomicAdd(&g_cnt[e], 1);
            g_bucket[e * NT + posn] = t;
        }
    }
}

// ---------------- final: out = h1 + y ----------------
__global__ void final_add_kernel(float* __restrict__ out)
{
    int i = blockIdx.x * blockDim.x + threadIdx.x;
    if (i < NT * DMODEL) out[i] = g_h1[i] + g_y[i];
}

// ---------------- launch ----------------
extern "C" void kernel_launch(void* const* d_in, const int* in_sizes, int n_in,
                              void* d_out, int out_size)
{
    const float* x        = (const float*)d_in[0];
    const float* w_q      = (const float*)d_in[1];
    const float* w_k      = (const float*)d_in[2];
    const float* w_v      = (const float*)d_in[3];
    const float* w_o      = (const float*)d_in[4];
    const float* q_norm_w = (const float*)d_in[5];
    const float* k_norm_w = (const float*)d_in[6];
    const float* ln1_w    = (const float*)d_in[7];
    const float* ln2_w    = (const float*)d_in[8];
    const float* gate_w   = (const float*)d_in[9];
    const float* gate_b   = (const float*)d_in[10];
    const float* wg       = (const float*)d_in[11];
    const float* wu       = (const float*)d_in[12];
    const float* wd       = (const float*)d_in[13];
    const float* sh_g     = (const float*)d_in[14];
    const float* sh_u     = (const float*)d_in[15];
    const float* sh_d     = (const float*)d_in[16];
    float* out = (float*)d_out;

    static int attr_done = 0;
    if (!attr_done) {
        cudaFuncSetAttribute(qkv3_kernel,   cudaFuncAttributeMaxDynamicSharedMemorySize, GEMM_SMEM3);
        cudaFuncSetAttribute(gemm3o_kernel, cudaFuncAttributeMaxDynamicSharedMemorySize, GEMM_SMEM3);
        cudaFuncSetAttribute(qk3_kernel,    cudaFuncAttributeMaxDynamicSharedMemorySize, GEMM_SMEM3);
        cudaFuncSetAttribute(pv3_kernel,    cudaFuncAttributeMaxDynamicSharedMemorySize, GEMM_SMEM3);
        cudaFuncSetAttribute(shgu_kernel,   cudaFuncAttributeMaxDynamicSharedMemorySize, GEMM_SMEM3);
        cudaFuncSetAttribute(egu_kernel,    cudaFuncAttributeMaxDynamicSharedMemorySize, GEMM_SMEM3);
        cudaFuncSetAttribute(dense1_kernel, cudaFuncAttributeMaxDynamicSharedMemorySize, GEMM_SMEM3);
        cudaFuncSetAttribute(edown1_kernel, cudaFuncAttributeMaxDynamicSharedMemorySize, GEMM_SMEM3);
        attr_done = 1;
    }

    Freqs fr;
    for (int j = 0; j < 64; j++)
        fr.f[j] = (float)(1.0 / pow(1000000.0, (double)j / 64.0));

    float *ph, *ph1, *pt, *ptr, *psg, *py, *pattn;
    float *pwgr, *pwur, *pwdr, *pshgr, *pshur, *pshdr;
    cudaGetSymbolAddress((void**)&ph,    g_h);
    cudaGetSymbolAddress((void**)&ph1,   g_h1);
    cudaGetSymbolAddress((void**)&pt,    g_t);
    cudaGetSymbolAddress((void**)&ptr,   g_tr);
    cudaGetSymbolAddress((void**)&psg,   g_sg);
    cudaGetSymbolAddress((void**)&py,    g_y);
    cudaGetSymbolAddress((void**)&pattn, g_attn);
    cudaGetSymbolAddress((void**)&pwgr,  g_wgr);
    cudaGetSymbolAddress((void**)&pwur,  g_wur);
    cudaGetSymbolAddress((void**)&pwdr,  g_wdr);
    cudaGetSymbolAddress((void**)&pshgr, g_shgr);
    cudaGetSymbolAddress((void**)&pshur, g_shur);
    cudaGetSymbolAddress((void**)&pshdr, g_shdr);

    // 0. pre-attn norm
    rmsnorm_kernel<<<LSEQ, 256>>>(x, ln1_w, ph, nullptr);
    // 1. fused QKV projection (3xTF32)
    qkv3_kernel<<<dim3(24, 16), 256, GEMM_SMEM3>>>(ph, w_q, w_k, w_v);
    // 2. fused q/k rmsnorm + rope + cnt zeroing
    qknorm_rope_kernel<<<LSEQ * (NH + NKVH), 128>>>(q_norm_w, k_norm_w, fr);
    // 3. QK^T logits (3xTF32, causal-skip)  <- profiled slot
    qk3_kernel<<<dim3(16, 16, NH), 256, GEMM_SMEM3>>>();
    // 4. row softmax (in place, zero-fills masked cols)
    softmax_kernel<<<dim3(LSEQ, NH), 256>>>();
    // 5. V transpose
    vtrans_kernel<<<NKVH * HDIM, 256>>>();
    // 6. P@V (3xTF32, causal K-truncation)
    pv3_kernel<<<dim3(16, NH), 256, GEMM_SMEM3>>>();
    // 6b. weight pre-rounding
    round_kernel<<<2048, 256>>>(wg,   pwgr,  (size_t)NE*EI*DMODEL/4);
    round_kernel<<<2048, 256>>>(wu,   pwur,  (size_t)NE*EI*DMODEL/4);
    round_kernel<<<2048, 256>>>(wd,   pwdr,  (size_t)NE*DMODEL*EI/4);
    round_kernel<<<512, 256>>>(sh_g, pshgr, (size_t)SHI*DMODEL/4);
    round_kernel<<<512, 256>>>(sh_u, pshur, (size_t)SHI*DMODEL/4);
    round_kernel<<<512, 256>>>(sh_d, pshdr, (size_t)DMODEL*SHI/4);
    // 7. output proj + residual (3xTF32)
    gemm3o_kernel<<<dim3(16, 16), 256, GEMM_SMEM3>>>(pattn, w_o, ph1, x);
    // 8. post-attn norm (full-precision g_t for gate, rounded g_tr for MoE)
    rmsnorm_kernel<<<LSEQ, 256>>>(ph1, ln2_w, pt, ptr);
    // 9. routing (fp32, exact)
    gate_kernel<<<NT, 256>>>(gate_w, gate_b);
    // 10. shared expert fused gate+up
    shgu_kernel<<<dim3(SHI / 64, NT / 128), 256, GEMM_SMEM3>>>(ptr, pshgr, pshur);
    // 11. shared expert down (STORES y)
    dense1_kernel<<<dim3(DMODEL / 128, NT / 128), 256, GEMM_SMEM3>>>(psg, pshdr, py, DMODEL, SHI);
    // 12. routed experts fused gate+up
    egu_kernel<<<dim3(EI / 64, NT / 128, NE), 256, GEMM_SMEM3>>>(pwgr, pwur);
    // 13. routed down (atomicAdd y)
    edown1_kernel<<<dim3(DMODEL / 128, NT / 128, NE), 256, GEMM_SMEM3>>>(pwdr);
    // 14. final residual add
    final_add_kernel<<<(NT * DMODEL + 255) / 256, 256>>>(out);
    (void)in_sizes; (void)n_in; (void)out_size;
}